// round 1
// baseline (speedup 1.0000x reference)
#include <cuda_runtime.h>
#include <math.h>

// ---------------- static scratch (no allocation allowed) ----------------
__device__ float g_bufA[16777216];   // max: act0 8*32*256*256, act6 8*32*249*249
__device__ float g_bufB[8388608];    // max: act1 8*64*128*128, act5 8e6
__device__ float g_wt0[3*49*32];
__device__ float g_wt1[32*9*64];
__device__ float g_wt2[64*9*128];
__device__ float g_wt3[128*9*256];
__device__ float g_wt4[256*9*128];
__device__ float g_wt5[128*9*64];
__device__ float g_wt6[64*9*32];
__device__ float g_wt7[32*49*4];
__device__ float g_mean[2048];
__device__ float g_rstd[2048];
__device__ float g_segsum[96];
__device__ float g_segcnt[32];

// ---------------- weight transposes ----------------
// conv weight [O][I][K] -> [ (i*K+k)*O + o ]
__global__ void k_tr_oik(const float* __restrict__ w, float* __restrict__ out,
                         int I, int O, int K) {
    int idx = blockIdx.x * blockDim.x + threadIdx.x;
    if (idx >= O * I * K) return;
    int o = idx / (I * K);
    int r = idx % (I * K);
    int i = r / K, k = r % K;
    out[(i * K + k) * O + o] = w[idx];
}
// convT weight [I][O][K] -> [ (i*K+k)*O + o ]
__global__ void k_tr_iok(const float* __restrict__ w, float* __restrict__ out,
                         int I, int O, int K) {
    int idx = blockIdx.x * blockDim.x + threadIdx.x;
    if (idx >= I * O * K) return;
    int i = idx / (O * K);
    int r = idx % (O * K);
    int o = r / K, k = r % K;
    out[(i * K + k) * O + o] = w[idx];
}
// w7 [3][32][49] -> [ (i*49+k)*4 + o ], 4th channel zero
__global__ void k_tr_w7(const float* __restrict__ w, float* __restrict__ out) {
    int idx = blockIdx.x * blockDim.x + threadIdx.x;
    if (idx >= 32 * 49 * 4) return;
    int p = idx >> 2, o = idx & 3;
    int i = p / 49, k = p % 49;
    out[idx] = (o < 3) ? w[(o * 32 + i) * 49 + k] : 0.f;
}

// ---------------- layer 0: reflect-pad 7x7 conv, 3->32, 256x256 ----------------
__global__ void k_conv7_l0(const float* __restrict__ x, const float* __restrict__ wt,
                           const float* __restrict__ bias, float* __restrict__ out) {
    __shared__ __align__(16) float s_w[3 * 49 * 32];
    __shared__ float s_in[3 * 22 * 22];
    __shared__ float s_b[32];
    int tx = threadIdx.x, ty = threadIdx.y;
    int tid = ty * 16 + tx;
    int n = blockIdx.z;
    int oy0 = blockIdx.y * 16, ox0 = blockIdx.x * 16;

    for (int i = tid; i < 3 * 49 * 32; i += 256) s_w[i] = wt[i];
    if (tid < 32) s_b[tid] = bias[tid];
    const float* xp = x + (size_t)n * 3 * 65536;
    for (int i = tid; i < 3 * 484; i += 256) {
        int ic = i / 484, rr = (i % 484) / 22, cc = i % 22;
        int iy = oy0 + rr - 3, ix = ox0 + cc - 3;
        iy = iy < 0 ? -iy : (iy > 255 ? 510 - iy : iy);
        ix = ix < 0 ? -ix : (ix > 255 ? 510 - ix : ix);
        s_in[i] = xp[ic * 65536 + iy * 256 + ix];
    }
    __syncthreads();

    float acc[32];
#pragma unroll
    for (int j = 0; j < 32; j++) acc[j] = 0.f;

    for (int ic = 0; ic < 3; ic++)
        for (int ky = 0; ky < 7; ky++)
#pragma unroll
            for (int kx = 0; kx < 7; kx++) {
                float v = s_in[ic * 484 + (ty + ky) * 22 + tx + kx];
                const float4* wp = (const float4*)(s_w + ((ic * 7 + ky) * 7 + kx) * 32);
#pragma unroll
                for (int q = 0; q < 8; q++) {
                    float4 w4 = wp[q];
                    acc[4 * q + 0] += v * w4.x;
                    acc[4 * q + 1] += v * w4.y;
                    acc[4 * q + 2] += v * w4.z;
                    acc[4 * q + 3] += v * w4.w;
                }
            }
    int oy = oy0 + ty, ox = ox0 + tx;
    float* op = out + (size_t)n * 32 * 65536 + oy * 256 + ox;
#pragma unroll
    for (int j = 0; j < 32; j++) op[j * 65536] = acc[j] + s_b[j];
}

// ---------------- 3x3 stride-2 conv, fused input IN+ReLU ----------------
template <int IC, int OC, int OCB>
__global__ void k_conv3s2(const float* __restrict__ in, const float* __restrict__ wt,
                          const float* __restrict__ bias, const float* __restrict__ mean,
                          const float* __restrict__ rstd, float* __restrict__ out,
                          int Hin, int Win, int Hout, int Wout) {
    __shared__ __align__(16) float s_w[IC * 9 * OCB];
    __shared__ float s_in[33 * 33];
    int tx = threadIdx.x, ty = threadIdx.y;
    int tid = ty * 16 + tx;
    int z = blockIdx.z;
    int n = z / (OC / OCB);
    int oc0 = (z % (OC / OCB)) * OCB;
    int oy0 = blockIdx.y * 16, ox0 = blockIdx.x * 16;

    for (int i = tid; i < IC * 9 * OCB; i += 256) {
        int p = i / OCB, j = i % OCB;
        s_w[i] = wt[p * OC + oc0 + j];
    }
    float acc[OCB];
#pragma unroll
    for (int j = 0; j < OCB; j++) acc[j] = 0.f;

    int iy0 = 2 * oy0 - 1, ix0 = 2 * ox0 - 1;
    for (int ic = 0; ic < IC; ic++) {
        __syncthreads();
        const float* ip = in + (size_t)(n * IC + ic) * Hin * Win;
        float m = mean[n * IC + ic], rs = rstd[n * IC + ic];
        for (int i = tid; i < 1089; i += 256) {
            int rr = i / 33, cc = i % 33;
            int iy = iy0 + rr, ix = ix0 + cc;
            float v = 0.f;
            if (iy >= 0 && iy < Hin && ix >= 0 && ix < Win)
                v = fmaxf((ip[iy * Win + ix] - m) * rs, 0.f);
            s_in[i] = v;
        }
        __syncthreads();
#pragma unroll
        for (int ky = 0; ky < 3; ky++)
#pragma unroll
            for (int kx = 0; kx < 3; kx++) {
                float v = s_in[(2 * ty + ky) * 33 + 2 * tx + kx];
                const float4* wp = (const float4*)(s_w + (ic * 9 + ky * 3 + kx) * OCB);
#pragma unroll
                for (int q = 0; q < OCB / 4; q++) {
                    float4 w4 = wp[q];
                    acc[4 * q + 0] += v * w4.x;
                    acc[4 * q + 1] += v * w4.y;
                    acc[4 * q + 2] += v * w4.z;
                    acc[4 * q + 3] += v * w4.w;
                }
            }
    }
    int oy = oy0 + ty, ox = ox0 + tx;
    float* op = out + ((size_t)(n * OC + oc0) * Hout + oy) * Wout + ox;
#pragma unroll
    for (int j = 0; j < OCB; j++) op[(size_t)j * Hout * Wout] = acc[j] + bias[oc0 + j];
}

// ---------------- 3x3 stride-2 transposed conv (sub-pixel decomposition) -------
// Each thread computes a 2x2 output parity block x OCB channels. Zero tap waste.
template <int IC, int OC, int OCB, int ICC>
__global__ void k_convT(const float* __restrict__ in, const float* __restrict__ wt,
                        const float* __restrict__ bias, const float* __restrict__ mean,
                        const float* __restrict__ rstd, float* __restrict__ out,
                        int Hin, int Win, int Hout, int Wout) {
    __shared__ __align__(16) float s_w[ICC * 9 * OCB];
    __shared__ float s_in[ICC * 17 * 18];
    int tx = threadIdx.x, ty = threadIdx.y;
    int tid = ty * 16 + tx;
    int z = blockIdx.z;
    int n = z / (OC / OCB);
    int oc0 = (z % (OC / OCB)) * OCB;
    int oy0 = blockIdx.y * 32, ox0 = blockIdx.x * 32;
    int iy0 = oy0 >> 1, ix0 = ox0 >> 1;

    float acc[4][OCB];
#pragma unroll
    for (int c = 0; c < 4; c++)
#pragma unroll
        for (int j = 0; j < OCB; j++) acc[c][j] = 0.f;

    for (int ch = 0; ch < IC / ICC; ch++) {
        __syncthreads();
        for (int i = tid; i < ICC * 9 * OCB; i += 256) {
            int p = i / OCB, j = i % OCB;
            s_w[i] = wt[(ch * ICC * 9 + p) * OC + oc0 + j];
        }
        for (int i = tid; i < ICC * 289; i += 256) {
            int icl = i / 289, rr = (i % 289) / 17, cc = i % 17;
            int ic = ch * ICC + icl;
            int iy = iy0 + rr, ix = ix0 + cc;
            float v = 0.f;
            if (iy < Hin && ix < Win) {
                float m = mean[n * IC + ic], rs = rstd[n * IC + ic];
                v = fmaxf((in[((size_t)(n * IC + ic) * Hin + iy) * Win + ix] - m) * rs, 0.f);
            }
            s_in[icl * 306 + rr * 18 + cc] = v;
        }
        __syncthreads();
        for (int icl = 0; icl < ICC; icl++) {
            const float* sp = s_in + icl * 306 + ty * 18 + tx;
            float s00 = sp[0], s01 = sp[1], s10 = sp[18], s11 = sp[19];
            const float4* wp = (const float4*)(s_w + icl * 9 * OCB);
#pragma unroll
            for (int q = 0; q < OCB / 4; q++) {
                float4 w;
#define FMA4(CLS, T, V)                               \
    w = wp[(T) * (OCB / 4) + q];                      \
    acc[CLS][4 * q + 0] += (V) * w.x;                 \
    acc[CLS][4 * q + 1] += (V) * w.y;                 \
    acc[CLS][4 * q + 2] += (V) * w.z;                 \
    acc[CLS][4 * q + 3] += (V) * w.w;
                FMA4(0, 4, s00)                         // even y, even x : ky=1,kx=1
                FMA4(1, 3, s01) FMA4(1, 5, s00)         // even y, odd x  : kx=0 / kx=2
                FMA4(2, 1, s10) FMA4(2, 7, s00)         // odd y,  even x : ky=0 / ky=2
                FMA4(3, 0, s11) FMA4(3, 2, s10)         // odd y,  odd x
                FMA4(3, 6, s01) FMA4(3, 8, s00)
#undef FMA4
            }
        }
    }
    int ye = oy0 + 2 * ty, xe = ox0 + 2 * tx;
    bool y0v = ye < Hout, y1v = (ye + 1) < Hout;
    bool x0v = xe < Wout, x1v = (xe + 1) < Wout;
#pragma unroll
    for (int j = 0; j < OCB; j++) {
        float bv = bias[oc0 + j];
        float* op = out + (size_t)(n * OC + oc0 + j) * Hout * Wout;
        if (y0v) {
            if (x0v) op[ye * Wout + xe] = acc[0][j] + bv;
            if (x1v) op[ye * Wout + xe + 1] = acc[1][j] + bv;
        }
        if (y1v) {
            if (x0v) op[(ye + 1) * Wout + xe] = acc[2][j] + bv;
            if (x1v) op[(ye + 1) * Wout + xe + 1] = acc[3][j] + bv;
        }
    }
}

// ---------------- layer 7: reflect-pad 7x7 conv 32->3 + tanh ----------------
__global__ void k_conv7_l7(const float* __restrict__ act, const float* __restrict__ wt,
                           const float* __restrict__ bias, const float* __restrict__ mean,
                           const float* __restrict__ rstd, float* __restrict__ out) {
    __shared__ __align__(16) float s_w[32 * 49 * 4];
    __shared__ float s_in[22 * 22];
    const int H = 249;
    int tx = threadIdx.x, ty = threadIdx.y;
    int tid = ty * 16 + tx;
    int n = blockIdx.z;
    int oy0 = blockIdx.y * 16, ox0 = blockIdx.x * 16;
    for (int i = tid; i < 32 * 49 * 4; i += 256) s_w[i] = wt[i];

    float acc[4] = {0.f, 0.f, 0.f, 0.f};
    for (int ic = 0; ic < 32; ic++) {
        __syncthreads();
        float m = mean[n * 32 + ic], rs = rstd[n * 32 + ic];
        const float* ip = act + (size_t)(n * 32 + ic) * 62001;
        for (int i = tid; i < 484; i += 256) {
            int rr = i / 22, cc = i % 22;
            int iy = oy0 + rr - 3, ix = ox0 + cc - 3;
            iy = iy < 0 ? -iy : (iy > 248 ? 496 - iy : iy);
            ix = ix < 0 ? -ix : (ix > 248 ? 496 - ix : ix);
            s_in[i] = fmaxf((ip[iy * 249 + ix] - m) * rs, 0.f);
        }
        __syncthreads();
        for (int ky = 0; ky < 7; ky++)
#pragma unroll
            for (int kx = 0; kx < 7; kx++) {
                float v = s_in[(ty + ky) * 22 + tx + kx];
                float4 w4 = ((const float4*)s_w)[(ic * 7 + ky) * 7 + kx];
                acc[0] += v * w4.x;
                acc[1] += v * w4.y;
                acc[2] += v * w4.z;
                acc[3] += v * w4.w;
            }
    }
    int oy = oy0 + ty, ox = ox0 + tx;
    if (oy < H && ox < H) {
#pragma unroll
        for (int k = 0; k < 3; k++)
            out[(size_t)(n * 3 + k) * 62001 + oy * 249 + ox] = tanhf(acc[k] + bias[k]);
    }
}

// ---------------- instance-norm stats (per (n,c) plane) ----------------
__global__ void k_instat(const float* __restrict__ x, float* __restrict__ mean,
                         float* __restrict__ rstd, int HW) {
    int p = blockIdx.x;
    const float* xp = x + (size_t)p * HW;
    double s = 0.0, s2 = 0.0;
    for (int i = threadIdx.x; i < HW; i += 256) {
        double v = xp[i];
        s += v;
        s2 += v * v;
    }
    for (int o = 16; o > 0; o >>= 1) {
        s += __shfl_down_sync(0xffffffffu, s, o);
        s2 += __shfl_down_sync(0xffffffffu, s2, o);
    }
    __shared__ double sh[16];
    int w = threadIdx.x >> 5, l = threadIdx.x & 31;
    if (l == 0) { sh[w] = s; sh[w + 8] = s2; }
    __syncthreads();
    if (threadIdx.x == 0) {
        for (int i = 1; i < 8; i++) { s += sh[i]; s2 += sh[i + 8]; }
        double m = s / HW;
        double var = s2 / HW - m * m;
        mean[p] = (float)m;
        rstd[p] = rsqrtf(fmaxf((float)var, 0.f) + 1e-5f);
    }
}

// ---------------- segment mean ----------------
__global__ void k_segzero(float* sum, float* cnt) {
    int t = threadIdx.x;
    if (t < 96) sum[t] = 0.f;
    if (t < 32) cnt[t] = 0.f;
}
__global__ void k_segacc(const float* __restrict__ src, const int* __restrict__ inst,
                         float* __restrict__ gsum, float* __restrict__ gcnt) {
    __shared__ float ss[96];
    __shared__ float sc[32];
    int tid = threadIdx.x;
    if (tid < 96) ss[tid] = 0.f;
    if (tid < 32) sc[tid] = 0.f;
    __syncthreads();
    const int P = 62001, NP = 8 * 62001;
    for (int i = blockIdx.x * blockDim.x + tid; i < NP; i += gridDim.x * blockDim.x) {
        int n = i / P, p = i % P;
        int id = inst[i];
        const float* b = src + (size_t)n * 3 * P + p;
        atomicAdd(&ss[id * 3 + 0], b[0]);
        atomicAdd(&ss[id * 3 + 1], b[P]);
        atomicAdd(&ss[id * 3 + 2], b[2 * P]);
        atomicAdd(&sc[id], 1.f);
    }
    __syncthreads();
    if (tid < 96) atomicAdd(&gsum[tid], ss[tid]);
    if (tid < 32) atomicAdd(&gcnt[tid], sc[tid]);
}
__global__ void k_segbcast(const int* __restrict__ inst, const float* __restrict__ gsum,
                           const float* __restrict__ gcnt, float* __restrict__ out) {
    const int P = 62001, T = 8 * 3 * P;
    for (int i = blockIdx.x * blockDim.x + threadIdx.x; i < T; i += gridDim.x * blockDim.x) {
        int n = i / (3 * P), r = i % (3 * P);
        int c = r / P, p = r % P;
        int id = inst[n * P + p];
        out[i] = gsum[id * 3 + c] / fmaxf(gcnt[id], 1.f);
    }
}

// ---------------- launch ----------------
extern "C" void kernel_launch(void* const* d_in, const int* in_sizes, int n_in,
                              void* d_out, int out_size) {
    const float* x = (const float*)d_in[0];
    const int* inst = (const int*)d_in[1];
    const float* w[8];
    const float* b[8];
    for (int i = 0; i < 8; i++) {
        w[i] = (const float*)d_in[2 + 2 * i];
        b[i] = (const float*)d_in[3 + 2 * i];
    }
    float* out = (float*)d_out;

    float *A, *B, *M, *R;
    float *WT0, *WT1, *WT2, *WT3, *WT4, *WT5, *WT6, *WT7, *SS, *SC;
    cudaGetSymbolAddress((void**)&A, g_bufA);
    cudaGetSymbolAddress((void**)&B, g_bufB);
    cudaGetSymbolAddress((void**)&M, g_mean);
    cudaGetSymbolAddress((void**)&R, g_rstd);
    cudaGetSymbolAddress((void**)&WT0, g_wt0);
    cudaGetSymbolAddress((void**)&WT1, g_wt1);
    cudaGetSymbolAddress((void**)&WT2, g_wt2);
    cudaGetSymbolAddress((void**)&WT3, g_wt3);
    cudaGetSymbolAddress((void**)&WT4, g_wt4);
    cudaGetSymbolAddress((void**)&WT5, g_wt5);
    cudaGetSymbolAddress((void**)&WT6, g_wt6);
    cudaGetSymbolAddress((void**)&WT7, g_wt7);
    cudaGetSymbolAddress((void**)&SS, g_segsum);
    cudaGetSymbolAddress((void**)&SC, g_segcnt);

    dim3 blk(16, 16);

    // weight transposes
    k_tr_oik<<<(3 * 49 * 32 + 255) / 256, 256>>>(w[0], WT0, 3, 32, 49);
    k_tr_oik<<<(32 * 9 * 64 + 255) / 256, 256>>>(w[1], WT1, 32, 64, 9);
    k_tr_oik<<<(64 * 9 * 128 + 255) / 256, 256>>>(w[2], WT2, 64, 128, 9);
    k_tr_oik<<<(128 * 9 * 256 + 255) / 256, 256>>>(w[3], WT3, 128, 256, 9);
    k_tr_iok<<<(256 * 9 * 128 + 255) / 256, 256>>>(w[4], WT4, 256, 128, 9);
    k_tr_iok<<<(128 * 9 * 64 + 255) / 256, 256>>>(w[5], WT5, 128, 64, 9);
    k_tr_iok<<<(64 * 9 * 32 + 255) / 256, 256>>>(w[6], WT6, 64, 32, 9);
    k_tr_w7<<<(32 * 49 * 4 + 255) / 256, 256>>>(w[7], WT7);

    // layer 0
    k_conv7_l0<<<dim3(16, 16, 8), blk>>>(x, WT0, b[0], A);
    k_instat<<<8 * 32, 256>>>(A, M, R, 65536);
    // layer 1-3 (downsample)
    k_conv3s2<32, 64, 8><<<dim3(8, 8, 8 * 8), blk>>>(A, WT1, b[1], M, R, B, 256, 256, 128, 128);
    k_instat<<<8 * 64, 256>>>(B, M, R, 16384);
    k_conv3s2<64, 128, 8><<<dim3(4, 4, 8 * 16), blk>>>(B, WT2, b[2], M, R, A, 128, 128, 64, 64);
    k_instat<<<8 * 128, 256>>>(A, M, R, 4096);
    k_conv3s2<128, 256, 8><<<dim3(2, 2, 8 * 32), blk>>>(A, WT3, b[3], M, R, B, 64, 64, 32, 32);
    k_instat<<<8 * 256, 256>>>(B, M, R, 1024);
    // layer 4-6 (upsample, transposed conv)
    k_convT<256, 128, 8, 16><<<dim3(2, 2, 8 * 16), blk>>>(B, WT4, b[4], M, R, A, 32, 32, 63, 63);
    k_instat<<<8 * 128, 256>>>(A, M, R, 3969);
    k_convT<128, 64, 8, 16><<<dim3(4, 4, 8 * 8), blk>>>(A, WT5, b[5], M, R, B, 63, 63, 125, 125);
    k_instat<<<8 * 64, 256>>>(B, M, R, 15625);
    k_convT<64, 32, 8, 16><<<dim3(8, 8, 8 * 4), blk>>>(B, WT6, b[6], M, R, A, 125, 125, 249, 249);
    k_instat<<<8 * 32, 256>>>(A, M, R, 62001);
    // layer 7 + tanh
    k_conv7_l7<<<dim3(16, 16, 8), blk>>>(A, WT7, b[7], M, R, B);
    // segment mean
    k_segzero<<<1, 128>>>(SS, SC);
    k_segacc<<<1024, 256>>>(B, inst, SS, SC);
    k_segbcast<<<2048, 256>>>(inst, SS, SC, out);
}

// round 2
// speedup vs baseline: 1.1353x; 1.1353x over previous
#include <cuda_runtime.h>
#include <math.h>

// ---------------- static scratch (no allocation allowed) ----------------
__device__ float g_bufA[16777216];   // max: act0 8*32*256*256, act6 8*32*249*249
__device__ float g_bufB[8388608];    // max: act1 8*64*128*128
__device__ float g_wt0[3*49*32];
__device__ float g_wt1[32*9*64];
__device__ float g_wt2[64*9*128];
__device__ float g_wt3[128*9*256];
__device__ float g_wt4[256*9*128];
__device__ float g_wt5[128*9*64];
__device__ float g_wt6[64*9*32];
__device__ float g_wt7[32*49*4];
__device__ float g_scale[2048];
__device__ float g_shift[2048];
__device__ float g_segsum[96];
__device__ float g_segcnt[32];

// ---------------- f32x2 packed helpers ----------------
__device__ __forceinline__ unsigned long long pack2(float v) {
    unsigned long long r;
    asm("mov.b64 %0, {%1, %1};" : "=l"(r) : "f"(v));
    return r;
}
__device__ __forceinline__ void fma2(unsigned long long& d, unsigned long long a,
                                     unsigned long long b) {
    asm("fma.rn.f32x2 %0, %1, %2, %0;" : "+l"(d) : "l"(a), "l"(b));
}
__device__ __forceinline__ float2 unpack2(unsigned long long v) {
    float2 f;
    asm("mov.b64 {%0, %1}, %2;" : "=f"(f.x), "=f"(f.y) : "l"(v));
    return f;
}
// accumulate OCB channels (OCB/2 packed pairs) for one tap. wbase 16B-aligned.
template <int OCB>
__device__ __forceinline__ void fma_tap(unsigned long long* acc, unsigned long long vv,
                                        const float* wbase) {
    const ulonglong2* wp = (const ulonglong2*)wbase;
#pragma unroll
    for (int q = 0; q < OCB / 4; q++) {
        ulonglong2 w2 = wp[q];
        fma2(acc[2 * q + 0], vv, w2.x);
        fma2(acc[2 * q + 1], vv, w2.y);
    }
}

// ---------------- weight transposes ----------------
__global__ void k_tr_oik(const float* __restrict__ w, float* __restrict__ out,
                         int I, int O, int K) {
    int idx = blockIdx.x * blockDim.x + threadIdx.x;
    if (idx >= O * I * K) return;
    int o = idx / (I * K);
    int r = idx % (I * K);
    int i = r / K, k = r % K;
    out[(i * K + k) * O + o] = w[idx];
}
__global__ void k_tr_iok(const float* __restrict__ w, float* __restrict__ out,
                         int I, int O, int K) {
    int idx = blockIdx.x * blockDim.x + threadIdx.x;
    if (idx >= I * O * K) return;
    int i = idx / (O * K);
    int r = idx % (O * K);
    int o = r / K, k = r % K;
    out[(i * K + k) * O + o] = w[idx];
}
__global__ void k_tr_w7(const float* __restrict__ w, float* __restrict__ out) {
    int idx = blockIdx.x * blockDim.x + threadIdx.x;
    if (idx >= 32 * 49 * 4) return;
    int p = idx >> 2, o = idx & 3;
    int i = p / 49, k = p % 49;
    out[idx] = (o < 3) ? w[(o * 32 + i) * 49 + k] : 0.f;
}

// ---------------- layer 0: reflect-pad 7x7 conv, 3->32, 256x256 ----------------
__global__ void k_conv7_l0(const float* __restrict__ x, const float* __restrict__ wt,
                           const float* __restrict__ bias, float* __restrict__ out) {
    __shared__ __align__(16) float s_w[3 * 49 * 32];
    __shared__ float s_in[3 * 484];
    int tx = threadIdx.x, ty = threadIdx.y;
    int tid = ty * 16 + tx;
    int n = blockIdx.z;
    int oy0 = blockIdx.y * 16, ox0 = blockIdx.x * 16;

    for (int i = tid; i < 3 * 49 * 32; i += 256) s_w[i] = wt[i];
    const float* xp = x + (size_t)n * 3 * 65536;
    for (int i = tid; i < 3 * 484; i += 256) {
        int ic = i / 484, rr = (i % 484) / 22, cc = i % 22;
        int iy = oy0 + rr - 3, ix = ox0 + cc - 3;
        iy = iy < 0 ? -iy : (iy > 255 ? 510 - iy : iy);
        ix = ix < 0 ? -ix : (ix > 255 ? 510 - ix : ix);
        s_in[i] = xp[ic * 65536 + iy * 256 + ix];
    }
    __syncthreads();

    unsigned long long acc[16];
#pragma unroll
    for (int j = 0; j < 16; j++) acc[j] = 0ull;

    for (int ic = 0; ic < 3; ic++)
        for (int ky = 0; ky < 7; ky++)
#pragma unroll
            for (int kx = 0; kx < 7; kx++) {
                unsigned long long vv = pack2(s_in[ic * 484 + (ty + ky) * 22 + tx + kx]);
                fma_tap<32>(acc, vv, s_w + ((ic * 7 + ky) * 7 + kx) * 32);
            }
    int oy = oy0 + ty, ox = ox0 + tx;
    float* op = out + (size_t)n * 32 * 65536 + oy * 256 + ox;
#pragma unroll
    for (int j = 0; j < 16; j++) {
        float2 a = unpack2(acc[j]);
        op[(size_t)(2 * j + 0) * 65536] = a.x + bias[2 * j + 0];
        op[(size_t)(2 * j + 1) * 65536] = a.y + bias[2 * j + 1];
    }
}

// ---------------- 3x3 stride-2 conv, fused input IN+ReLU, OCB=32 ----------------
template <int IC, int OC, int ICC>
__global__ void k_conv3s2(const float* __restrict__ in, const float* __restrict__ wt,
                          const float* __restrict__ bias, const float* __restrict__ scale,
                          const float* __restrict__ shift, float* __restrict__ out,
                          int Hin, int Win, int Hout, int Wout) {
    __shared__ __align__(16) float s_w[ICC * 9 * 32];
    __shared__ float s_in[ICC * 1089];
    int tx = threadIdx.x, ty = threadIdx.y;
    int tid = ty * 16 + tx;
    int z = blockIdx.z;
    int n = z / (OC / 32);
    int oc0 = (z % (OC / 32)) * 32;
    int oy0 = blockIdx.y * 16, ox0 = blockIdx.x * 16;
    int iy0 = 2 * oy0 - 1, ix0 = 2 * ox0 - 1;

    unsigned long long acc[16];
#pragma unroll
    for (int j = 0; j < 16; j++) acc[j] = 0ull;

    for (int ch = 0; ch < IC / ICC; ch++) {
        __syncthreads();
        for (int i = tid; i < ICC * 9 * 32; i += 256) {
            int p = i >> 5, j = i & 31;
            s_w[i] = wt[(ch * ICC * 9 + p) * OC + oc0 + j];
        }
        for (int i = tid; i < ICC * 1089; i += 256) {
            int icl = i / 1089, r = (i % 1089) / 33, c = i % 33;
            int ic = ch * ICC + icl;
            int iy = iy0 + r, ix = ix0 + c;
            float v = 0.f;
            if (iy >= 0 && iy < Hin && ix >= 0 && ix < Win)
                v = fmaxf(fmaf(in[((size_t)(n * IC + ic) * Hin + iy) * Win + ix],
                               scale[n * IC + ic], shift[n * IC + ic]), 0.f);
            s_in[i] = v;
        }
        __syncthreads();
#pragma unroll
        for (int icl = 0; icl < ICC; icl++) {
            const float* sb = s_in + icl * 1089 + 2 * ty * 33 + 2 * tx;
            const float* wb = s_w + icl * 9 * 32;
#pragma unroll
            for (int ky = 0; ky < 3; ky++)
#pragma unroll
                for (int kx = 0; kx < 3; kx++) {
                    unsigned long long vv = pack2(sb[ky * 33 + kx]);
                    fma_tap<32>(acc, vv, wb + (ky * 3 + kx) * 32);
                }
        }
    }
    int oy = oy0 + ty, ox = ox0 + tx;
    float* op = out + ((size_t)(n * OC + oc0) * Hout + oy) * Wout + ox;
#pragma unroll
    for (int j = 0; j < 16; j++) {
        float2 a = unpack2(acc[j]);
        op[(size_t)(2 * j + 0) * Hout * Wout] = a.x + bias[oc0 + 2 * j + 0];
        op[(size_t)(2 * j + 1) * Hout * Wout] = a.y + bias[oc0 + 2 * j + 1];
    }
}

// ---------------- 3x3 stride-2 transposed conv (sub-pixel decomposition) -------
template <int IC, int OC, int OCB, int ICC>
__global__ void __launch_bounds__(256)
k_convT(const float* __restrict__ in, const float* __restrict__ wt,
        const float* __restrict__ bias, const float* __restrict__ scale,
        const float* __restrict__ shift, float* __restrict__ out,
        int Hin, int Win, int Hout, int Wout) {
    __shared__ __align__(16) float s_w[ICC * 9 * OCB];
    __shared__ float s_in[ICC * 306];
    int tx = threadIdx.x, ty = threadIdx.y;
    int tid = ty * 16 + tx;
    int z = blockIdx.z;
    int n = z / (OC / OCB);
    int oc0 = (z % (OC / OCB)) * OCB;
    int oy0 = blockIdx.y * 32, ox0 = blockIdx.x * 32;
    int iy0 = oy0 >> 1, ix0 = ox0 >> 1;

    unsigned long long acc[4][OCB / 2];
#pragma unroll
    for (int c = 0; c < 4; c++)
#pragma unroll
        for (int j = 0; j < OCB / 2; j++) acc[c][j] = 0ull;

    for (int ch = 0; ch < IC / ICC; ch++) {
        __syncthreads();
        for (int i = tid; i < ICC * 9 * OCB; i += 256) {
            int p = i / OCB, j = i % OCB;
            s_w[i] = wt[(ch * ICC * 9 + p) * OC + oc0 + j];
        }
        for (int i = tid; i < ICC * 289; i += 256) {
            int icl = i / 289, rr = (i % 289) / 17, cc = i % 17;
            int ic = ch * ICC + icl;
            int iy = iy0 + rr, ix = ix0 + cc;
            float v = 0.f;
            if (iy < Hin && ix < Win)
                v = fmaxf(fmaf(in[((size_t)(n * IC + ic) * Hin + iy) * Win + ix],
                               scale[n * IC + ic], shift[n * IC + ic]), 0.f);
            s_in[icl * 306 + rr * 18 + cc] = v;
        }
        __syncthreads();
#pragma unroll 4
        for (int icl = 0; icl < ICC; icl++) {
            const float* sp = s_in + icl * 306 + ty * 18 + tx;
            unsigned long long v00 = pack2(sp[0]);
            unsigned long long v01 = pack2(sp[1]);
            unsigned long long v10 = pack2(sp[18]);
            unsigned long long v11 = pack2(sp[19]);
            const float* wb = s_w + icl * 9 * OCB;
            fma_tap<OCB>(acc[0], v00, wb + 4 * OCB);  // even y, even x: ky=1,kx=1
            fma_tap<OCB>(acc[1], v01, wb + 3 * OCB);  // even y, odd x
            fma_tap<OCB>(acc[1], v00, wb + 5 * OCB);
            fma_tap<OCB>(acc[2], v10, wb + 1 * OCB);  // odd y, even x
            fma_tap<OCB>(acc[2], v00, wb + 7 * OCB);
            fma_tap<OCB>(acc[3], v11, wb + 0 * OCB);  // odd y, odd x
            fma_tap<OCB>(acc[3], v10, wb + 2 * OCB);
            fma_tap<OCB>(acc[3], v01, wb + 6 * OCB);
            fma_tap<OCB>(acc[3], v00, wb + 8 * OCB);
        }
    }
    int ye = oy0 + 2 * ty, xe = ox0 + 2 * tx;
    bool y0v = ye < Hout, y1v = (ye + 1) < Hout;
    bool x0v = xe < Wout, x1v = (xe + 1) < Wout;
#pragma unroll
    for (int j = 0; j < OCB / 2; j++) {
        float b0 = bias[oc0 + 2 * j], b1 = bias[oc0 + 2 * j + 1];
        float* op0 = out + (size_t)(n * OC + oc0 + 2 * j) * Hout * Wout;
        float* op1 = op0 + (size_t)Hout * Wout;
        float2 a;
        if (y0v && x0v) { a = unpack2(acc[0][j]); op0[ye * Wout + xe] = a.x + b0; op1[ye * Wout + xe] = a.y + b1; }
        if (y0v && x1v) { a = unpack2(acc[1][j]); op0[ye * Wout + xe + 1] = a.x + b0; op1[ye * Wout + xe + 1] = a.y + b1; }
        if (y1v && x0v) { a = unpack2(acc[2][j]); op0[(ye + 1) * Wout + xe] = a.x + b0; op1[(ye + 1) * Wout + xe] = a.y + b1; }
        if (y1v && x1v) { a = unpack2(acc[3][j]); op0[(ye + 1) * Wout + xe + 1] = a.x + b0; op1[(ye + 1) * Wout + xe + 1] = a.y + b1; }
    }
}

// ---------------- layer 7: reflect-pad 7x7 conv 32->3 + tanh, 2x2 px/thread ----
__global__ void k_conv7_l7(const float* __restrict__ act, const float* __restrict__ wt,
                           const float* __restrict__ bias, const float* __restrict__ scale,
                           const float* __restrict__ shift, float* __restrict__ out) {
    __shared__ __align__(16) float s_w[32 * 49 * 4];
    __shared__ float s_in[38 * 39];
    const int H = 249;
    int tx = threadIdx.x, ty = threadIdx.y;
    int tid = ty * 16 + tx;
    int n = blockIdx.z;
    int oy0 = blockIdx.y * 32, ox0 = blockIdx.x * 32;
    for (int i = tid; i < 32 * 49 * 4; i += 256) s_w[i] = wt[i];

    unsigned long long acc[4][2];
#pragma unroll
    for (int p = 0; p < 4; p++) { acc[p][0] = 0ull; acc[p][1] = 0ull; }

    for (int ic = 0; ic < 32; ic++) {
        __syncthreads();
        float sc = scale[n * 32 + ic], sh = shift[n * 32 + ic];
        const float* ip = act + (size_t)(n * 32 + ic) * 62001;
        for (int i = tid; i < 38 * 38; i += 256) {
            int rr = i / 38, cc = i % 38;
            int iy = oy0 + rr - 3, ix = ox0 + cc - 3;
            iy = iy < 0 ? -iy : (iy > 248 ? 496 - iy : iy);
            ix = ix < 0 ? -ix : (ix > 248 ? 496 - ix : ix);
            s_in[rr * 39 + cc] = fmaxf(fmaf(ip[iy * 249 + ix], sc, sh), 0.f);
        }
        __syncthreads();
        const float* wic = s_w + ic * 49 * 4;
        for (int ky = 0; ky < 7; ky++)
#pragma unroll
            for (int kx = 0; kx < 7; kx++) {
                const float* wb = wic + (ky * 7 + kx) * 4;
                const float* sp = s_in + (2 * ty + ky) * 39 + 2 * tx + kx;
#pragma unroll
                for (int dy = 0; dy < 2; dy++)
#pragma unroll
                    for (int dx = 0; dx < 2; dx++) {
                        unsigned long long vv = pack2(sp[dy * 39 + dx]);
                        fma_tap<4>(acc[dy * 2 + dx], vv, wb);
                    }
            }
    }
    float b0 = bias[0], b1 = bias[1], b2 = bias[2];
#pragma unroll
    for (int dy = 0; dy < 2; dy++)
#pragma unroll
        for (int dx = 0; dx < 2; dx++) {
            int oy = oy0 + 2 * ty + dy, ox = ox0 + 2 * tx + dx;
            if (oy < H && ox < H) {
                float2 a0 = unpack2(acc[dy * 2 + dx][0]);
                float2 a1 = unpack2(acc[dy * 2 + dx][1]);
                size_t base = (size_t)n * 3 * 62001 + oy * 249 + ox;
                out[base] = tanhf(a0.x + b0);
                out[base + 62001] = tanhf(a0.y + b1);
                out[base + 2 * 62001] = tanhf(a1.x + b2);
            }
        }
}

// ---------------- instance-norm stats: scale = rstd, shift = -mean*rstd --------
__global__ void k_instat(const float* __restrict__ x, float* __restrict__ scale,
                         float* __restrict__ shift, int HW) {
    int p = blockIdx.x;
    const float* xp = x + (size_t)p * HW;
    double s = 0.0, s2 = 0.0;
    for (int i = threadIdx.x; i < HW; i += 256) {
        double v = xp[i];
        s += v;
        s2 += v * v;
    }
    for (int o = 16; o > 0; o >>= 1) {
        s += __shfl_down_sync(0xffffffffu, s, o);
        s2 += __shfl_down_sync(0xffffffffu, s2, o);
    }
    __shared__ double sh[16];
    int w = threadIdx.x >> 5, l = threadIdx.x & 31;
    if (l == 0) { sh[w] = s; sh[w + 8] = s2; }
    __syncthreads();
    if (threadIdx.x == 0) {
        for (int i = 1; i < 8; i++) { s += sh[i]; s2 += sh[i + 8]; }
        double m = s / HW;
        double var = s2 / HW - m * m;
        float rs = rsqrtf(fmaxf((float)var, 0.f) + 1e-5f);
        scale[p] = rs;
        shift[p] = -(float)m * rs;
    }
}

// ---------------- segment mean ----------------
__global__ void k_segzero(float* sum, float* cnt) {
    int t = threadIdx.x;
    if (t < 96) sum[t] = 0.f;
    if (t < 32) cnt[t] = 0.f;
}
__global__ void k_segacc(const float* __restrict__ src, const int* __restrict__ inst,
                         float* __restrict__ gsum, float* __restrict__ gcnt) {
    __shared__ float ss[96];
    __shared__ float sc[32];
    int tid = threadIdx.x;
    if (tid < 96) ss[tid] = 0.f;
    if (tid < 32) sc[tid] = 0.f;
    __syncthreads();
    const int P = 62001, NP = 8 * 62001;
    for (int i = blockIdx.x * blockDim.x + tid; i < NP; i += gridDim.x * blockDim.x) {
        int n = i / P, p = i % P;
        int id = inst[i];
        const float* b = src + (size_t)n * 3 * P + p;
        atomicAdd(&ss[id * 3 + 0], b[0]);
        atomicAdd(&ss[id * 3 + 1], b[P]);
        atomicAdd(&ss[id * 3 + 2], b[2 * P]);
        atomicAdd(&sc[id], 1.f);
    }
    __syncthreads();
    if (tid < 96) atomicAdd(&gsum[tid], ss[tid]);
    if (tid < 32) atomicAdd(&gcnt[tid], sc[tid]);
}
__global__ void k_segbcast(const int* __restrict__ inst, const float* __restrict__ gsum,
                           const float* __restrict__ gcnt, float* __restrict__ out) {
    const int P = 62001, T = 8 * 3 * P;
    for (int i = blockIdx.x * blockDim.x + threadIdx.x; i < T; i += gridDim.x * blockDim.x) {
        int n = i / (3 * P), r = i % (3 * P);
        int c = r / P, p = r % P;
        int id = inst[n * P + p];
        out[i] = gsum[id * 3 + c] / fmaxf(gcnt[id], 1.f);
    }
}

// ---------------- launch ----------------
extern "C" void kernel_launch(void* const* d_in, const int* in_sizes, int n_in,
                              void* d_out, int out_size) {
    const float* x = (const float*)d_in[0];
    const int* inst = (const int*)d_in[1];
    const float* w[8];
    const float* b[8];
    for (int i = 0; i < 8; i++) {
        w[i] = (const float*)d_in[2 + 2 * i];
        b[i] = (const float*)d_in[3 + 2 * i];
    }
    float* out = (float*)d_out;

    float *A, *B, *SC, *SH;
    float *WT0, *WT1, *WT2, *WT3, *WT4, *WT5, *WT6, *WT7, *SS, *SN;
    cudaGetSymbolAddress((void**)&A, g_bufA);
    cudaGetSymbolAddress((void**)&B, g_bufB);
    cudaGetSymbolAddress((void**)&SC, g_scale);
    cudaGetSymbolAddress((void**)&SH, g_shift);
    cudaGetSymbolAddress((void**)&WT0, g_wt0);
    cudaGetSymbolAddress((void**)&WT1, g_wt1);
    cudaGetSymbolAddress((void**)&WT2, g_wt2);
    cudaGetSymbolAddress((void**)&WT3, g_wt3);
    cudaGetSymbolAddress((void**)&WT4, g_wt4);
    cudaGetSymbolAddress((void**)&WT5, g_wt5);
    cudaGetSymbolAddress((void**)&WT6, g_wt6);
    cudaGetSymbolAddress((void**)&WT7, g_wt7);
    cudaGetSymbolAddress((void**)&SS, g_segsum);
    cudaGetSymbolAddress((void**)&SN, g_segcnt);

    dim3 blk(16, 16);

    // weight transposes
    k_tr_oik<<<(3 * 49 * 32 + 255) / 256, 256>>>(w[0], WT0, 3, 32, 49);
    k_tr_oik<<<(32 * 9 * 64 + 255) / 256, 256>>>(w[1], WT1, 32, 64, 9);
    k_tr_oik<<<(64 * 9 * 128 + 255) / 256, 256>>>(w[2], WT2, 64, 128, 9);
    k_tr_oik<<<(128 * 9 * 256 + 255) / 256, 256>>>(w[3], WT3, 128, 256, 9);
    k_tr_iok<<<(256 * 9 * 128 + 255) / 256, 256>>>(w[4], WT4, 256, 128, 9);
    k_tr_iok<<<(128 * 9 * 64 + 255) / 256, 256>>>(w[5], WT5, 128, 64, 9);
    k_tr_iok<<<(64 * 9 * 32 + 255) / 256, 256>>>(w[6], WT6, 64, 32, 9);
    k_tr_w7<<<(32 * 49 * 4 + 255) / 256, 256>>>(w[7], WT7);

    // layer 0
    k_conv7_l0<<<dim3(16, 16, 8), blk>>>(x, WT0, b[0], A);
    k_instat<<<8 * 32, 256>>>(A, SC, SH, 65536);
    // layers 1-3 (downsample)
    k_conv3s2<32, 64, 4><<<dim3(8, 8, 16), blk>>>(A, WT1, b[1], SC, SH, B, 256, 256, 128, 128);
    k_instat<<<8 * 64, 256>>>(B, SC, SH, 16384);
    k_conv3s2<64, 128, 4><<<dim3(4, 4, 32), blk>>>(B, WT2, b[2], SC, SH, A, 128, 128, 64, 64);
    k_instat<<<8 * 128, 256>>>(A, SC, SH, 4096);
    k_conv3s2<128, 256, 4><<<dim3(2, 2, 64), blk>>>(A, WT3, b[3], SC, SH, B, 64, 64, 32, 32);
    k_instat<<<8 * 256, 256>>>(B, SC, SH, 1024);
    // layers 4-6 (upsample, transposed conv)
    k_convT<256, 128, 8, 16><<<dim3(2, 2, 128), blk>>>(B, WT4, b[4], SC, SH, A, 32, 32, 63, 63);
    k_instat<<<8 * 128, 256>>>(A, SC, SH, 3969);
    k_convT<128, 64, 16, 16><<<dim3(4, 4, 32), blk>>>(A, WT5, b[5], SC, SH, B, 63, 63, 125, 125);
    k_instat<<<8 * 64, 256>>>(B, SC, SH, 15625);
    k_convT<64, 32, 16, 16><<<dim3(8, 8, 16), blk>>>(B, WT6, b[6], SC, SH, A, 125, 125, 249, 249);
    k_instat<<<8 * 32, 256>>>(A, SC, SH, 62001);
    // layer 7 + tanh
    k_conv7_l7<<<dim3(8, 8, 8), blk>>>(A, WT7, b[7], SC, SH, B);
    // segment mean
    k_segzero<<<1, 128>>>(SS, SN);
    k_segacc<<<1024, 256>>>(B, inst, SS, SN);
    k_segbcast<<<2048, 256>>>(inst, SS, SN, out);
}

// round 3
// speedup vs baseline: 1.8448x; 1.6249x over previous
#include <cuda_runtime.h>
#include <math.h>

// ---------------- static scratch ----------------
__device__ __align__(16) float g_bufA[16777216];
__device__ __align__(16) float g_bufB[8388608];
__device__ __align__(16) float g_wt0[3*49*32];
__device__ __align__(16) float g_wt1[32*9*64];
__device__ __align__(16) float g_wt2[64*9*128];
__device__ __align__(16) float g_wt3[128*9*256];
__device__ __align__(16) float g_wt4[256*9*128];
__device__ __align__(16) float g_wt5[128*9*64];
__device__ __align__(16) float g_wt6[64*9*32];
__device__ __align__(16) float g_wt7[32*49*4];
__device__ float g_scale[2048];
__device__ float g_shift[2048];
__device__ float g_segsum[96];
__device__ float g_segcnt[32];

// ---------------- f32x2 packed helpers ----------------
__device__ __forceinline__ unsigned long long pack2(float v) {
    unsigned long long r;
    asm("mov.b64 %0, {%1, %1};" : "=l"(r) : "f"(v));
    return r;
}
__device__ __forceinline__ void fma2(unsigned long long& d, unsigned long long a,
                                     unsigned long long b) {
    asm("fma.rn.f32x2 %0, %1, %2, %0;" : "+l"(d) : "l"(a), "l"(b));
}
__device__ __forceinline__ float2 unpack2(unsigned long long v) {
    float2 f;
    asm("mov.b64 {%0, %1}, %2;" : "=f"(f.x), "=f"(f.y) : "l"(v));
    return f;
}
template <int OCB>
__device__ __forceinline__ void fma_tap(unsigned long long* acc, unsigned long long vv,
                                        const float* wbase) {
    const ulonglong2* wp = (const ulonglong2*)wbase;
#pragma unroll
    for (int q = 0; q < OCB / 4; q++) {
        ulonglong2 w2 = wp[q];
        fma2(acc[2 * q + 0], vv, w2.x);
        fma2(acc[2 * q + 1], vv, w2.y);
    }
}

// ---------------- cp.async helpers ----------------
__device__ __forceinline__ unsigned s2u(const void* p) {
    return (unsigned)__cvta_generic_to_shared(p);
}
__device__ __forceinline__ void cp4(unsigned dst, const float* src, bool pred) {
    asm volatile("cp.async.ca.shared.global [%0], [%1], 4, %2;" ::
                 "r"(dst), "l"(src), "r"(pred ? 4u : 0u));
}
__device__ __forceinline__ void cp16(unsigned dst, const float* src) {
    asm volatile("cp.async.ca.shared.global [%0], [%1], 16;" ::
                 "r"(dst), "l"(src));
}
__device__ __forceinline__ void cp_commit() {
    asm volatile("cp.async.commit_group;" ::: "memory");
}
template <int N>
__device__ __forceinline__ void cp_wait() {
    asm volatile("cp.async.wait_group %0;" :: "n"(N) : "memory");
}

// ---------------- fused weight prep ----------------
__global__ void k_prep(const float* __restrict__ w0, const float* __restrict__ w1,
                       const float* __restrict__ w2, const float* __restrict__ w3,
                       const float* __restrict__ w4, const float* __restrict__ w5,
                       const float* __restrict__ w6, const float* __restrict__ w7,
                       float* o0, float* o1, float* o2, float* o3,
                       float* o4, float* o5, float* o6, float* o7) {
    int idx = blockIdx.x * 256 + threadIdx.x;
    switch (blockIdx.y) {
    case 0: if (idx < 32*3*49)   { int o=idx/147,  r=idx%147,  i=r/49, k=r%49; o0[(i*49+k)*32+o]=w0[idx]; } break;
    case 1: if (idx < 64*32*9)   { int o=idx/288,  r=idx%288,  i=r/9,  k=r%9;  o1[(i*9+k)*64+o]=w1[idx]; } break;
    case 2: if (idx < 128*64*9)  { int o=idx/576,  r=idx%576,  i=r/9,  k=r%9;  o2[(i*9+k)*128+o]=w2[idx]; } break;
    case 3: if (idx < 256*128*9) { int o=idx/1152, r=idx%1152, i=r/9,  k=r%9;  o3[(i*9+k)*256+o]=w3[idx]; } break;
    case 4: if (idx < 256*128*9) { int i=idx/1152, r=idx%1152, o=r/9,  k=r%9;  o4[(i*9+k)*128+o]=w4[idx]; } break;
    case 5: if (idx < 128*64*9)  { int i=idx/576,  r=idx%576,  o=r/9,  k=r%9;  o5[(i*9+k)*64+o]=w5[idx]; } break;
    case 6: if (idx < 64*32*9)   { int i=idx/288,  r=idx%288,  o=r/9,  k=r%9;  o6[(i*9+k)*32+o]=w6[idx]; } break;
    case 7: if (idx < 32*49*4)   { int p=idx>>2, o=idx&3; int i=p/49, k=p%49;
                                   o7[idx] = (o < 3) ? w7[(o*32+i)*49+k] : 0.f; } break;
    }
}

// ---------------- layer 0: reflect-pad 7x7 conv, 3->32 ----------------
__global__ void k_conv7_l0(const float* __restrict__ x, const float* __restrict__ wt,
                           const float* __restrict__ bias, float* __restrict__ out) {
    __shared__ __align__(16) float s_w[3 * 49 * 32];
    __shared__ float s_in[3 * 484];
    int tid = threadIdx.x;
    int tx = tid & 15, ty = tid >> 4;
    int n = blockIdx.z;
    int oy0 = blockIdx.y * 16, ox0 = blockIdx.x * 16;

    for (int i = tid; i < 3 * 49 * 32; i += 256) s_w[i] = wt[i];
    const float* xp = x + (size_t)n * 3 * 65536;
    for (int i = tid; i < 3 * 484; i += 256) {
        int ic = i / 484, rr = (i % 484) / 22, cc = i % 22;
        int iy = oy0 + rr - 3, ix = ox0 + cc - 3;
        iy = iy < 0 ? -iy : (iy > 255 ? 510 - iy : iy);
        ix = ix < 0 ? -ix : (ix > 255 ? 510 - ix : ix);
        s_in[i] = xp[ic * 65536 + iy * 256 + ix];
    }
    __syncthreads();

    unsigned long long acc[16];
#pragma unroll
    for (int j = 0; j < 16; j++) acc[j] = 0ull;

    for (int ic = 0; ic < 3; ic++)
#pragma unroll 1
        for (int ky = 0; ky < 7; ky++)
#pragma unroll
            for (int kx = 0; kx < 7; kx++) {
                unsigned long long vv = pack2(s_in[ic * 484 + (ty + ky) * 22 + tx + kx]);
                fma_tap<32>(acc, vv, s_w + ((ic * 7 + ky) * 7 + kx) * 32);
            }
    int oy = oy0 + ty, ox = ox0 + tx;
    float* op = out + (size_t)n * 32 * 65536 + oy * 256 + ox;
#pragma unroll
    for (int j = 0; j < 16; j++) {
        float2 a = unpack2(acc[j]);
        op[(size_t)(2 * j + 0) * 65536] = a.x + bias[2 * j + 0];
        op[(size_t)(2 * j + 1) * 65536] = a.y + bias[2 * j + 1];
    }
}

// ---------------- 3x3 stride-2 conv, cp.async double-buffered ----------------
template <int IC, int OC, int OCB, int ICC>
__global__ void __launch_bounds__(256, 2)
k_conv3s2(const float* __restrict__ in, const float* __restrict__ wt,
          const float* __restrict__ bias, const float* __restrict__ scale,
          const float* __restrict__ shift, float* __restrict__ out,
          int Hin, int Win, int Hout, int Wout) {
    extern __shared__ float smem[];
    float* s_w  = smem;                         // 2 * ICC*9*OCB
    float* s_in = s_w + 2 * ICC * 9 * OCB;      // 2 * ICC*1089
    float* s_sc = s_in + 2 * ICC * 1089;
    float* s_sh = s_sc + IC;

    const int tid = threadIdx.x;
    const int tx = tid & 15, ty = tid >> 4;
    const int z = blockIdx.z;
    const int n = z / (OC / OCB);
    const int oc0 = (z % (OC / OCB)) * OCB;
    const int oy0 = blockIdx.y * 16, ox0 = blockIdx.x * 16;
    const int iy0 = 2 * oy0 - 1, ix0 = 2 * ox0 - 1;

    for (int i = tid; i < IC; i += 256) {
        s_sc[i] = scale[n * IC + i];
        s_sh[i] = shift[n * IC + i];
    }
    const float* inp = in + (size_t)n * IC * Hin * Win;

    auto prefetch = [&](int st, int b) {
        int ic0 = st * ICC;
        float* bw = s_w + b * (ICC * 9 * OCB);
        float* bi = s_in + b * (ICC * 1089);
        for (int i = tid; i < ICC * 1089; i += 256) {
            int icl = i / 1089, rem = i % 1089;
            int r = rem / 33, c = rem % 33;
            int iy = iy0 + r, ix = ix0 + c;
            bool ok = ((unsigned)iy < (unsigned)Hin) && ((unsigned)ix < (unsigned)Win);
            const float* src = inp + (size_t)(ic0 + icl) * Hin * Win + (ok ? iy * Win + ix : 0);
            cp4(s2u(bi + i), src, ok);
        }
        const float* wsrc = wt + (size_t)ic0 * 9 * OC + oc0;
        for (int i = tid; i < ICC * 9 * (OCB / 4); i += 256) {
            int p = i / (OCB / 4), c = i % (OCB / 4);
            cp16(s2u(bw + p * OCB + 4 * c), wsrc + (size_t)p * OC + 4 * c);
        }
    };

    unsigned long long acc[OCB / 2];
#pragma unroll
    for (int j = 0; j < OCB / 2; j++) acc[j] = 0ull;

    prefetch(0, 0);
    cp_commit();
    const int NS = IC / ICC;
    for (int s = 0; s < NS; s++) {
        if (s + 1 < NS) { prefetch(s + 1, (s + 1) & 1); cp_commit(); cp_wait<1>(); }
        else cp_wait<0>();
        __syncthreads();
        float* bi = s_in + (s & 1) * (ICC * 1089);
        const float* bw = s_w + (s & 1) * (ICC * 9 * OCB);
        // normalize + relu in place (OOB zero-pad -> 0)
        for (int i = tid; i < ICC * 1089; i += 256) {
            int icl = i / 1089, rem = i % 1089;
            int r = rem / 33, c = rem % 33;
            int iy = iy0 + r, ix = ix0 + c;
            bool ok = ((unsigned)iy < (unsigned)Hin) && ((unsigned)ix < (unsigned)Win);
            int ic = s * ICC + icl;
            float v = fmaxf(fmaf(bi[i], s_sc[ic], s_sh[ic]), 0.f);
            bi[i] = ok ? v : 0.f;
        }
        __syncthreads();
#pragma unroll 1
        for (int icl = 0; icl < ICC; icl++) {
            const float* sb = bi + icl * 1089 + (2 * ty) * 33 + 2 * tx;
            const float* wb = bw + icl * 9 * OCB;
#pragma unroll
            for (int ky = 0; ky < 3; ky++)
#pragma unroll
                for (int kx = 0; kx < 3; kx++)
                    fma_tap<OCB>(acc, pack2(sb[ky * 33 + kx]), wb + (ky * 3 + kx) * OCB);
        }
        __syncthreads();
    }

    int oy = oy0 + ty, ox = ox0 + tx;
    float* op = out + ((size_t)(n * OC + oc0) * Hout + oy) * Wout + ox;
#pragma unroll
    for (int j = 0; j < OCB / 2; j++) {
        float2 a = unpack2(acc[j]);
        op[(size_t)(2 * j + 0) * Hout * Wout] = a.x + bias[oc0 + 2 * j + 0];
        op[(size_t)(2 * j + 1) * Hout * Wout] = a.y + bias[oc0 + 2 * j + 1];
    }
}

// ---------------- 3x3 s2 transposed conv, cp.async double-buffered ----------------
template <int IC, int OC, int OCB, int ICC>
__global__ void __launch_bounds__(256, 2)
k_convT(const float* __restrict__ in, const float* __restrict__ wt,
        const float* __restrict__ bias, const float* __restrict__ scale,
        const float* __restrict__ shift, float* __restrict__ out,
        int Hin, int Win, int Hout, int Wout) {
    extern __shared__ float smem[];
    float* s_w  = smem;                        // 2 * ICC*9*OCB
    float* s_in = s_w + 2 * ICC * 9 * OCB;     // 2 * ICC*306
    float* s_sc = s_in + 2 * ICC * 306;
    float* s_sh = s_sc + IC;

    const int tid = threadIdx.x;
    const int tx = tid & 15, ty = tid >> 4;
    const int z = blockIdx.z;
    const int n = z / (OC / OCB);
    const int oc0 = (z % (OC / OCB)) * OCB;
    const int oy0 = blockIdx.y * 32, ox0 = blockIdx.x * 32;
    const int iy0 = oy0 >> 1, ix0 = ox0 >> 1;

    for (int i = tid; i < IC; i += 256) {
        s_sc[i] = scale[n * IC + i];
        s_sh[i] = shift[n * IC + i];
    }
    const float* inp = in + (size_t)n * IC * Hin * Win;

    auto prefetch = [&](int st, int b) {
        int ic0 = st * ICC;
        float* bw = s_w + b * (ICC * 9 * OCB);
        float* bi = s_in + b * (ICC * 306);
        for (int i = tid; i < ICC * 289; i += 256) {
            int icl = i / 289, rem = i % 289;
            int r = rem / 17, c = rem % 17;
            int iy = iy0 + r, ix = ix0 + c;
            bool ok = (iy < Hin) && (ix < Win);
            const float* src = inp + (size_t)(ic0 + icl) * Hin * Win + (ok ? iy * Win + ix : 0);
            cp4(s2u(bi + icl * 306 + r * 18 + c), src, ok);
        }
        const float* wsrc = wt + (size_t)ic0 * 9 * OC + oc0;
        for (int i = tid; i < ICC * 9 * (OCB / 4); i += 256) {
            int p = i / (OCB / 4), c = i % (OCB / 4);
            cp16(s2u(bw + p * OCB + 4 * c), wsrc + (size_t)p * OC + 4 * c);
        }
    };

    unsigned long long acc[4][OCB / 2];
#pragma unroll
    for (int cc = 0; cc < 4; cc++)
#pragma unroll
        for (int j = 0; j < OCB / 2; j++) acc[cc][j] = 0ull;

    prefetch(0, 0);
    cp_commit();
    const int NS = IC / ICC;
    for (int s = 0; s < NS; s++) {
        if (s + 1 < NS) { prefetch(s + 1, (s + 1) & 1); cp_commit(); cp_wait<1>(); }
        else cp_wait<0>();
        __syncthreads();
        const float* bi = s_in + (s & 1) * (ICC * 306);
        const float* bw = s_w + (s & 1) * (ICC * 9 * OCB);
#pragma unroll 4
        for (int icl = 0; icl < ICC; icl++) {
            int ic = s * ICC + icl;
            float sc = s_sc[ic], sh = s_sh[ic];
            const float* sp = bi + icl * 306 + ty * 18 + tx;
            // OOB staged values normalize to relu(sh) but only feed masked outputs.
            unsigned long long v00 = pack2(fmaxf(fmaf(sp[0], sc, sh), 0.f));
            unsigned long long v01 = pack2(fmaxf(fmaf(sp[1], sc, sh), 0.f));
            unsigned long long v10 = pack2(fmaxf(fmaf(sp[18], sc, sh), 0.f));
            unsigned long long v11 = pack2(fmaxf(fmaf(sp[19], sc, sh), 0.f));
            const float* wb = bw + icl * 9 * OCB;
            fma_tap<OCB>(acc[0], v00, wb + 4 * OCB);
            fma_tap<OCB>(acc[1], v01, wb + 3 * OCB);
            fma_tap<OCB>(acc[1], v00, wb + 5 * OCB);
            fma_tap<OCB>(acc[2], v10, wb + 1 * OCB);
            fma_tap<OCB>(acc[2], v00, wb + 7 * OCB);
            fma_tap<OCB>(acc[3], v11, wb + 0 * OCB);
            fma_tap<OCB>(acc[3], v10, wb + 2 * OCB);
            fma_tap<OCB>(acc[3], v01, wb + 6 * OCB);
            fma_tap<OCB>(acc[3], v00, wb + 8 * OCB);
        }
        __syncthreads();
    }

    int ye = oy0 + 2 * ty, xe = ox0 + 2 * tx;
    bool y0v = ye < Hout, y1v = (ye + 1) < Hout;
    bool x0v = xe < Wout, x1v = (xe + 1) < Wout;
#pragma unroll
    for (int j = 0; j < OCB / 2; j++) {
        float b0 = bias[oc0 + 2 * j], b1 = bias[oc0 + 2 * j + 1];
        float* op0 = out + (size_t)(n * OC + oc0 + 2 * j) * Hout * Wout;
        float* op1 = op0 + (size_t)Hout * Wout;
        float2 a;
        if (y0v && x0v) { a = unpack2(acc[0][j]); op0[ye * Wout + xe] = a.x + b0; op1[ye * Wout + xe] = a.y + b1; }
        if (y0v && x1v) { a = unpack2(acc[1][j]); op0[ye * Wout + xe + 1] = a.x + b0; op1[ye * Wout + xe + 1] = a.y + b1; }
        if (y1v && x0v) { a = unpack2(acc[2][j]); op0[(ye + 1) * Wout + xe] = a.x + b0; op1[(ye + 1) * Wout + xe] = a.y + b1; }
        if (y1v && x1v) { a = unpack2(acc[3][j]); op0[(ye + 1) * Wout + xe + 1] = a.x + b0; op1[(ye + 1) * Wout + xe + 1] = a.y + b1; }
    }
}

// ---------------- layer 7: reflect-pad 7x7 conv 32->3 + tanh ----------------
__global__ void __launch_bounds__(256, 2)
k_conv7_l7(const float* __restrict__ act, const float* __restrict__ wt,
           const float* __restrict__ bias, const float* __restrict__ scale,
           const float* __restrict__ shift, float* __restrict__ out) {
    extern __shared__ float smem[];
    float* s_w  = smem;                 // 6272
    float* s_in = s_w + 6272;           // 2 * 4*1482
    float* s_sc = s_in + 2 * 4 * 1482;
    float* s_sh = s_sc + 32;

    const int H = 249;
    const int tid = threadIdx.x;
    const int tx = tid & 15, ty = tid >> 4;
    const int n = blockIdx.z;
    const int oy0 = blockIdx.y * 32, ox0 = blockIdx.x * 32;

    for (int i = tid; i < 6272; i += 256) s_w[i] = wt[i];
    if (tid < 32) { s_sc[tid] = scale[n * 32 + tid]; s_sh[tid] = shift[n * 32 + tid]; }

    const float* ap = act + (size_t)n * 32 * 62001;
    auto prefetch = [&](int st, int b) {
        float* bi = s_in + b * (4 * 1482);
        int ic0 = st * 4;
        for (int i = tid; i < 4 * 1444; i += 256) {
            int icl = i / 1444, rem = i % 1444;
            int r = rem / 38, c = rem % 38;
            int iy = oy0 + r - 3, ix = ox0 + c - 3;
            iy = iy < 0 ? -iy : (iy > 248 ? 496 - iy : iy);
            ix = ix < 0 ? -ix : (ix > 248 ? 496 - ix : ix);
            cp4(s2u(bi + icl * 1482 + r * 39 + c),
                ap + (size_t)(ic0 + icl) * 62001 + iy * 249 + ix, true);
        }
    };

    unsigned long long acc[4][2];
#pragma unroll
    for (int p = 0; p < 4; p++) { acc[p][0] = 0ull; acc[p][1] = 0ull; }

    prefetch(0, 0);
    cp_commit();
    for (int s = 0; s < 8; s++) {
        if (s < 7) { prefetch(s + 1, (s + 1) & 1); cp_commit(); cp_wait<1>(); }
        else cp_wait<0>();
        __syncthreads();
        float* bi = s_in + (s & 1) * (4 * 1482);
        for (int i = tid; i < 4 * 1444; i += 256) {
            int icl = i / 1444, rem = i % 1444;
            int r = rem / 38, c = rem % 38;
            int ic = s * 4 + icl;
            float* p = bi + icl * 1482 + r * 39 + c;
            *p = fmaxf(fmaf(*p, s_sc[ic], s_sh[ic]), 0.f);
        }
        __syncthreads();
#pragma unroll 1
        for (int icl = 0; icl < 4; icl++) {
            const float* wic = s_w + (s * 4 + icl) * 196;
            const float* si = bi + icl * 1482;
#pragma unroll 1
            for (int ky = 0; ky < 7; ky++) {
                const float* sp = si + (2 * ty + ky) * 39 + 2 * tx;
                const float* wb = wic + ky * 28;
#pragma unroll
                for (int kx = 0; kx < 7; kx++)
#pragma unroll
                    for (int dy = 0; dy < 2; dy++)
#pragma unroll
                        for (int dx = 0; dx < 2; dx++)
                            fma_tap<4>(acc[dy * 2 + dx], pack2(sp[dy * 39 + kx + dx]), wb + kx * 4);
            }
        }
        __syncthreads();
    }

    float b0 = bias[0], b1 = bias[1], b2 = bias[2];
#pragma unroll
    for (int dy = 0; dy < 2; dy++)
#pragma unroll
        for (int dx = 0; dx < 2; dx++) {
            int oy = oy0 + 2 * ty + dy, ox = ox0 + 2 * tx + dx;
            if (oy < H && ox < H) {
                float2 a0 = unpack2(acc[dy * 2 + dx][0]);
                float2 a1 = unpack2(acc[dy * 2 + dx][1]);
                size_t base = (size_t)n * 3 * 62001 + oy * 249 + ox;
                out[base] = tanhf(a0.x + b0);
                out[base + 62001] = tanhf(a0.y + b1);
                out[base + 2 * 62001] = tanhf(a1.x + b2);
            }
        }
}

// ---------------- instance-norm stats (fp32, 4 chains) ----------------
__global__ void k_instat(const float* __restrict__ x, float* __restrict__ scale,
                         float* __restrict__ shift, int HW) {
    int p = blockIdx.x;
    const float* xp = x + (size_t)p * HW;
    float s0 = 0, s1 = 0, q0 = 0, q1 = 0;
    int i = threadIdx.x;
    for (; i + 256 < HW; i += 512) {
        float a = xp[i], b = xp[i + 256];
        s0 += a; q0 += a * a;
        s1 += b; q1 += b * b;
    }
    if (i < HW) { float a = xp[i]; s0 += a; q0 += a * a; }
    float s = s0 + s1, q = q0 + q1;
    for (int o = 16; o > 0; o >>= 1) {
        s += __shfl_down_sync(0xffffffffu, s, o);
        q += __shfl_down_sync(0xffffffffu, q, o);
    }
    __shared__ float sh[16];
    int w = threadIdx.x >> 5, l = threadIdx.x & 31;
    if (l == 0) { sh[w] = s; sh[w + 8] = q; }
    __syncthreads();
    if (threadIdx.x == 0) {
        for (int k = 1; k < 8; k++) { s += sh[k]; q += sh[k + 8]; }
        float m = s / HW;
        float var = q / HW - m * m;
        float rs = rsqrtf(fmaxf(var, 0.f) + 1e-5f);
        scale[p] = rs;
        shift[p] = -m * rs;
    }
}

// ---------------- segment mean ----------------
__global__ void k_segzero(float* sum, float* cnt) {
    int t = threadIdx.x;
    if (t < 96) sum[t] = 0.f;
    if (t < 32) cnt[t] = 0.f;
}
__global__ void k_segacc(const float* __restrict__ src, const int* __restrict__ inst,
                         float* __restrict__ gsum, float* __restrict__ gcnt) {
    __shared__ float ss[96];
    __shared__ float sc[32];
    int tid = threadIdx.x;
    if (tid < 96) ss[tid] = 0.f;
    if (tid < 32) sc[tid] = 0.f;
    __syncthreads();
    const int P = 62001, NP = 8 * 62001;
    for (int i = blockIdx.x * blockDim.x + tid; i < NP; i += gridDim.x * blockDim.x) {
        int n = i / P, p = i % P;
        int id = inst[i];
        const float* b = src + (size_t)n * 3 * P + p;
        atomicAdd(&ss[id * 3 + 0], b[0]);
        atomicAdd(&ss[id * 3 + 1], b[P]);
        atomicAdd(&ss[id * 3 + 2], b[2 * P]);
        atomicAdd(&sc[id], 1.f);
    }
    __syncthreads();
    if (tid < 96) atomicAdd(&gsum[tid], ss[tid]);
    if (tid < 32) atomicAdd(&gcnt[tid], sc[tid]);
}
__global__ void k_segbcast(const int* __restrict__ inst, const float* __restrict__ gsum,
                           const float* __restrict__ gcnt, float* __restrict__ out) {
    const int P = 62001, T = 8 * 3 * P;
    for (int i = blockIdx.x * blockDim.x + threadIdx.x; i < T; i += gridDim.x * blockDim.x) {
        int n = i / (3 * P), r = i % (3 * P);
        int c = r / P, p = r % P;
        int id = inst[n * P + p];
        out[i] = gsum[id * 3 + c] / fmaxf(gcnt[id], 1.f);
    }
}

// ---------------- launch ----------------
extern "C" void kernel_launch(void* const* d_in, const int* in_sizes, int n_in,
                              void* d_out, int out_size) {
    const float* x = (const float*)d_in[0];
    const int* inst = (const int*)d_in[1];
    const float* w[8];
    const float* b[8];
    for (int i = 0; i < 8; i++) {
        w[i] = (const float*)d_in[2 + 2 * i];
        b[i] = (const float*)d_in[3 + 2 * i];
    }
    float* out = (float*)d_out;

    float *A, *B, *SC, *SH;
    float *WT0, *WT1, *WT2, *WT3, *WT4, *WT5, *WT6, *WT7, *SS, *SN;
    cudaGetSymbolAddress((void**)&A, g_bufA);
    cudaGetSymbolAddress((void**)&B, g_bufB);
    cudaGetSymbolAddress((void**)&SC, g_scale);
    cudaGetSymbolAddress((void**)&SH, g_shift);
    cudaGetSymbolAddress((void**)&WT0, g_wt0);
    cudaGetSymbolAddress((void**)&WT1, g_wt1);
    cudaGetSymbolAddress((void**)&WT2, g_wt2);
    cudaGetSymbolAddress((void**)&WT3, g_wt3);
    cudaGetSymbolAddress((void**)&WT4, g_wt4);
    cudaGetSymbolAddress((void**)&WT5, g_wt5);
    cudaGetSymbolAddress((void**)&WT6, g_wt6);
    cudaGetSymbolAddress((void**)&WT7, g_wt7);
    cudaGetSymbolAddress((void**)&SS, g_segsum);
    cudaGetSymbolAddress((void**)&SN, g_segcnt);

    // dynamic smem sizes (bytes)
    const int SM_C1 = (2*8*9*64 + 2*8*1089 + 2*32) * 4;
    const int SM_C2 = (2*8*9*64 + 2*8*1089 + 2*64) * 4;
    const int SM_C3 = (2*8*9*32 + 2*8*1089 + 2*128) * 4;
    const int SM_T4 = (2*16*9*16 + 2*16*306 + 2*256) * 4;
    const int SM_T5 = (2*16*9*16 + 2*16*306 + 2*128) * 4;
    const int SM_T6 = (2*16*9*16 + 2*16*306 + 2*64) * 4;
    const int SM_L7 = (6272 + 2*4*1482 + 2*32) * 4;

    cudaFuncSetAttribute(k_conv3s2<32, 64, 64, 8>,  cudaFuncAttributeMaxDynamicSharedMemorySize, SM_C1);
    cudaFuncSetAttribute(k_conv3s2<64, 128, 64, 8>, cudaFuncAttributeMaxDynamicSharedMemorySize, SM_C2);
    cudaFuncSetAttribute(k_conv3s2<128, 256, 32, 8>,cudaFuncAttributeMaxDynamicSharedMemorySize, SM_C3);
    cudaFuncSetAttribute(k_convT<256, 128, 16, 16>, cudaFuncAttributeMaxDynamicSharedMemorySize, SM_T4);
    cudaFuncSetAttribute(k_convT<128, 64, 16, 16>,  cudaFuncAttributeMaxDynamicSharedMemorySize, SM_T5);
    cudaFuncSetAttribute(k_convT<64, 32, 16, 16>,   cudaFuncAttributeMaxDynamicSharedMemorySize, SM_T6);
    cudaFuncSetAttribute(k_conv7_l7,                cudaFuncAttributeMaxDynamicSharedMemorySize, SM_L7);

    // launch 0: fused weight prep
    k_prep<<<dim3(1152, 8), 256>>>(w[0], w[1], w[2], w[3], w[4], w[5], w[6], w[7],
                                   WT0, WT1, WT2, WT3, WT4, WT5, WT6, WT7);
    // launch 1: layer 0
    k_conv7_l0<<<dim3(16, 16, 8), 256>>>(x, WT0, b[0], A);
    k_instat<<<8 * 32, 256>>>(A, SC, SH, 65536);
    // layers 1-3
    k_conv3s2<32, 64, 64, 8><<<dim3(8, 8, 8), 256, SM_C1>>>(A, WT1, b[1], SC, SH, B, 256, 256, 128, 128);
    k_instat<<<8 * 64, 256>>>(B, SC, SH, 16384);
    k_conv3s2<64, 128, 64, 8><<<dim3(4, 4, 16), 256, SM_C2>>>(B, WT2, b[2], SC, SH, A, 128, 128, 64, 64);
    k_instat<<<8 * 128, 256>>>(A, SC, SH, 4096);
    k_conv3s2<128, 256, 32, 8><<<dim3(2, 2, 64), 256, SM_C3>>>(A, WT3, b[3], SC, SH, B, 64, 64, 32, 32);
    k_instat<<<8 * 256, 256>>>(B, SC, SH, 1024);
    // layers 4-6
    k_convT<256, 128, 16, 16><<<dim3(2, 2, 64), 256, SM_T4>>>(B, WT4, b[4], SC, SH, A, 32, 32, 63, 63);
    k_instat<<<8 * 128, 256>>>(A, SC, SH, 3969);
    k_convT<128, 64, 16, 16><<<dim3(4, 4, 32), 256, SM_T5>>>(A, WT5, b[5], SC, SH, B, 63, 63, 125, 125);
    k_instat<<<8 * 64, 256>>>(B, SC, SH, 15625);
    k_convT<64, 32, 16, 16><<<dim3(8, 8, 16), 256, SM_T6>>>(B, WT6, b[6], SC, SH, A, 125, 125, 249, 249);
    k_instat<<<8 * 32, 256>>>(A, SC, SH, 62001);
    // layer 7
    k_conv7_l7<<<dim3(8, 8, 8), 256, SM_L7>>>(A, WT7, b[7], SC, SH, B);
    // segment mean
    k_segzero<<<1, 128>>>(SS, SN);
    k_segacc<<<1024, 256>>>(B, inst, SS, SN);
    k_segbcast<<<2048, 256>>>(inst, SS, SN, out);
}

// round 7
// speedup vs baseline: 2.0992x; 1.1379x over previous
#include <cuda_runtime.h>
#include <math.h>

// ---------------- static scratch ----------------
__device__ __align__(16) float g_bufA[16777216];
__device__ __align__(16) float g_bufB[8388608];
__device__ __align__(16) float g_wt0[3*49*32];
__device__ __align__(16) float g_wt1[32*9*64];
__device__ __align__(16) float g_wt2[64*9*128];
__device__ __align__(16) float g_wt3[128*9*256];
__device__ __align__(16) float g_wt4[256*9*128];
__device__ __align__(16) float g_wt5[128*9*64];
__device__ __align__(16) float g_wt6[64*9*32];
__device__ __align__(16) float g_wt7[32*49*4];
__device__ float g_scale[2048];
__device__ float g_shift[2048];
__device__ float g_segsum[96];
__device__ float g_segcnt[32];

typedef unsigned long long ull;

// ---------------- f32x2 packed helpers ----------------
__device__ __forceinline__ ull pack2(float v) {
    ull r;
    asm("mov.b64 %0, {%1, %1};" : "=l"(r) : "f"(v));
    return r;
}
__device__ __forceinline__ void fma2(ull& d, ull a, ull b) {
    asm("fma.rn.f32x2 %0, %1, %2, %0;" : "+l"(d) : "l"(a), "l"(b));
}
__device__ __forceinline__ float2 unpack2(ull v) {
    float2 f;
    asm("mov.b64 {%0, %1}, %2;" : "=f"(f.x), "=f"(f.y) : "l"(v));
    return f;
}

// ---------------- cp.async helpers ----------------
__device__ __forceinline__ unsigned s2u(const void* p) {
    return (unsigned)__cvta_generic_to_shared(p);
}
__device__ __forceinline__ void cp4(unsigned dst, const float* src, bool pred) {
    asm volatile("cp.async.ca.shared.global [%0], [%1], 4, %2;" ::
                 "r"(dst), "l"(src), "r"(pred ? 4u : 0u));
}
__device__ __forceinline__ void cp16(unsigned dst, const float* src) {
    asm volatile("cp.async.ca.shared.global [%0], [%1], 16;" ::
                 "r"(dst), "l"(src));
}
__device__ __forceinline__ void cp_commit() {
    asm volatile("cp.async.commit_group;" ::: "memory");
}
template <int N>
__device__ __forceinline__ void cp_wait() {
    asm volatile("cp.async.wait_group %0;" :: "n"(N) : "memory");
}

// ---------------- fused weight prep ----------------
__global__ void k_prep(const float* __restrict__ w0, const float* __restrict__ w1,
                       const float* __restrict__ w2, const float* __restrict__ w3,
                       const float* __restrict__ w4, const float* __restrict__ w5,
                       const float* __restrict__ w6, const float* __restrict__ w7,
                       float* o0, float* o1, float* o2, float* o3,
                       float* o4, float* o5, float* o6, float* o7) {
    int idx = blockIdx.x * 256 + threadIdx.x;
    switch (blockIdx.y) {
    case 0: if (idx < 32*3*49)   { int o=idx/147,  r=idx%147,  i=r/49, k=r%49; o0[(i*49+k)*32+o]=w0[idx]; } break;
    case 1: if (idx < 64*32*9)   { int o=idx/288,  r=idx%288,  i=r/9,  k=r%9;  o1[(i*9+k)*64+o]=w1[idx]; } break;
    case 2: if (idx < 128*64*9)  { int o=idx/576,  r=idx%576,  i=r/9,  k=r%9;  o2[(i*9+k)*128+o]=w2[idx]; } break;
    case 3: if (idx < 256*128*9) { int o=idx/1152, r=idx%1152, i=r/9,  k=r%9;  o3[(i*9+k)*256+o]=w3[idx]; } break;
    case 4: if (idx < 256*128*9) { int i=idx/1152, r=idx%1152, o=r/9,  k=r%9;  o4[(i*9+k)*128+o]=w4[idx]; } break;
    case 5: if (idx < 128*64*9)  { int i=idx/576,  r=idx%576,  o=r/9,  k=r%9;  o5[(i*9+k)*64+o]=w5[idx]; } break;
    case 6: if (idx < 64*32*9)   { int i=idx/288,  r=idx%288,  o=r/9,  k=r%9;  o6[(i*9+k)*32+o]=w6[idx]; } break;
    case 7: if (idx < 32*49*4)   { int p=idx>>2, o=idx&3; int i=p/49, k=p%49;
                                   o7[idx] = (o < 3) ? w7[(o*32+i)*49+k] : 0.f; } break;
    }
}

// ---------------- layer 0: reflect-pad 7x7 conv, 3->32, 2px x 16oc / thread ----
__global__ void __launch_bounds__(256)
k_conv7_l0(const float* __restrict__ x, const float* __restrict__ wt,
           const float* __restrict__ bias, float* __restrict__ out) {
    __shared__ __align__(16) float s_w[3 * 49 * 32];
    __shared__ float s_in[3 * 484];
    const int tid = threadIdx.x;
    const int og = tid >> 7;            // oc half: og*16
    const int rem = tid & 127;
    const int ty = rem >> 4;            // 0..7 -> rows ty, ty+8
    const int tx = rem & 15;
    const int n = blockIdx.z;
    const int oy0 = blockIdx.y * 16, ox0 = blockIdx.x * 16;

    for (int i = tid; i < 3 * 49 * 32; i += 256) s_w[i] = wt[i];
    const float* xp = x + (size_t)n * 3 * 65536;
    for (int i = tid; i < 3 * 484; i += 256) {
        int ic = i / 484, rr = (i % 484) / 22, cc = i % 22;
        int iy = oy0 + rr - 3, ix = ox0 + cc - 3;
        iy = iy < 0 ? -iy : (iy > 255 ? 510 - iy : iy);
        ix = ix < 0 ? -ix : (ix > 255 ? 510 - ix : ix);
        s_in[i] = xp[ic * 65536 + iy * 256 + ix];
    }
    __syncthreads();

    ull acc0[8], acc1[8];
#pragma unroll
    for (int j = 0; j < 8; j++) { acc0[j] = 0ull; acc1[j] = 0ull; }

    for (int ic = 0; ic < 3; ic++)
#pragma unroll 1
        for (int ky = 0; ky < 7; ky++)
#pragma unroll
            for (int kx = 0; kx < 7; kx++) {
                ull v0 = pack2(s_in[ic * 484 + (ty + ky) * 22 + tx + kx]);
                ull v1 = pack2(s_in[ic * 484 + (ty + 8 + ky) * 22 + tx + kx]);
                const ulonglong2* wp =
                    (const ulonglong2*)(s_w + ((ic * 7 + ky) * 7 + kx) * 32 + og * 16);
#pragma unroll
                for (int q = 0; q < 4; q++) {
                    ulonglong2 w2 = wp[q];
                    fma2(acc0[2 * q + 0], v0, w2.x);
                    fma2(acc0[2 * q + 1], v0, w2.y);
                    fma2(acc1[2 * q + 0], v1, w2.x);
                    fma2(acc1[2 * q + 1], v1, w2.y);
                }
            }
    int oy = oy0 + ty, ox = ox0 + tx;
    float* op = out + (size_t)n * 32 * 65536 + (size_t)(og * 16) * 65536 + oy * 256 + ox;
#pragma unroll
    for (int j = 0; j < 8; j++) {
        float2 a = unpack2(acc0[j]);
        float2 b = unpack2(acc1[j]);
        float bz0 = bias[og * 16 + 2 * j], bz1 = bias[og * 16 + 2 * j + 1];
        op[(size_t)(2 * j + 0) * 65536] = a.x + bz0;
        op[(size_t)(2 * j + 1) * 65536] = a.y + bz1;
        op[(size_t)(2 * j + 0) * 65536 + 8 * 256] = b.x + bz0;
        op[(size_t)(2 * j + 1) * 65536 + 8 * 256] = b.y + bz1;
    }
}

// ---------------- 3x3 stride-2 conv, 2px x 32oc / thread, cp.async pipelined ----
template <int IC, int OC, int ICC>
__global__ void __launch_bounds__(256, 2)
k_conv3s2(const float* __restrict__ in, const float* __restrict__ wt,
          const float* __restrict__ bias, const float* __restrict__ scale,
          const float* __restrict__ shift, float* __restrict__ out,
          int Hin, int Win, int Hout, int Wout) {
    const int OCB = 64;
    extern __shared__ float smem[];
    float* s_w  = smem;                         // 2 * ICC*9*64
    float* s_in = s_w + 2 * ICC * 9 * OCB;      // 2 * ICC*1089
    float* s_sc = s_in + 2 * ICC * 1089;
    float* s_sh = s_sc + IC;

    const int tid = threadIdx.x;
    const int og = tid >> 7;            // oc half: og*32
    const int rem = tid & 127;
    const int ty = rem >> 4;            // rows ty, ty+8
    const int tx = rem & 15;
    const int z = blockIdx.z;
    const int n = z / (OC / OCB);
    const int oc0 = (z % (OC / OCB)) * OCB;
    const int oy0 = blockIdx.y * 16, ox0 = blockIdx.x * 16;
    const int iy0 = 2 * oy0 - 1, ix0 = 2 * ox0 - 1;

    for (int i = tid; i < IC; i += 256) {
        s_sc[i] = scale[n * IC + i];
        s_sh[i] = shift[n * IC + i];
    }
    const float* inp = in + (size_t)n * IC * Hin * Win;

    auto prefetch = [&](int st, int b) {
        int ic0 = st * ICC;
        float* bw = s_w + b * (ICC * 9 * OCB);
        float* bi = s_in + b * (ICC * 1089);
        for (int i = tid; i < ICC * 1089; i += 256) {
            int icl = i / 1089, r2 = i % 1089;
            int r = r2 / 33, c = r2 % 33;
            int iy = iy0 + r, ix = ix0 + c;
            bool ok = ((unsigned)iy < (unsigned)Hin) && ((unsigned)ix < (unsigned)Win);
            const float* src = inp + (size_t)(ic0 + icl) * Hin * Win + (ok ? iy * Win + ix : 0);
            cp4(s2u(bi + i), src, ok);
        }
        const float* wsrc = wt + (size_t)ic0 * 9 * OC + oc0;
        for (int i = tid; i < ICC * 9 * (OCB / 4); i += 256) {
            int p = i / (OCB / 4), c = i % (OCB / 4);
            cp16(s2u(bw + p * OCB + 4 * c), wsrc + (size_t)p * OC + 4 * c);
        }
    };

    ull acc0[16], acc1[16];
#pragma unroll
    for (int j = 0; j < 16; j++) { acc0[j] = 0ull; acc1[j] = 0ull; }

    prefetch(0, 0);
    cp_commit();
    const int NS = IC / ICC;
    for (int s = 0; s < NS; s++) {
        if (s + 1 < NS) { prefetch(s + 1, (s + 1) & 1); cp_commit(); cp_wait<1>(); }
        else cp_wait<0>();
        __syncthreads();
        float* bi = s_in + (s & 1) * (ICC * 1089);
        const float* bw = s_w + (s & 1) * (ICC * 9 * OCB);
        // normalize + relu in place (OOB zero-pad -> 0)
        for (int i = tid; i < ICC * 1089; i += 256) {
            int icl = i / 1089, r2 = i % 1089;
            int r = r2 / 33, c = r2 % 33;
            int iy = iy0 + r, ix = ix0 + c;
            bool ok = ((unsigned)iy < (unsigned)Hin) && ((unsigned)ix < (unsigned)Win);
            int ic = s * ICC + icl;
            float v = fmaxf(fmaf(bi[i], s_sc[ic], s_sh[ic]), 0.f);
            bi[i] = ok ? v : 0.f;
        }
        __syncthreads();
#pragma unroll 1
        for (int icl = 0; icl < ICC; icl++) {
            const float* sb0 = bi + icl * 1089 + (2 * ty) * 33 + 2 * tx;
            const float* sb1 = sb0 + 528;   // +16 rows
            const float* wb = bw + icl * 9 * OCB + og * 32;
#pragma unroll
            for (int ky = 0; ky < 3; ky++)
#pragma unroll
                for (int kx = 0; kx < 3; kx++) {
                    ull v0 = pack2(sb0[ky * 33 + kx]);
                    ull v1 = pack2(sb1[ky * 33 + kx]);
                    const ulonglong2* wp = (const ulonglong2*)(wb + (ky * 3 + kx) * OCB);
#pragma unroll
                    for (int q = 0; q < 8; q++) {
                        ulonglong2 w2 = wp[q];
                        fma2(acc0[2 * q + 0], v0, w2.x);
                        fma2(acc0[2 * q + 1], v0, w2.y);
                        fma2(acc1[2 * q + 0], v1, w2.x);
                        fma2(acc1[2 * q + 1], v1, w2.y);
                    }
                }
        }
        __syncthreads();
    }

    int oy = oy0 + ty, ox = ox0 + tx;
    int ocb = oc0 + og * 32;
    float* op = out + ((size_t)(n * OC + ocb) * Hout + oy) * Wout + ox;
    const size_t cs = (size_t)Hout * Wout;
#pragma unroll
    for (int j = 0; j < 16; j++) {
        float2 a = unpack2(acc0[j]);
        float2 b = unpack2(acc1[j]);
        float bz0 = bias[ocb + 2 * j], bz1 = bias[ocb + 2 * j + 1];
        op[(size_t)(2 * j + 0) * cs] = a.x + bz0;
        op[(size_t)(2 * j + 1) * cs] = a.y + bz1;
        op[(size_t)(2 * j + 0) * cs + 8 * Wout] = b.x + bz0;
        op[(size_t)(2 * j + 1) * cs + 8 * Wout] = b.y + bz1;
    }
}

// ---------------- convT: 8oc, two 2x2 parity blocks / thread, 32x64 out tile ----
__device__ __forceinline__ void tap8(ull* A, ull* B, ull va, ull vb,
                                     const ulonglong2* wp) {
    ulonglong2 w0 = wp[0], w1 = wp[1];
    fma2(A[0], va, w0.x); fma2(A[1], va, w0.y);
    fma2(A[2], va, w1.x); fma2(A[3], va, w1.y);
    fma2(B[0], vb, w0.x); fma2(B[1], vb, w0.y);
    fma2(B[2], vb, w1.x); fma2(B[3], vb, w1.y);
}

template <int IC, int OC, int ICC>
__global__ void __launch_bounds__(256, 2)
k_convT(const float* __restrict__ in, const float* __restrict__ wt,
        const float* __restrict__ bias, const float* __restrict__ scale,
        const float* __restrict__ shift, float* __restrict__ out,
        int Hin, int Win, int Hout, int Wout) {
    const int OCB = 8;
    extern __shared__ float smem[];
    float* s_w  = smem;                        // 2 * ICC*9*8
    float* s_in = s_w + 2 * ICC * 9 * OCB;     // 2 * ICC*578 (17x34)
    float* s_sc = s_in + 2 * ICC * 578;
    float* s_sh = s_sc + IC;

    const int tid = threadIdx.x;
    const int ty = tid >> 4;       // 0..15 parity row
    const int tx = tid & 15;       // parity cols tx and tx+16
    const int z = blockIdx.z;
    const int n = z / (OC / OCB);
    const int oc0 = (z % (OC / OCB)) * OCB;
    const int oy0 = blockIdx.y * 32, ox0 = blockIdx.x * 64;
    const int iy0 = oy0 >> 1, ix0 = ox0 >> 1;

    for (int i = tid; i < IC; i += 256) {
        s_sc[i] = scale[n * IC + i];
        s_sh[i] = shift[n * IC + i];
    }
    const float* inp = in + (size_t)n * IC * Hin * Win;

    auto prefetch = [&](int st, int b) {
        int ic0 = st * ICC;
        float* bw = s_w + b * (ICC * 9 * OCB);
        float* bi = s_in + b * (ICC * 578);
        for (int i = tid; i < ICC * 561; i += 256) {   // 17*33
            int icl = i / 561, r2 = i % 561;
            int r = r2 / 33, c = r2 % 33;
            int iy = iy0 + r, ix = ix0 + c;
            bool ok = (iy < Hin) && (ix < Win);
            const float* src = inp + (size_t)(ic0 + icl) * Hin * Win + (ok ? iy * Win + ix : 0);
            cp4(s2u(bi + icl * 578 + r * 34 + c), src, ok);
        }
        const float* wsrc = wt + (size_t)ic0 * 9 * OC + oc0;
        for (int i = tid; i < ICC * 9 * (OCB / 4); i += 256) {
            int p = i / (OCB / 4), c = i % (OCB / 4);
            cp16(s2u(bw + p * OCB + 4 * c), wsrc + (size_t)p * OC + 4 * c);
        }
    };

    ull acc[2][4][4];
#pragma unroll
    for (int b2 = 0; b2 < 2; b2++)
#pragma unroll
        for (int c = 0; c < 4; c++)
#pragma unroll
            for (int j = 0; j < 4; j++) acc[b2][c][j] = 0ull;

    prefetch(0, 0);
    cp_commit();
    const int NS = IC / ICC;
    for (int s = 0; s < NS; s++) {
        if (s + 1 < NS) { prefetch(s + 1, (s + 1) & 1); cp_commit(); cp_wait<1>(); }
        else cp_wait<0>();
        __syncthreads();
        const float* bi = s_in + (s & 1) * (ICC * 578);
        const float* bw = s_w + (s & 1) * (ICC * 9 * OCB);
#pragma unroll 2
        for (int icl = 0; icl < ICC; icl++) {
            int ic = s * ICC + icl;
            float sc = s_sc[ic], sh = s_sh[ic];
            const float* sp = bi + icl * 578 + ty * 34 + tx;
            // OOB staged zeros normalize to relu(sh) but feed only masked outputs.
            ull a00 = pack2(fmaxf(fmaf(sp[0], sc, sh), 0.f));
            ull a01 = pack2(fmaxf(fmaf(sp[1], sc, sh), 0.f));
            ull a10 = pack2(fmaxf(fmaf(sp[34], sc, sh), 0.f));
            ull a11 = pack2(fmaxf(fmaf(sp[35], sc, sh), 0.f));
            ull b00 = pack2(fmaxf(fmaf(sp[16], sc, sh), 0.f));
            ull b01 = pack2(fmaxf(fmaf(sp[17], sc, sh), 0.f));
            ull b10 = pack2(fmaxf(fmaf(sp[50], sc, sh), 0.f));
            ull b11 = pack2(fmaxf(fmaf(sp[51], sc, sh), 0.f));
            const ulonglong2* wp = (const ulonglong2*)(bw + icl * 9 * OCB);
            tap8(acc[0][3], acc[1][3], a11, b11, wp + 0);   // tap0
            tap8(acc[0][2], acc[1][2], a10, b10, wp + 2);   // tap1
            tap8(acc[0][3], acc[1][3], a10, b10, wp + 4);   // tap2
            tap8(acc[0][1], acc[1][1], a01, b01, wp + 6);   // tap3
            tap8(acc[0][0], acc[1][0], a00, b00, wp + 8);   // tap4
            tap8(acc[0][1], acc[1][1], a00, b00, wp + 10);  // tap5
            tap8(acc[0][3], acc[1][3], a01, b01, wp + 12);  // tap6
            tap8(acc[0][2], acc[1][2], a00, b00, wp + 14);  // tap7
            tap8(acc[0][3], acc[1][3], a00, b00, wp + 16);  // tap8
        }
        __syncthreads();
    }

    const size_t cs = (size_t)Hout * Wout;
#pragma unroll
    for (int b2 = 0; b2 < 2; b2++) {
        int ye = oy0 + 2 * ty;
        int xe = ox0 + 2 * (tx + b2 * 16);
        bool y0v = ye < Hout, y1v = (ye + 1) < Hout;
        bool x0v = xe < Wout, x1v = (xe + 1) < Wout;
#pragma unroll
        for (int j = 0; j < 4; j++) {
            float bz0 = bias[oc0 + 2 * j], bz1 = bias[oc0 + 2 * j + 1];
            float* op0 = out + (size_t)(n * OC + oc0 + 2 * j) * cs;
            float* op1 = op0 + cs;
            float2 a;
            if (y0v && x0v) { a = unpack2(acc[b2][0][j]); op0[ye * Wout + xe] = a.x + bz0; op1[ye * Wout + xe] = a.y + bz1; }
            if (y0v && x1v) { a = unpack2(acc[b2][1][j]); op0[ye * Wout + xe + 1] = a.x + bz0; op1[ye * Wout + xe + 1] = a.y + bz1; }
            if (y1v && x0v) { a = unpack2(acc[b2][2][j]); op0[(ye + 1) * Wout + xe] = a.x + bz0; op1[(ye + 1) * Wout + xe] = a.y + bz1; }
            if (y1v && x1v) { a = unpack2(acc[b2][3][j]); op0[(ye + 1) * Wout + xe + 1] = a.x + bz0; op1[(ye + 1) * Wout + xe + 1] = a.y + bz1; }
        }
    }
}

// ---------------- layer 7: 7x7 conv 32->3 + tanh, row-cached ----------------
__global__ void __launch_bounds__(256, 2)
k_conv7_l7(const float* __restrict__ act, const float* __restrict__ wt,
           const float* __restrict__ bias, const float* __restrict__ scale,
           const float* __restrict__ shift, float* __restrict__ out) {
    extern __shared__ float smem[];
    float* s_w  = smem;                 // 6272
    float* s_in = s_w + 6272;           // 2 * 4*1482
    float* s_sc = s_in + 2 * 4 * 1482;
    float* s_sh = s_sc + 32;

    const int H = 249;
    const int tid = threadIdx.x;
    const int tx = tid & 15, ty = tid >> 4;
    const int n = blockIdx.z;
    const int oy0 = blockIdx.y * 32, ox0 = blockIdx.x * 32;

    for (int i = tid; i < 6272; i += 256) s_w[i] = wt[i];
    if (tid < 32) { s_sc[tid] = scale[n * 32 + tid]; s_sh[tid] = shift[n * 32 + tid]; }

    const float* ap = act + (size_t)n * 32 * 62001;
    auto prefetch = [&](int st, int b) {
        float* bi = s_in + b * (4 * 1482);
        int ic0 = st * 4;
        for (int i = tid; i < 4 * 1444; i += 256) {
            int icl = i / 1444, r2 = i % 1444;
            int r = r2 / 38, c = r2 % 38;
            int iy = oy0 + r - 3, ix = ox0 + c - 3;
            iy = iy < 0 ? -iy : (iy > 248 ? 496 - iy : iy);
            ix = ix < 0 ? -ix : (ix > 248 ? 496 - ix : ix);
            cp4(s2u(bi + icl * 1482 + r * 39 + c),
                ap + (size_t)(ic0 + icl) * 62001 + iy * 249 + ix, true);
        }
    };

    ull acc[4][2];
#pragma unroll
    for (int p = 0; p < 4; p++) { acc[p][0] = 0ull; acc[p][1] = 0ull; }

    prefetch(0, 0);
    cp_commit();
    for (int s = 0; s < 8; s++) {
        if (s < 7) { prefetch(s + 1, (s + 1) & 1); cp_commit(); cp_wait<1>(); }
        else cp_wait<0>();
        __syncthreads();
        float* bi = s_in + (s & 1) * (4 * 1482);
        for (int i = tid; i < 4 * 1444; i += 256) {
            int icl = i / 1444, r2 = i % 1444;
            int r = r2 / 38, c = r2 % 38;
            int ic = s * 4 + icl;
            float* p = bi + icl * 1482 + r * 39 + c;
            *p = fmaxf(fmaf(*p, s_sc[ic], s_sh[ic]), 0.f);
        }
        __syncthreads();
#pragma unroll 1
        for (int icl = 0; icl < 4; icl++) {
            const float* wic = s_w + (s * 4 + icl) * 196;
            const float* si = bi + icl * 1482;
#pragma unroll 1
            for (int ky = 0; ky < 7; ky++) {
                const float* sp0 = si + (2 * ty + ky) * 39 + 2 * tx;
                ull r0[9], r1[9];
#pragma unroll
                for (int k = 0; k < 9; k++) {
                    r0[k] = pack2(sp0[k]);
                    r1[k] = pack2(sp0[39 + k]);
                }
                const ulonglong2* wp = (const ulonglong2*)(wic + ky * 28);
#pragma unroll
                for (int kx = 0; kx < 7; kx++) {
                    ulonglong2 w2 = wp[kx];
                    fma2(acc[0][0], r0[kx], w2.x);     fma2(acc[0][1], r0[kx], w2.y);
                    fma2(acc[1][0], r0[kx + 1], w2.x); fma2(acc[1][1], r0[kx + 1], w2.y);
                    fma2(acc[2][0], r1[kx], w2.x);     fma2(acc[2][1], r1[kx], w2.y);
                    fma2(acc[3][0], r1[kx + 1], w2.x); fma2(acc[3][1], r1[kx + 1], w2.y);
                }
            }
        }
        __syncthreads();
    }

    float b0 = bias[0], b1 = bias[1], b2 = bias[2];
#pragma unroll
    for (int dy = 0; dy < 2; dy++)
#pragma unroll
        for (int dx = 0; dx < 2; dx++) {
            int oy = oy0 + 2 * ty + dy, ox = ox0 + 2 * tx + dx;
            if (oy < H && ox < H) {
                float2 a0 = unpack2(acc[dy * 2 + dx][0]);
                float2 a1 = unpack2(acc[dy * 2 + dx][1]);
                size_t base = (size_t)n * 3 * 62001 + oy * 249 + ox;
                out[base] = tanhf(a0.x + b0);
                out[base + 62001] = tanhf(a0.y + b1);
                out[base + 2 * 62001] = tanhf(a1.x + b2);
            }
        }
}

// ---------------- instance-norm stats (fp32, vectorized) ----------------
__global__ void k_instat(const float* __restrict__ x, float* __restrict__ scale,
                         float* __restrict__ shift, int HW) {
    int p = blockIdx.x;
    const float* xp = x + (size_t)p * HW;
    float s0 = 0, s1 = 0, q0 = 0, q1 = 0;
    if ((HW & 3) == 0) {
        const float4* x4 = (const float4*)xp;
        int n4 = HW >> 2;
        for (int i = threadIdx.x; i < n4; i += 256) {
            float4 v = x4[i];
            s0 += v.x + v.y; q0 += v.x * v.x + v.y * v.y;
            s1 += v.z + v.w; q1 += v.z * v.z + v.w * v.w;
        }
    } else {
        int i = threadIdx.x;
        for (; i + 256 < HW; i += 512) {
            float a = xp[i], b = xp[i + 256];
            s0 += a; q0 += a * a;
            s1 += b; q1 += b * b;
        }
        if (i < HW) { float a = xp[i]; s0 += a; q0 += a * a; }
    }
    float s = s0 + s1, q = q0 + q1;
    for (int o = 16; o > 0; o >>= 1) {
        s += __shfl_down_sync(0xffffffffu, s, o);
        q += __shfl_down_sync(0xffffffffu, q, o);
    }
    __shared__ float sh[16];
    int w = threadIdx.x >> 5, l = threadIdx.x & 31;
    if (l == 0) { sh[w] = s; sh[w + 8] = q; }
    __syncthreads();
    if (threadIdx.x == 0) {
        for (int k = 1; k < 8; k++) { s += sh[k]; q += sh[k + 8]; }
        float m = s / HW;
        float var = q / HW - m * m;
        float rs = rsqrtf(fmaxf(var, 0.f) + 1e-5f);
        scale[p] = rs;
        shift[p] = -m * rs;
    }
}

// ---------------- segment mean ----------------
__global__ void k_segzero(float* sum, float* cnt) {
    int t = threadIdx.x;
    if (t < 96) sum[t] = 0.f;
    if (t < 32) cnt[t] = 0.f;
}
__global__ void k_segacc(const float* __restrict__ src, const int* __restrict__ inst,
                         float* __restrict__ gsum, float* __restrict__ gcnt) {
    __shared__ float ss[96];
    __shared__ float sc[32];
    int tid = threadIdx.x;
    if (tid < 96) ss[tid] = 0.f;
    if (tid < 32) sc[tid] = 0.f;
    __syncthreads();
    const int P = 62001, NP = 8 * 62001;
    for (int i = blockIdx.x * blockDim.x + tid; i < NP; i += gridDim.x * blockDim.x) {
        int n = i / P, p = i % P;
        int id = inst[i];
        const float* b = src + (size_t)n * 3 * P + p;
        atomicAdd(&ss[id * 3 + 0], b[0]);
        atomicAdd(&ss[id * 3 + 1], b[P]);
        atomicAdd(&ss[id * 3 + 2], b[2 * P]);
        atomicAdd(&sc[id], 1.f);
    }
    __syncthreads();
    if (tid < 96) atomicAdd(&gsum[tid], ss[tid]);
    if (tid < 32) atomicAdd(&gcnt[tid], sc[tid]);
}
__global__ void k_segbcast(const int* __restrict__ inst, const float* __restrict__ gsum,
                           const float* __restrict__ gcnt, float* __restrict__ out) {
    const int P = 62001, T = 8 * 3 * P;
    for (int i = blockIdx.x * blockDim.x + threadIdx.x; i < T; i += gridDim.x * blockDim.x) {
        int n = i / (3 * P), r = i % (3 * P);
        int c = r / P, p = r % P;
        int id = inst[n * P + p];
        out[i] = gsum[id * 3 + c] / fmaxf(gcnt[id], 1.f);
    }
}

// ---------------- launch ----------------
extern "C" void kernel_launch(void* const* d_in, const int* in_sizes, int n_in,
                              void* d_out, int out_size) {
    const float* x = (const float*)d_in[0];
    const int* inst = (const int*)d_in[1];
    const float* w[8];
    const float* b[8];
    for (int i = 0; i < 8; i++) {
        w[i] = (const float*)d_in[2 + 2 * i];
        b[i] = (const float*)d_in[3 + 2 * i];
    }
    float* out = (float*)d_out;

    float *A, *B, *SC, *SH;
    float *WT0, *WT1, *WT2, *WT3, *WT4, *WT5, *WT6, *WT7, *SS, *SN;
    cudaGetSymbolAddress((void**)&A, g_bufA);
    cudaGetSymbolAddress((void**)&B, g_bufB);
    cudaGetSymbolAddress((void**)&SC, g_scale);
    cudaGetSymbolAddress((void**)&SH, g_shift);
    cudaGetSymbolAddress((void**)&WT0, g_wt0);
    cudaGetSymbolAddress((void**)&WT1, g_wt1);
    cudaGetSymbolAddress((void**)&WT2, g_wt2);
    cudaGetSymbolAddress((void**)&WT3, g_wt3);
    cudaGetSymbolAddress((void**)&WT4, g_wt4);
    cudaGetSymbolAddress((void**)&WT5, g_wt5);
    cudaGetSymbolAddress((void**)&WT6, g_wt6);
    cudaGetSymbolAddress((void**)&WT7, g_wt7);
    cudaGetSymbolAddress((void**)&SS, g_segsum);
    cudaGetSymbolAddress((void**)&SN, g_segcnt);

    // dynamic smem sizes (bytes)
    const int SM_C1 = (2*8*9*64 + 2*8*1089 + 2*32) * 4;
    const int SM_C2 = (2*8*9*64 + 2*8*1089 + 2*64) * 4;
    const int SM_C3 = (2*8*9*64 + 2*8*1089 + 2*128) * 4;
    const int SM_T4 = (2*8*9*8 + 2*8*578 + 2*256) * 4;
    const int SM_T5 = (2*8*9*8 + 2*8*578 + 2*128) * 4;
    const int SM_T6 = (2*8*9*8 + 2*8*578 + 2*64) * 4;
    const int SM_L7 = (6272 + 2*4*1482 + 2*32) * 4;

    cudaFuncSetAttribute(k_conv3s2<32, 64, 8>,  cudaFuncAttributeMaxDynamicSharedMemorySize, SM_C1);
    cudaFuncSetAttribute(k_conv3s2<64, 128, 8>, cudaFuncAttributeMaxDynamicSharedMemorySize, SM_C2);
    cudaFuncSetAttribute(k_conv3s2<128, 256, 8>,cudaFuncAttributeMaxDynamicSharedMemorySize, SM_C3);
    cudaFuncSetAttribute(k_convT<256, 128, 8>,  cudaFuncAttributeMaxDynamicSharedMemorySize, SM_T4);
    cudaFuncSetAttribute(k_convT<128, 64, 8>,   cudaFuncAttributeMaxDynamicSharedMemorySize, SM_T5);
    cudaFuncSetAttribute(k_convT<64, 32, 8>,    cudaFuncAttributeMaxDynamicSharedMemorySize, SM_T6);
    cudaFuncSetAttribute(k_conv7_l7,            cudaFuncAttributeMaxDynamicSharedMemorySize, SM_L7);

    // weight prep
    k_prep<<<dim3(1152, 8), 256>>>(w[0], w[1], w[2], w[3], w[4], w[5], w[6], w[7],
                                   WT0, WT1, WT2, WT3, WT4, WT5, WT6, WT7);
    // layer 0
    k_conv7_l0<<<dim3(16, 16, 8), 256>>>(x, WT0, b[0], A);
    k_instat<<<8 * 32, 256>>>(A, SC, SH, 65536);
    // layers 1-3
    k_conv3s2<32, 64, 8><<<dim3(8, 8, 8), 256, SM_C1>>>(A, WT1, b[1], SC, SH, B, 256, 256, 128, 128);
    k_instat<<<8 * 64, 256>>>(B, SC, SH, 16384);
    k_conv3s2<64, 128, 8><<<dim3(4, 4, 16), 256, SM_C2>>>(B, WT2, b[2], SC, SH, A, 128, 128, 64, 64);
    k_instat<<<8 * 128, 256>>>(A, SC, SH, 4096);
    k_conv3s2<128, 256, 8><<<dim3(2, 2, 32), 256, SM_C3>>>(A, WT3, b[3], SC, SH, B, 64, 64, 32, 32);
    k_instat<<<8 * 256, 256>>>(B, SC, SH, 1024);
    // layers 4-6 (transposed conv)
    k_convT<256, 128, 8><<<dim3(1, 2, 128), 256, SM_T4>>>(B, WT4, b[4], SC, SH, A, 32, 32, 63, 63);
    k_instat<<<8 * 128, 256>>>(A, SC, SH, 3969);
    k_convT<128, 64, 8><<<dim3(2, 4, 64), 256, SM_T5>>>(A, WT5, b[5], SC, SH, B, 63, 63, 125, 125);
    k_instat<<<8 * 64, 256>>>(B, SC, SH, 15625);
    k_convT<64, 32, 8><<<dim3(4, 8, 32), 256, SM_T6>>>(B, WT6, b[6], SC, SH, A, 125, 125, 249, 249);
    k_instat<<<8 * 32, 256>>>(A, SC, SH, 62001);
    // layer 7
    k_conv7_l7<<<dim3(8, 8, 8), 256, SM_L7>>>(A, WT7, b[7], SC, SH, B);
    // segment mean
    k_segzero<<<1, 128>>>(SS, SN);
    k_segacc<<<1024, 256>>>(B, inst, SS, SN);
    k_segbcast<<<2048, 256>>>(inst, SS, SN, out);
}

// round 8
// speedup vs baseline: 2.2321x; 1.0633x over previous
#include <cuda_runtime.h>
#include <math.h>

// ---------------- static scratch ----------------
__device__ __align__(16) float g_bufA[16777216];
__device__ __align__(16) float g_bufB[8388608];
__device__ __align__(16) float g_wt0[3*49*32];
__device__ __align__(16) float g_wt1[32*9*64];
__device__ __align__(16) float g_wt2[64*9*128];
__device__ __align__(16) float g_wt3[128*9*256];
__device__ __align__(16) float g_wt4[256*9*128];
__device__ __align__(16) float g_wt5[128*9*64];
__device__ __align__(16) float g_wt6[64*9*32];
__device__ __align__(16) float g_wt7[32*49*4];
__device__ float g_segsum[96];
__device__ float g_segcnt[32];

typedef unsigned long long ull;

// ---------------- f32x2 packed helpers ----------------
__device__ __forceinline__ ull pack2(float v) {
    ull r;
    asm("mov.b64 %0, {%1, %1};" : "=l"(r) : "f"(v));
    return r;
}
__device__ __forceinline__ void fma2(ull& d, ull a, ull b) {
    asm("fma.rn.f32x2 %0, %1, %2, %0;" : "+l"(d) : "l"(a), "l"(b));
}
__device__ __forceinline__ float2 unpack2(ull v) {
    float2 f;
    asm("mov.b64 {%0, %1}, %2;" : "=f"(f.x), "=f"(f.y) : "l"(v));
    return f;
}

// ---------------- cp.async helpers ----------------
__device__ __forceinline__ unsigned s2u(const void* p) {
    return (unsigned)__cvta_generic_to_shared(p);
}
__device__ __forceinline__ void cp4(unsigned dst, const float* src, bool pred) {
    asm volatile("cp.async.ca.shared.global [%0], [%1], 4, %2;" ::
                 "r"(dst), "l"(src), "r"(pred ? 4u : 0u));
}
__device__ __forceinline__ void cp16(unsigned dst, const float* src) {
    asm volatile("cp.async.ca.shared.global [%0], [%1], 16;" ::
                 "r"(dst), "l"(src));
}
__device__ __forceinline__ void cp_commit() {
    asm volatile("cp.async.commit_group;" ::: "memory");
}
template <int N>
__device__ __forceinline__ void cp_wait() {
    asm volatile("cp.async.wait_group %0;" :: "n"(N) : "memory");
}

// ---------------- fused weight prep ----------------
__global__ void k_prep(const float* __restrict__ w0, const float* __restrict__ w1,
                       const float* __restrict__ w2, const float* __restrict__ w3,
                       const float* __restrict__ w4, const float* __restrict__ w5,
                       const float* __restrict__ w6, const float* __restrict__ w7,
                       float* o0, float* o1, float* o2, float* o3,
                       float* o4, float* o5, float* o6, float* o7) {
    int idx = blockIdx.x * 256 + threadIdx.x;
    switch (blockIdx.y) {
    case 0: if (idx < 32*3*49)   { int o=idx/147,  r=idx%147,  i=r/49, k=r%49; o0[(i*49+k)*32+o]=w0[idx]; } break;
    case 1: if (idx < 64*32*9)   { int o=idx/288,  r=idx%288,  i=r/9,  k=r%9;  o1[(i*9+k)*64+o]=w1[idx]; } break;
    case 2: if (idx < 128*64*9)  { int o=idx/576,  r=idx%576,  i=r/9,  k=r%9;  o2[(i*9+k)*128+o]=w2[idx]; } break;
    case 3: if (idx < 256*128*9) { int o=idx/1152, r=idx%1152, i=r/9,  k=r%9;  o3[(i*9+k)*256+o]=w3[idx]; } break;
    case 4: if (idx < 256*128*9) { int i=idx/1152, r=idx%1152, o=r/9,  k=r%9;  o4[(i*9+k)*128+o]=w4[idx]; } break;
    case 5: if (idx < 128*64*9)  { int i=idx/576,  r=idx%576,  o=r/9,  k=r%9;  o5[(i*9+k)*64+o]=w5[idx]; } break;
    case 6: if (idx < 64*32*9)   { int i=idx/288,  r=idx%288,  o=r/9,  k=r%9;  o6[(i*9+k)*32+o]=w6[idx]; } break;
    case 7: if (idx < 32*49*4)   { int p=idx>>2, o=idx&3; int i=p/49, k=p%49;
                                   o7[idx] = (o < 3) ? w7[(o*32+i)*49+k] : 0.f; } break;
    }
}

// ---------------- layer 0: reflect-pad 7x7 conv, 3->32, 2px x 16oc / thread ----
__global__ void __launch_bounds__(256)
k_conv7_l0(const float* __restrict__ x, const float* __restrict__ wt,
           const float* __restrict__ bias, float* __restrict__ out) {
    __shared__ __align__(16) float s_w[3 * 49 * 32];
    __shared__ float s_in[3 * 484];
    const int tid = threadIdx.x;
    const int og = tid >> 7;            // oc half: og*16
    const int rem = tid & 127;
    const int ty = rem >> 4;            // 0..7 -> rows ty, ty+8
    const int tx = rem & 15;
    const int n = blockIdx.z;
    const int oy0 = blockIdx.y * 16, ox0 = blockIdx.x * 16;

    for (int i = tid; i < 3 * 49 * 32; i += 256) s_w[i] = wt[i];
    const float* xp = x + (size_t)n * 3 * 65536;
    for (int i = tid; i < 3 * 484; i += 256) {
        int ic = i / 484, rr = (i % 484) / 22, cc = i % 22;
        int iy = oy0 + rr - 3, ix = ox0 + cc - 3;
        iy = iy < 0 ? -iy : (iy > 255 ? 510 - iy : iy);
        ix = ix < 0 ? -ix : (ix > 255 ? 510 - ix : ix);
        s_in[i] = xp[ic * 65536 + iy * 256 + ix];
    }
    __syncthreads();

    ull acc0[8], acc1[8];
#pragma unroll
    for (int j = 0; j < 8; j++) { acc0[j] = 0ull; acc1[j] = 0ull; }

    for (int ic = 0; ic < 3; ic++)
#pragma unroll 1
        for (int ky = 0; ky < 7; ky++)
#pragma unroll
            for (int kx = 0; kx < 7; kx++) {
                ull v0 = pack2(s_in[ic * 484 + (ty + ky) * 22 + tx + kx]);
                ull v1 = pack2(s_in[ic * 484 + (ty + 8 + ky) * 22 + tx + kx]);
                const ulonglong2* wp =
                    (const ulonglong2*)(s_w + ((ic * 7 + ky) * 7 + kx) * 32 + og * 16);
#pragma unroll
                for (int q = 0; q < 4; q++) {
                    ulonglong2 w2 = wp[q];
                    fma2(acc0[2 * q + 0], v0, w2.x);
                    fma2(acc0[2 * q + 1], v0, w2.y);
                    fma2(acc1[2 * q + 0], v1, w2.x);
                    fma2(acc1[2 * q + 1], v1, w2.y);
                }
            }
    int oy = oy0 + ty, ox = ox0 + tx;
    float* op = out + (size_t)n * 32 * 65536 + (size_t)(og * 16) * 65536 + oy * 256 + ox;
#pragma unroll
    for (int j = 0; j < 8; j++) {
        float2 a = unpack2(acc0[j]);
        float2 b = unpack2(acc1[j]);
        float bz0 = bias[og * 16 + 2 * j], bz1 = bias[og * 16 + 2 * j + 1];
        op[(size_t)(2 * j + 0) * 65536] = a.x + bz0;
        op[(size_t)(2 * j + 1) * 65536] = a.y + bz1;
        op[(size_t)(2 * j + 0) * 65536 + 8 * 256] = b.x + bz0;
        op[(size_t)(2 * j + 1) * 65536 + 8 * 256] = b.y + bz1;
    }
}

// ---------------- 3x3 stride-2 conv on pre-normalized input ----------------
template <int IC, int OC, int ICC>
__global__ void __launch_bounds__(256, 2)
k_conv3s2(const float* __restrict__ in, const float* __restrict__ wt,
          const float* __restrict__ bias, float* __restrict__ out,
          int Hin, int Win, int Hout, int Wout) {
    const int OCB = 64;
    extern __shared__ float smem[];
    float* s_w  = smem;                         // 2 * ICC*9*64
    float* s_in = s_w + 2 * ICC * 9 * OCB;      // 2 * ICC*1089

    const int tid = threadIdx.x;
    const int og = tid >> 7;            // oc half: og*32
    const int rem = tid & 127;
    const int ty = rem >> 4;            // rows ty, ty+8
    const int tx = rem & 15;
    const int z = blockIdx.z;
    const int n = z / (OC / OCB);
    const int oc0 = (z % (OC / OCB)) * OCB;
    const int oy0 = blockIdx.y * 16, ox0 = blockIdx.x * 16;
    const int iy0 = 2 * oy0 - 1, ix0 = 2 * ox0 - 1;

    const float* inp = in + (size_t)n * IC * Hin * Win;

    auto prefetch = [&](int st, int b) {
        int ic0 = st * ICC;
        float* bw = s_w + b * (ICC * 9 * OCB);
        float* bi = s_in + b * (ICC * 1089);
        for (int i = tid; i < ICC * 1089; i += 256) {
            int icl = i / 1089, r2 = i % 1089;
            int r = r2 / 33, c = r2 % 33;
            int iy = iy0 + r, ix = ix0 + c;
            bool ok = ((unsigned)iy < (unsigned)Hin) && ((unsigned)ix < (unsigned)Win);
            const float* src = inp + (size_t)(ic0 + icl) * Hin * Win + (ok ? iy * Win + ix : 0);
            cp4(s2u(bi + i), src, ok);
        }
        const float* wsrc = wt + (size_t)ic0 * 9 * OC + oc0;
        for (int i = tid; i < ICC * 9 * (OCB / 4); i += 256) {
            int p = i / (OCB / 4), c = i % (OCB / 4);
            cp16(s2u(bw + p * OCB + 4 * c), wsrc + (size_t)p * OC + 4 * c);
        }
    };

    ull acc0[16], acc1[16];
#pragma unroll
    for (int j = 0; j < 16; j++) { acc0[j] = 0ull; acc1[j] = 0ull; }

    prefetch(0, 0);
    cp_commit();
    const int NS = IC / ICC;
    for (int s = 0; s < NS; s++) {
        if (s + 1 < NS) { prefetch(s + 1, (s + 1) & 1); cp_commit(); cp_wait<1>(); }
        else cp_wait<0>();
        __syncthreads();
        const float* bi = s_in + (s & 1) * (ICC * 1089);
        const float* bw = s_w + (s & 1) * (ICC * 9 * OCB);
#pragma unroll 1
        for (int icl = 0; icl < ICC; icl++) {
            const float* sb0 = bi + icl * 1089 + (2 * ty) * 33 + 2 * tx;
            const float* sb1 = sb0 + 528;   // +16 rows
            const float* wb = bw + icl * 9 * OCB + og * 32;
#pragma unroll
            for (int ky = 0; ky < 3; ky++)
#pragma unroll
                for (int kx = 0; kx < 3; kx++) {
                    ull v0 = pack2(sb0[ky * 33 + kx]);
                    ull v1 = pack2(sb1[ky * 33 + kx]);
                    const ulonglong2* wp = (const ulonglong2*)(wb + (ky * 3 + kx) * OCB);
#pragma unroll
                    for (int q = 0; q < 8; q++) {
                        ulonglong2 w2 = wp[q];
                        fma2(acc0[2 * q + 0], v0, w2.x);
                        fma2(acc0[2 * q + 1], v0, w2.y);
                        fma2(acc1[2 * q + 0], v1, w2.x);
                        fma2(acc1[2 * q + 1], v1, w2.y);
                    }
                }
        }
        __syncthreads();
    }

    int oy = oy0 + ty, ox = ox0 + tx;
    int ocb = oc0 + og * 32;
    float* op = out + ((size_t)(n * OC + ocb) * Hout + oy) * Wout + ox;
    const size_t cs = (size_t)Hout * Wout;
#pragma unroll
    for (int j = 0; j < 16; j++) {
        float2 a = unpack2(acc0[j]);
        float2 b = unpack2(acc1[j]);
        float bz0 = bias[ocb + 2 * j], bz1 = bias[ocb + 2 * j + 1];
        op[(size_t)(2 * j + 0) * cs] = a.x + bz0;
        op[(size_t)(2 * j + 1) * cs] = a.y + bz1;
        op[(size_t)(2 * j + 0) * cs + 8 * Wout] = b.x + bz0;
        op[(size_t)(2 * j + 1) * cs + 8 * Wout] = b.y + bz1;
    }
}

// ---------------- convT on pre-normalized input ----------------
__device__ __forceinline__ void tap8(ull* A, ull* B, ull va, ull vb,
                                     const ulonglong2* wp) {
    ulonglong2 w0 = wp[0], w1 = wp[1];
    fma2(A[0], va, w0.x); fma2(A[1], va, w0.y);
    fma2(A[2], va, w1.x); fma2(A[3], va, w1.y);
    fma2(B[0], vb, w0.x); fma2(B[1], vb, w0.y);
    fma2(B[2], vb, w1.x); fma2(B[3], vb, w1.y);
}

template <int IC, int OC, int ICC>
__global__ void __launch_bounds__(256, 2)
k_convT(const float* __restrict__ in, const float* __restrict__ wt,
        const float* __restrict__ bias, float* __restrict__ out,
        int Hin, int Win, int Hout, int Wout) {
    const int OCB = 8;
    extern __shared__ float smem[];
    float* s_w  = smem;                        // 2 * ICC*9*8
    float* s_in = s_w + 2 * ICC * 9 * OCB;     // 2 * ICC*578 (17x34)

    const int tid = threadIdx.x;
    const int ty = tid >> 4;       // 0..15 parity row
    const int tx = tid & 15;       // parity cols tx and tx+16
    const int z = blockIdx.z;
    const int n = z / (OC / OCB);
    const int oc0 = (z % (OC / OCB)) * OCB;
    const int oy0 = blockIdx.y * 32, ox0 = blockIdx.x * 64;
    const int iy0 = oy0 >> 1, ix0 = ox0 >> 1;

    const float* inp = in + (size_t)n * IC * Hin * Win;

    auto prefetch = [&](int st, int b) {
        int ic0 = st * ICC;
        float* bw = s_w + b * (ICC * 9 * OCB);
        float* bi = s_in + b * (ICC * 578);
        for (int i = tid; i < ICC * 561; i += 256) {   // 17*33
            int icl = i / 561, r2 = i % 561;
            int r = r2 / 33, c = r2 % 33;
            int iy = iy0 + r, ix = ix0 + c;
            bool ok = (iy < Hin) && (ix < Win);
            const float* src = inp + (size_t)(ic0 + icl) * Hin * Win + (ok ? iy * Win + ix : 0);
            cp4(s2u(bi + icl * 578 + r * 34 + c), src, ok);
        }
        const float* wsrc = wt + (size_t)ic0 * 9 * OC + oc0;
        for (int i = tid; i < ICC * 9 * (OCB / 4); i += 256) {
            int p = i / (OCB / 4), c = i % (OCB / 4);
            cp16(s2u(bw + p * OCB + 4 * c), wsrc + (size_t)p * OC + 4 * c);
        }
    };

    ull acc[2][4][4];
#pragma unroll
    for (int b2 = 0; b2 < 2; b2++)
#pragma unroll
        for (int c = 0; c < 4; c++)
#pragma unroll
            for (int j = 0; j < 4; j++) acc[b2][c][j] = 0ull;

    prefetch(0, 0);
    cp_commit();
    const int NS = IC / ICC;
    for (int s = 0; s < NS; s++) {
        if (s + 1 < NS) { prefetch(s + 1, (s + 1) & 1); cp_commit(); cp_wait<1>(); }
        else cp_wait<0>();
        __syncthreads();
        const float* bi = s_in + (s & 1) * (ICC * 578);
        const float* bw = s_w + (s & 1) * (ICC * 9 * OCB);
#pragma unroll 2
        for (int icl = 0; icl < ICC; icl++) {
            const float* sp = bi + icl * 578 + ty * 34 + tx;
            ull a00 = pack2(sp[0]);
            ull a01 = pack2(sp[1]);
            ull a10 = pack2(sp[34]);
            ull a11 = pack2(sp[35]);
            ull b00 = pack2(sp[16]);
            ull b01 = pack2(sp[17]);
            ull b10 = pack2(sp[50]);
            ull b11 = pack2(sp[51]);
            const ulonglong2* wp = (const ulonglong2*)(bw + icl * 9 * OCB);
            tap8(acc[0][3], acc[1][3], a11, b11, wp + 0);   // tap0
            tap8(acc[0][2], acc[1][2], a10, b10, wp + 2);   // tap1
            tap8(acc[0][3], acc[1][3], a10, b10, wp + 4);   // tap2
            tap8(acc[0][1], acc[1][1], a01, b01, wp + 6);   // tap3
            tap8(acc[0][0], acc[1][0], a00, b00, wp + 8);   // tap4
            tap8(acc[0][1], acc[1][1], a00, b00, wp + 10);  // tap5
            tap8(acc[0][3], acc[1][3], a01, b01, wp + 12);  // tap6
            tap8(acc[0][2], acc[1][2], a00, b00, wp + 14);  // tap7
            tap8(acc[0][3], acc[1][3], a00, b00, wp + 16);  // tap8
        }
        __syncthreads();
    }

    const size_t cs = (size_t)Hout * Wout;
#pragma unroll
    for (int b2 = 0; b2 < 2; b2++) {
        int ye = oy0 + 2 * ty;
        int xe = ox0 + 2 * (tx + b2 * 16);
        bool y0v = ye < Hout, y1v = (ye + 1) < Hout;
        bool x0v = xe < Wout, x1v = (xe + 1) < Wout;
#pragma unroll
        for (int j = 0; j < 4; j++) {
            float bz0 = bias[oc0 + 2 * j], bz1 = bias[oc0 + 2 * j + 1];
            float* op0 = out + (size_t)(n * OC + oc0 + 2 * j) * cs;
            float* op1 = op0 + cs;
            float2 a;
            if (y0v && x0v) { a = unpack2(acc[b2][0][j]); op0[ye * Wout + xe] = a.x + bz0; op1[ye * Wout + xe] = a.y + bz1; }
            if (y0v && x1v) { a = unpack2(acc[b2][1][j]); op0[ye * Wout + xe + 1] = a.x + bz0; op1[ye * Wout + xe + 1] = a.y + bz1; }
            if (y1v && x0v) { a = unpack2(acc[b2][2][j]); op0[(ye + 1) * Wout + xe] = a.x + bz0; op1[(ye + 1) * Wout + xe] = a.y + bz1; }
            if (y1v && x1v) { a = unpack2(acc[b2][3][j]); op0[(ye + 1) * Wout + xe + 1] = a.x + bz0; op1[(ye + 1) * Wout + xe + 1] = a.y + bz1; }
        }
    }
}

// ---------------- layer 7: 7x7 conv 32->3 + tanh on pre-normalized input -------
__global__ void __launch_bounds__(256, 2)
k_conv7_l7(const float* __restrict__ act, const float* __restrict__ wt,
           const float* __restrict__ bias, float* __restrict__ out) {
    extern __shared__ float smem[];
    float* s_w  = smem;                 // 6272
    float* s_in = s_w + 6272;           // 2 * 4*1482

    const int H = 249;
    const int tid = threadIdx.x;
    const int tx = tid & 15, ty = tid >> 4;
    const int n = blockIdx.z;
    const int oy0 = blockIdx.y * 32, ox0 = blockIdx.x * 32;

    for (int i = tid; i < 6272; i += 256) s_w[i] = wt[i];

    const float* ap = act + (size_t)n * 32 * 62001;
    auto prefetch = [&](int st, int b) {
        float* bi = s_in + b * (4 * 1482);
        int ic0 = st * 4;
        for (int i = tid; i < 4 * 1444; i += 256) {
            int icl = i / 1444, r2 = i % 1444;
            int r = r2 / 38, c = r2 % 38;
            int iy = oy0 + r - 3, ix = ox0 + c - 3;
            iy = iy < 0 ? -iy : (iy > 248 ? 496 - iy : iy);
            ix = ix < 0 ? -ix : (ix > 248 ? 496 - ix : ix);
            cp4(s2u(bi + icl * 1482 + r * 39 + c),
                ap + (size_t)(ic0 + icl) * 62001 + iy * 249 + ix, true);
        }
    };

    ull acc[4][2];
#pragma unroll
    for (int p = 0; p < 4; p++) { acc[p][0] = 0ull; acc[p][1] = 0ull; }

    prefetch(0, 0);
    cp_commit();
    for (int s = 0; s < 8; s++) {
        if (s < 7) { prefetch(s + 1, (s + 1) & 1); cp_commit(); cp_wait<1>(); }
        else cp_wait<0>();
        __syncthreads();
        const float* bi = s_in + (s & 1) * (4 * 1482);
#pragma unroll 1
        for (int icl = 0; icl < 4; icl++) {
            const float* wic = s_w + (s * 4 + icl) * 196;
            const float* si = bi + icl * 1482;
#pragma unroll 1
            for (int ky = 0; ky < 7; ky++) {
                const float* sp0 = si + (2 * ty + ky) * 39 + 2 * tx;
                ull r0[9], r1[9];
#pragma unroll
                for (int k = 0; k < 9; k++) {
                    r0[k] = pack2(sp0[k]);
                    r1[k] = pack2(sp0[39 + k]);
                }
                const ulonglong2* wp = (const ulonglong2*)(wic + ky * 28);
#pragma unroll
                for (int kx = 0; kx < 7; kx++) {
                    ulonglong2 w2 = wp[kx];
                    fma2(acc[0][0], r0[kx], w2.x);     fma2(acc[0][1], r0[kx], w2.y);
                    fma2(acc[1][0], r0[kx + 1], w2.x); fma2(acc[1][1], r0[kx + 1], w2.y);
                    fma2(acc[2][0], r1[kx], w2.x);     fma2(acc[2][1], r1[kx], w2.y);
                    fma2(acc[3][0], r1[kx + 1], w2.x); fma2(acc[3][1], r1[kx + 1], w2.y);
                }
            }
        }
        __syncthreads();
    }

    float b0 = bias[0], b1 = bias[1], b2 = bias[2];
#pragma unroll
    for (int dy = 0; dy < 2; dy++)
#pragma unroll
        for (int dx = 0; dx < 2; dx++) {
            int oy = oy0 + 2 * ty + dy, ox = ox0 + 2 * tx + dx;
            if (oy < H && ox < H) {
                float2 a0 = unpack2(acc[dy * 2 + dx][0]);
                float2 a1 = unpack2(acc[dy * 2 + dx][1]);
                size_t base = (size_t)n * 3 * 62001 + oy * 249 + ox;
                out[base] = tanhf(a0.x + b0);
                out[base + 62001] = tanhf(a0.y + b1);
                out[base + 2 * 62001] = tanhf(a1.x + b2);
            }
        }
}

// ---------------- instance-norm stats + in-place normalize + ReLU ----------------
__global__ void k_instat(float* __restrict__ x, int HW) {
    int p = blockIdx.x;
    float* xp = x + (size_t)p * HW;
    float s0 = 0, s1 = 0, q0 = 0, q1 = 0;
    const bool vec = ((HW & 3) == 0);
    if (vec) {
        const float4* x4 = (const float4*)xp;
        int n4 = HW >> 2;
        for (int i = threadIdx.x; i < n4; i += 256) {
            float4 v = x4[i];
            s0 += v.x + v.y; q0 += v.x * v.x + v.y * v.y;
            s1 += v.z + v.w; q1 += v.z * v.z + v.w * v.w;
        }
    } else {
        int i = threadIdx.x;
        for (; i + 256 < HW; i += 512) {
            float a = xp[i], b = xp[i + 256];
            s0 += a; q0 += a * a;
            s1 += b; q1 += b * b;
        }
        if (i < HW) { float a = xp[i]; s0 += a; q0 += a * a; }
    }
    float s = s0 + s1, q = q0 + q1;
    for (int o = 16; o > 0; o >>= 1) {
        s += __shfl_down_sync(0xffffffffu, s, o);
        q += __shfl_down_sync(0xffffffffu, q, o);
    }
    __shared__ float sh[16];
    __shared__ float s_stat[2];
    int w = threadIdx.x >> 5, l = threadIdx.x & 31;
    if (l == 0) { sh[w] = s; sh[w + 8] = q; }
    __syncthreads();
    if (threadIdx.x == 0) {
        for (int k = 1; k < 8; k++) { s += sh[k]; q += sh[k + 8]; }
        float m = s / HW;
        float var = q / HW - m * m;
        float rs = rsqrtf(fmaxf(var, 0.f) + 1e-5f);
        s_stat[0] = rs;
        s_stat[1] = -m * rs;
    }
    __syncthreads();
    float rs = s_stat[0], sf = s_stat[1];
    // in-place normalize + relu
    if (vec) {
        float4* x4 = (float4*)xp;
        int n4 = HW >> 2;
        for (int i = threadIdx.x; i < n4; i += 256) {
            float4 v = x4[i];
            v.x = fmaxf(fmaf(v.x, rs, sf), 0.f);
            v.y = fmaxf(fmaf(v.y, rs, sf), 0.f);
            v.z = fmaxf(fmaf(v.z, rs, sf), 0.f);
            v.w = fmaxf(fmaf(v.w, rs, sf), 0.f);
            x4[i] = v;
        }
    } else {
        for (int i = threadIdx.x; i < HW; i += 256)
            xp[i] = fmaxf(fmaf(xp[i], rs, sf), 0.f);
    }
}

// ---------------- segment mean ----------------
__global__ void k_segzero(float* sum, float* cnt) {
    int t = threadIdx.x;
    if (t < 96) sum[t] = 0.f;
    if (t < 32) cnt[t] = 0.f;
}
__global__ void k_segacc(const float* __restrict__ src, const int* __restrict__ inst,
                         float* __restrict__ gsum, float* __restrict__ gcnt) {
    __shared__ float ss[96];
    __shared__ float sc[32];
    int tid = threadIdx.x;
    if (tid < 96) ss[tid] = 0.f;
    if (tid < 32) sc[tid] = 0.f;
    __syncthreads();
    const int P = 62001, NP = 8 * 62001;
    for (int i = blockIdx.x * blockDim.x + tid; i < NP; i += gridDim.x * blockDim.x) {
        int n = i / P, p = i % P;
        int id = inst[i];
        const float* b = src + (size_t)n * 3 * P + p;
        atomicAdd(&ss[id * 3 + 0], b[0]);
        atomicAdd(&ss[id * 3 + 1], b[P]);
        atomicAdd(&ss[id * 3 + 2], b[2 * P]);
        atomicAdd(&sc[id], 1.f);
    }
    __syncthreads();
    if (tid < 96) atomicAdd(&gsum[tid], ss[tid]);
    if (tid < 32) atomicAdd(&gcnt[tid], sc[tid]);
}
__global__ void k_segbcast(const int* __restrict__ inst, const float* __restrict__ gsum,
                           const float* __restrict__ gcnt, float* __restrict__ out) {
    const int P = 62001, T = 8 * 3 * P;
    for (int i = blockIdx.x * blockDim.x + threadIdx.x; i < T; i += gridDim.x * blockDim.x) {
        int n = i / (3 * P), r = i % (3 * P);
        int c = r / P, p = r % P;
        int id = inst[n * P + p];
        out[i] = gsum[id * 3 + c] / fmaxf(gcnt[id], 1.f);
    }
}

// ---------------- launch ----------------
extern "C" void kernel_launch(void* const* d_in, const int* in_sizes, int n_in,
                              void* d_out, int out_size) {
    const float* x = (const float*)d_in[0];
    const int* inst = (const int*)d_in[1];
    const float* w[8];
    const float* b[8];
    for (int i = 0; i < 8; i++) {
        w[i] = (const float*)d_in[2 + 2 * i];
        b[i] = (const float*)d_in[3 + 2 * i];
    }
    float* out = (float*)d_out;

    float *A, *B;
    float *WT0, *WT1, *WT2, *WT3, *WT4, *WT5, *WT6, *WT7, *SS, *SN;
    cudaGetSymbolAddress((void**)&A, g_bufA);
    cudaGetSymbolAddress((void**)&B, g_bufB);
    cudaGetSymbolAddress((void**)&WT0, g_wt0);
    cudaGetSymbolAddress((void**)&WT1, g_wt1);
    cudaGetSymbolAddress((void**)&WT2, g_wt2);
    cudaGetSymbolAddress((void**)&WT3, g_wt3);
    cudaGetSymbolAddress((void**)&WT4, g_wt4);
    cudaGetSymbolAddress((void**)&WT5, g_wt5);
    cudaGetSymbolAddress((void**)&WT6, g_wt6);
    cudaGetSymbolAddress((void**)&WT7, g_wt7);
    cudaGetSymbolAddress((void**)&SS, g_segsum);
    cudaGetSymbolAddress((void**)&SN, g_segcnt);

    // dynamic smem sizes (bytes)
    const int SM_C = (2*8*9*64 + 2*8*1089) * 4;
    const int SM_T = (2*8*9*8 + 2*8*578) * 4;
    const int SM_L7 = (6272 + 2*4*1482) * 4;

    cudaFuncSetAttribute(k_conv3s2<32, 64, 8>,  cudaFuncAttributeMaxDynamicSharedMemorySize, SM_C);
    cudaFuncSetAttribute(k_conv3s2<64, 128, 8>, cudaFuncAttributeMaxDynamicSharedMemorySize, SM_C);
    cudaFuncSetAttribute(k_conv3s2<128, 256, 8>,cudaFuncAttributeMaxDynamicSharedMemorySize, SM_C);
    cudaFuncSetAttribute(k_convT<256, 128, 8>,  cudaFuncAttributeMaxDynamicSharedMemorySize, SM_T);
    cudaFuncSetAttribute(k_convT<128, 64, 8>,   cudaFuncAttributeMaxDynamicSharedMemorySize, SM_T);
    cudaFuncSetAttribute(k_convT<64, 32, 8>,    cudaFuncAttributeMaxDynamicSharedMemorySize, SM_T);
    cudaFuncSetAttribute(k_conv7_l7,            cudaFuncAttributeMaxDynamicSharedMemorySize, SM_L7);

    // weight prep
    k_prep<<<dim3(1152, 8), 256>>>(w[0], w[1], w[2], w[3], w[4], w[5], w[6], w[7],
                                   WT0, WT1, WT2, WT3, WT4, WT5, WT6, WT7);
    // layer 0
    k_conv7_l0<<<dim3(16, 16, 8), 256>>>(x, WT0, b[0], A);
    k_instat<<<8 * 32, 256>>>(A, 65536);
    // layers 1-3
    k_conv3s2<32, 64, 8><<<dim3(8, 8, 8), 256, SM_C>>>(A, WT1, b[1], B, 256, 256, 128, 128);
    k_instat<<<8 * 64, 256>>>(B, 16384);
    k_conv3s2<64, 128, 8><<<dim3(4, 4, 16), 256, SM_C>>>(B, WT2, b[2], A, 128, 128, 64, 64);
    k_instat<<<8 * 128, 256>>>(A, 4096);
    k_conv3s2<128, 256, 8><<<dim3(2, 2, 32), 256, SM_C>>>(A, WT3, b[3], B, 64, 64, 32, 32);
    k_instat<<<8 * 256, 256>>>(B, 1024);
    // layers 4-6 (transposed conv)
    k_convT<256, 128, 8><<<dim3(1, 2, 128), 256, SM_T>>>(B, WT4, b[4], A, 32, 32, 63, 63);
    k_instat<<<8 * 128, 256>>>(A, 3969);
    k_convT<128, 64, 8><<<dim3(2, 4, 64), 256, SM_T>>>(A, WT5, b[5], B, 63, 63, 125, 125);
    k_instat<<<8 * 64, 256>>>(B, 15625);
    k_convT<64, 32, 8><<<dim3(4, 8, 32), 256, SM_T>>>(B, WT6, b[6], A, 125, 125, 249, 249);
    k_instat<<<8 * 32, 256>>>(A, 62001);
    // layer 7
    k_conv7_l7<<<dim3(8, 8, 8), 256, SM_L7>>>(A, WT7, b[7], B);
    // segment mean
    k_segzero<<<1, 128>>>(SS, SN);
    k_segacc<<<1024, 256>>>(B, inst, SS, SN);
    k_segbcast<<<2048, 256>>>(inst, SS, SN, out);
}

// round 10
// speedup vs baseline: 2.3217x; 1.0401x over previous
#include <cuda_runtime.h>
#include <math.h>

// ---------------- static scratch ----------------
__device__ __align__(16) float g_bufA[16777216];
__device__ __align__(16) float g_bufB[8388608];
__device__ __align__(16) float g_wt0[3*49*32];
__device__ __align__(16) float g_wt1[32*9*64];
__device__ __align__(16) float g_wt2[64*9*128];
__device__ __align__(16) float g_wt3[128*9*256];
__device__ __align__(16) float g_wt4[256*9*128];
__device__ __align__(16) float g_wt5[128*9*64];
__device__ __align__(16) float g_wt6[64*9*32];
__device__ __align__(16) float g_wt7[32*49*4];
__device__ float g_segsum[96];
__device__ float g_segcnt[32];

typedef unsigned long long ull;

// ---------------- f32x2 packed helpers ----------------
__device__ __forceinline__ ull pack2(float v) {
    ull r;
    asm("mov.b64 %0, {%1, %1};" : "=l"(r) : "f"(v));
    return r;
}
__device__ __forceinline__ void fma2(ull& d, ull a, ull b) {
    asm("fma.rn.f32x2 %0, %1, %2, %0;" : "+l"(d) : "l"(a), "l"(b));
}
__device__ __forceinline__ float2 unpack2(ull v) {
    float2 f;
    asm("mov.b64 {%0, %1}, %2;" : "=f"(f.x), "=f"(f.y) : "l"(v));
    return f;
}

// ---------------- cp.async helpers ----------------
__device__ __forceinline__ unsigned s2u(const void* p) {
    return (unsigned)__cvta_generic_to_shared(p);
}
__device__ __forceinline__ void cp4(unsigned dst, const float* src, bool pred) {
    asm volatile("cp.async.ca.shared.global [%0], [%1], 4, %2;" ::
                 "r"(dst), "l"(src), "r"(pred ? 4u : 0u));
}
__device__ __forceinline__ void cp16(unsigned dst, const float* src) {
    asm volatile("cp.async.ca.shared.global [%0], [%1], 16;" ::
                 "r"(dst), "l"(src));
}
// 16B copy with variable valid source bytes (rest zero-filled)
__device__ __forceinline__ void cp16z(unsigned dst, const float* src, unsigned sz) {
    asm volatile("cp.async.ca.shared.global [%0], [%1], 16, %2;" ::
                 "r"(dst), "l"(src), "r"(sz));
}
__device__ __forceinline__ void cp_commit() {
    asm volatile("cp.async.commit_group;" ::: "memory");
}
template <int N>
__device__ __forceinline__ void cp_wait() {
    asm volatile("cp.async.wait_group %0;" :: "n"(N) : "memory");
}

// ---------------- fused weight prep ----------------
__global__ void k_prep(const float* __restrict__ w0, const float* __restrict__ w1,
                       const float* __restrict__ w2, const float* __restrict__ w3,
                       const float* __restrict__ w4, const float* __restrict__ w5,
                       const float* __restrict__ w6, const float* __restrict__ w7,
                       float* o0, float* o1, float* o2, float* o3,
                       float* o4, float* o5, float* o6, float* o7) {
    int idx = blockIdx.x * 256 + threadIdx.x;
    switch (blockIdx.y) {
    case 0: if (idx < 32*3*49)   { int o=idx/147,  r=idx%147,  i=r/49, k=r%49; o0[(i*49+k)*32+o]=w0[idx]; } break;
    case 1: if (idx < 64*32*9)   { int o=idx/288,  r=idx%288,  i=r/9,  k=r%9;  o1[(i*9+k)*64+o]=w1[idx]; } break;
    case 2: if (idx < 128*64*9)  { int o=idx/576,  r=idx%576,  i=r/9,  k=r%9;  o2[(i*9+k)*128+o]=w2[idx]; } break;
    case 3: if (idx < 256*128*9) { int o=idx/1152, r=idx%1152, i=r/9,  k=r%9;  o3[(i*9+k)*256+o]=w3[idx]; } break;
    case 4: if (idx < 256*128*9) { int i=idx/1152, r=idx%1152, o=r/9,  k=r%9;  o4[(i*9+k)*128+o]=w4[idx]; } break;
    case 5: if (idx < 128*64*9)  { int i=idx/576,  r=idx%576,  o=r/9,  k=r%9;  o5[(i*9+k)*64+o]=w5[idx]; } break;
    case 6: if (idx < 64*32*9)   { int i=idx/288,  r=idx%288,  o=r/9,  k=r%9;  o6[(i*9+k)*32+o]=w6[idx]; } break;
    case 7: if (idx < 32*49*4)   { int p=idx>>2, o=idx&3; int i=p/49, k=p%49;
                                   o7[idx] = (o < 3) ? w7[(o*32+i)*49+k] : 0.f; } break;
    }
}

// ---------------- layer 0: reflect-pad 7x7 conv, 3->32, 2px x 16oc / thread ----
__global__ void __launch_bounds__(256)
k_conv7_l0(const float* __restrict__ x, const float* __restrict__ wt,
           const float* __restrict__ bias, float* __restrict__ out) {
    __shared__ __align__(16) float s_w[3 * 49 * 32];
    __shared__ float s_in[3 * 484];
    const int tid = threadIdx.x;
    const int og = tid >> 7;            // oc half: og*16
    const int rem = tid & 127;
    const int ty = rem >> 4;            // 0..7 -> rows ty, ty+8
    const int tx = rem & 15;
    const int n = blockIdx.z;
    const int oy0 = blockIdx.y * 16, ox0 = blockIdx.x * 16;

    for (int i = tid; i < 3 * 49 * 32; i += 256) s_w[i] = wt[i];
    const float* xp = x + (size_t)n * 3 * 65536;
    for (int i = tid; i < 3 * 484; i += 256) {
        int ic = i / 484, rr = (i % 484) / 22, cc = i % 22;
        int iy = oy0 + rr - 3, ix = ox0 + cc - 3;
        iy = iy < 0 ? -iy : (iy > 255 ? 510 - iy : iy);
        ix = ix < 0 ? -ix : (ix > 255 ? 510 - ix : ix);
        s_in[i] = xp[ic * 65536 + iy * 256 + ix];
    }
    __syncthreads();

    ull acc0[8], acc1[8];
#pragma unroll
    for (int j = 0; j < 8; j++) { acc0[j] = 0ull; acc1[j] = 0ull; }

    for (int ic = 0; ic < 3; ic++)
#pragma unroll 1
        for (int ky = 0; ky < 7; ky++)
#pragma unroll
            for (int kx = 0; kx < 7; kx++) {
                ull v0 = pack2(s_in[ic * 484 + (ty + ky) * 22 + tx + kx]);
                ull v1 = pack2(s_in[ic * 484 + (ty + 8 + ky) * 22 + tx + kx]);
                const ulonglong2* wp =
                    (const ulonglong2*)(s_w + ((ic * 7 + ky) * 7 + kx) * 32 + og * 16);
#pragma unroll
                for (int q = 0; q < 4; q++) {
                    ulonglong2 w2 = wp[q];
                    fma2(acc0[2 * q + 0], v0, w2.x);
                    fma2(acc0[2 * q + 1], v0, w2.y);
                    fma2(acc1[2 * q + 0], v1, w2.x);
                    fma2(acc1[2 * q + 1], v1, w2.y);
                }
            }
    int oy = oy0 + ty, ox = ox0 + tx;
    float* op = out + (size_t)n * 32 * 65536 + (size_t)(og * 16) * 65536 + oy * 256 + ox;
#pragma unroll
    for (int j = 0; j < 8; j++) {
        float2 a = unpack2(acc0[j]);
        float2 b = unpack2(acc1[j]);
        float bz0 = bias[og * 16 + 2 * j], bz1 = bias[og * 16 + 2 * j + 1];
        op[(size_t)(2 * j + 0) * 65536] = a.x + bz0;
        op[(size_t)(2 * j + 1) * 65536] = a.y + bz1;
        op[(size_t)(2 * j + 0) * 65536 + 8 * 256] = b.x + bz0;
        op[(size_t)(2 * j + 1) * 65536 + 8 * 256] = b.y + bz1;
    }
}

// ---------------- 3x3 stride-2 conv, cp.async.16 staging, pitch 36 ----------------
// smem tile row covers ix = 2*ox0-4 .. 2*ox0+31 (36 floats, 16B-aligned source).
// Needed ix for tap kx at pixel tx: 2*ox0-1 + 2*tx + kx  ->  col = 3 + 2*tx + kx.
template <int IC, int OC, int ICC>
__global__ void __launch_bounds__(256, 2)
k_conv3s2(const float* __restrict__ in, const float* __restrict__ wt,
          const float* __restrict__ bias, float* __restrict__ out,
          int Hin, int Win, int Hout, int Wout) {
    const int OCB = 64;
    const int PIN = 33 * 36;                    // floats per ic plane tile
    extern __shared__ float smem[];
    float* s_w  = smem;                         // 2 * ICC*9*64
    float* s_in = s_w + 2 * ICC * 9 * OCB;      // 2 * ICC*PIN

    const int tid = threadIdx.x;
    const int og = tid >> 7;            // oc half: og*32
    const int rem = tid & 127;
    const int ty = rem >> 4;            // rows ty, ty+8
    const int tx = rem & 15;
    const int z = blockIdx.z;
    const int n = z / (OC / OCB);
    const int oc0 = (z % (OC / OCB)) * OCB;
    const int oy0 = blockIdx.y * 16, ox0 = blockIdx.x * 16;
    const int iy0 = 2 * oy0 - 1;
    const int ixa = 2 * ox0 - 4;        // 16B-aligned source base (multiple of 4)

    const float* inp = in + (size_t)n * IC * Hin * Win;

    auto prefetch = [&](int st, int b) {
        int ic0 = st * ICC;
        float* bw = s_w + b * (ICC * 9 * OCB);
        float* bi = s_in + b * (ICC * PIN);
        // input: ICC * 33 rows * 9 16B-chunks
        for (int i = tid; i < ICC * 33 * 9; i += 256) {
            int icl = i / 297;
            int r2 = i % 297;
            int r = r2 / 9, c9 = r2 % 9;
            int iy = iy0 + r;
            int sx = ixa + 4 * c9;
            bool ok = ((unsigned)iy < (unsigned)Hin) && (sx >= 0);
            unsigned sz = ok ? 16u : 0u;
            const float* src = inp + (size_t)(ic0 + icl) * Hin * Win +
                               (ok ? iy * Win + sx : 0);
            cp16z(s2u(bi + icl * PIN + r * 36 + 4 * c9), src, sz);
        }
        const float* wsrc = wt + (size_t)ic0 * 9 * OC + oc0;
        for (int i = tid; i < ICC * 9 * (OCB / 4); i += 256) {
            int p = i / (OCB / 4), c = i % (OCB / 4);
            cp16(s2u(bw + p * OCB + 4 * c), wsrc + (size_t)p * OC + 4 * c);
        }
    };

    ull acc0[16], acc1[16];
#pragma unroll
    for (int j = 0; j < 16; j++) { acc0[j] = 0ull; acc1[j] = 0ull; }

    prefetch(0, 0);
    cp_commit();
    const int NS = IC / ICC;
    for (int s = 0; s < NS; s++) {
        if (s + 1 < NS) { prefetch(s + 1, (s + 1) & 1); cp_commit(); cp_wait<1>(); }
        else cp_wait<0>();
        __syncthreads();
        const float* bi = s_in + (s & 1) * (ICC * PIN);
        const float* bw = s_w + (s & 1) * (ICC * 9 * OCB);
#pragma unroll 1
        for (int icl = 0; icl < ICC; icl++) {
            const float* sb0 = bi + icl * PIN + (2 * ty) * 36 + 2 * tx + 3;
            const float* sb1 = sb0 + 16 * 36;   // +16 rows
            const float* wb = bw + icl * 9 * OCB + og * 32;
#pragma unroll
            for (int ky = 0; ky < 3; ky++)
#pragma unroll
                for (int kx = 0; kx < 3; kx++) {
                    ull v0 = pack2(sb0[ky * 36 + kx]);
                    ull v1 = pack2(sb1[ky * 36 + kx]);
                    const ulonglong2* wp = (const ulonglong2*)(wb + (ky * 3 + kx) * OCB);
#pragma unroll
                    for (int q = 0; q < 8; q++) {
                        ulonglong2 w2 = wp[q];
                        fma2(acc0[2 * q + 0], v0, w2.x);
                        fma2(acc0[2 * q + 1], v0, w2.y);
                        fma2(acc1[2 * q + 0], v1, w2.x);
                        fma2(acc1[2 * q + 1], v1, w2.y);
                    }
                }
        }
        __syncthreads();
    }

    int oy = oy0 + ty, ox = ox0 + tx;
    int ocb = oc0 + og * 32;
    float* op = out + ((size_t)(n * OC + ocb) * Hout + oy) * Wout + ox;
    const size_t cs = (size_t)Hout * Wout;
#pragma unroll
    for (int j = 0; j < 16; j++) {
        float2 a = unpack2(acc0[j]);
        float2 b = unpack2(acc1[j]);
        float bz0 = bias[ocb + 2 * j], bz1 = bias[ocb + 2 * j + 1];
        op[(size_t)(2 * j + 0) * cs] = a.x + bz0;
        op[(size_t)(2 * j + 1) * cs] = a.y + bz1;
        op[(size_t)(2 * j + 0) * cs + 8 * Wout] = b.x + bz0;
        op[(size_t)(2 * j + 1) * cs + 8 * Wout] = b.y + bz1;
    }
}

// ---------------- convT on pre-normalized input ----------------
__device__ __forceinline__ void tap8(ull* A, ull* B, ull va, ull vb,
                                     const ulonglong2* wp) {
    ulonglong2 w0 = wp[0], w1 = wp[1];
    fma2(A[0], va, w0.x); fma2(A[1], va, w0.y);
    fma2(A[2], va, w1.x); fma2(A[3], va, w1.y);
    fma2(B[0], vb, w0.x); fma2(B[1], vb, w0.y);
    fma2(B[2], vb, w1.x); fma2(B[3], vb, w1.y);
}

template <int IC, int OC, int ICC>
__global__ void __launch_bounds__(256, 2)
k_convT(const float* __restrict__ in, const float* __restrict__ wt,
        const float* __restrict__ bias, float* __restrict__ out,
        int Hin, int Win, int Hout, int Wout) {
    const int OCB = 8;
    extern __shared__ float smem[];
    float* s_w  = smem;                        // 2 * ICC*9*8
    float* s_in = s_w + 2 * ICC * 9 * OCB;     // 2 * ICC*578 (17x34)

    const int tid = threadIdx.x;
    const int ty = tid >> 4;       // 0..15 parity row
    const int tx = tid & 15;       // parity cols tx and tx+16
    const int z = blockIdx.z;
    const int n = z / (OC / OCB);
    const int oc0 = (z % (OC / OCB)) * OCB;
    const int oy0 = blockIdx.y * 32, ox0 = blockIdx.x * 64;
    const int iy0 = oy0 >> 1, ix0 = ox0 >> 1;

    const float* inp = in + (size_t)n * IC * Hin * Win;

    auto prefetch = [&](int st, int b) {
        int ic0 = st * ICC;
        float* bw = s_w + b * (ICC * 9 * OCB);
        float* bi = s_in + b * (ICC * 578);
        for (int i = tid; i < ICC * 561; i += 256) {   // 17*33
            int icl = i / 561, r2 = i % 561;
            int r = r2 / 33, c = r2 % 33;
            int iy = iy0 + r, ix = ix0 + c;
            bool ok = (iy < Hin) && (ix < Win);
            const float* src = inp + (size_t)(ic0 + icl) * Hin * Win + (ok ? iy * Win + ix : 0);
            cp4(s2u(bi + icl * 578 + r * 34 + c), src, ok);
        }
        const float* wsrc = wt + (size_t)ic0 * 9 * OC + oc0;
        for (int i = tid; i < ICC * 9 * (OCB / 4); i += 256) {
            int p = i / (OCB / 4), c = i % (OCB / 4);
            cp16(s2u(bw + p * OCB + 4 * c), wsrc + (size_t)p * OC + 4 * c);
        }
    };

    ull acc[2][4][4];
#pragma unroll
    for (int b2 = 0; b2 < 2; b2++)
#pragma unroll
        for (int c = 0; c < 4; c++)
#pragma unroll
            for (int j = 0; j < 4; j++) acc[b2][c][j] = 0ull;

    prefetch(0, 0);
    cp_commit();
    const int NS = IC / ICC;
    for (int s = 0; s < NS; s++) {
        if (s + 1 < NS) { prefetch(s + 1, (s + 1) & 1); cp_commit(); cp_wait<1>(); }
        else cp_wait<0>();
        __syncthreads();
        const float* bi = s_in + (s & 1) * (ICC * 578);
        const float* bw = s_w + (s & 1) * (ICC * 9 * OCB);
#pragma unroll 2
        for (int icl = 0; icl < ICC; icl++) {
            const float* sp = bi + icl * 578 + ty * 34 + tx;
            ull a00 = pack2(sp[0]);
            ull a01 = pack2(sp[1]);
            ull a10 = pack2(sp[34]);
            ull a11 = pack2(sp[35]);
            ull b00 = pack2(sp[16]);
            ull b01 = pack2(sp[17]);
            ull b10 = pack2(sp[50]);
            ull b11 = pack2(sp[51]);
            const ulonglong2* wp = (const ulonglong2*)(bw + icl * 9 * OCB);
            tap8(acc[0][3], acc[1][3], a11, b11, wp + 0);   // tap0
            tap8(acc[0][2], acc[1][2], a10, b10, wp + 2);   // tap1
            tap8(acc[0][3], acc[1][3], a10, b10, wp + 4);   // tap2
            tap8(acc[0][1], acc[1][1], a01, b01, wp + 6);   // tap3
            tap8(acc[0][0], acc[1][0], a00, b00, wp + 8);   // tap4
            tap8(acc[0][1], acc[1][1], a00, b00, wp + 10);  // tap5
            tap8(acc[0][3], acc[1][3], a01, b01, wp + 12);  // tap6
            tap8(acc[0][2], acc[1][2], a00, b00, wp + 14);  // tap7
            tap8(acc[0][3], acc[1][3], a00, b00, wp + 16);  // tap8
        }
        __syncthreads();
    }

    const size_t cs = (size_t)Hout * Wout;
#pragma unroll
    for (int b2 = 0; b2 < 2; b2++) {
        int ye = oy0 + 2 * ty;
        int xe = ox0 + 2 * (tx + b2 * 16);
        bool y0v = ye < Hout, y1v = (ye + 1) < Hout;
        bool x0v = xe < Wout, x1v = (xe + 1) < Wout;
#pragma unroll
        for (int j = 0; j < 4; j++) {
            float bz0 = bias[oc0 + 2 * j], bz1 = bias[oc0 + 2 * j + 1];
            float* op0 = out + (size_t)(n * OC + oc0 + 2 * j) * cs;
            float* op1 = op0 + cs;
            float2 a;
            if (y0v && x0v) { a = unpack2(acc[b2][0][j]); op0[ye * Wout + xe] = a.x + bz0; op1[ye * Wout + xe] = a.y + bz1; }
            if (y0v && x1v) { a = unpack2(acc[b2][1][j]); op0[ye * Wout + xe + 1] = a.x + bz0; op1[ye * Wout + xe + 1] = a.y + bz1; }
            if (y1v && x0v) { a = unpack2(acc[b2][2][j]); op0[(ye + 1) * Wout + xe] = a.x + bz0; op1[(ye + 1) * Wout + xe] = a.y + bz1; }
            if (y1v && x1v) { a = unpack2(acc[b2][3][j]); op0[(ye + 1) * Wout + xe + 1] = a.x + bz0; op1[(ye + 1) * Wout + xe + 1] = a.y + bz1; }
        }
    }
}

// ---------------- layer 7: 7x7 conv 32->3 + tanh + fused segment accumulate ----
__global__ void __launch_bounds__(256, 2)
k_conv7_l7(const float* __restrict__ act, const float* __restrict__ wt,
           const float* __restrict__ bias, const int* __restrict__ inst,
           float* __restrict__ gsum, float* __restrict__ gcnt) {
    extern __shared__ float smem[];
    float* s_w  = smem;                 // 6272
    float* s_in = s_w + 6272;           // 2 * 4*1482
    __shared__ float ssb[96];
    __shared__ float scb[32];

    const int H = 249;
    const int tid = threadIdx.x;
    const int tx = tid & 15, ty = tid >> 4;
    const int n = blockIdx.z;
    const int oy0 = blockIdx.y * 32, ox0 = blockIdx.x * 32;

    for (int i = tid; i < 6272; i += 256) s_w[i] = wt[i];
    if (tid < 96) ssb[tid] = 0.f;
    if (tid < 32) scb[tid] = 0.f;

    const float* ap = act + (size_t)n * 32 * 62001;
    auto prefetch = [&](int st, int b) {
        float* bi = s_in + b * (4 * 1482);
        int ic0 = st * 4;
        for (int i = tid; i < 4 * 1444; i += 256) {
            int icl = i / 1444, r2 = i % 1444;
            int r = r2 / 38, c = r2 % 38;
            int iy = oy0 + r - 3, ix = ox0 + c - 3;
            iy = iy < 0 ? -iy : (iy > 248 ? 496 - iy : iy);
            ix = ix < 0 ? -ix : (ix > 248 ? 496 - ix : ix);
            cp4(s2u(bi + icl * 1482 + r * 39 + c),
                ap + (size_t)(ic0 + icl) * 62001 + iy * 249 + ix, true);
        }
    };

    ull acc[4][2];
#pragma unroll
    for (int p = 0; p < 4; p++) { acc[p][0] = 0ull; acc[p][1] = 0ull; }

    prefetch(0, 0);
    cp_commit();
    for (int s = 0; s < 8; s++) {
        if (s < 7) { prefetch(s + 1, (s + 1) & 1); cp_commit(); cp_wait<1>(); }
        else cp_wait<0>();
        __syncthreads();
        const float* bi = s_in + (s & 1) * (4 * 1482);
#pragma unroll 1
        for (int icl = 0; icl < 4; icl++) {
            const float* wic = s_w + (s * 4 + icl) * 196;
            const float* si = bi + icl * 1482;
#pragma unroll 1
            for (int ky = 0; ky < 7; ky++) {
                const float* sp0 = si + (2 * ty + ky) * 39 + 2 * tx;
                ull r0[9], r1[9];
#pragma unroll
                for (int k = 0; k < 9; k++) {
                    r0[k] = pack2(sp0[k]);
                    r1[k] = pack2(sp0[39 + k]);
                }
                const ulonglong2* wp = (const ulonglong2*)(wic + ky * 28);
#pragma unroll
                for (int kx = 0; kx < 7; kx++) {
                    ulonglong2 w2 = wp[kx];
                    fma2(acc[0][0], r0[kx], w2.x);     fma2(acc[0][1], r0[kx], w2.y);
                    fma2(acc[1][0], r0[kx + 1], w2.x); fma2(acc[1][1], r0[kx + 1], w2.y);
                    fma2(acc[2][0], r1[kx], w2.x);     fma2(acc[2][1], r1[kx], w2.y);
                    fma2(acc[3][0], r1[kx + 1], w2.x); fma2(acc[3][1], r1[kx + 1], w2.y);
                }
            }
        }
        __syncthreads();
    }

    float b0 = bias[0], b1 = bias[1], b2 = bias[2];
    const int* ip = inst + (size_t)n * 62001;
#pragma unroll
    for (int dy = 0; dy < 2; dy++)
#pragma unroll
        for (int dx = 0; dx < 2; dx++) {
            int oy = oy0 + 2 * ty + dy, ox = ox0 + 2 * tx + dx;
            if (oy < H && ox < H) {
                float2 a0 = unpack2(acc[dy * 2 + dx][0]);
                float2 a1 = unpack2(acc[dy * 2 + dx][1]);
                float t0 = tanhf(a0.x + b0);
                float t1 = tanhf(a0.y + b1);
                float t2 = tanhf(a1.x + b2);
                int id = ip[oy * 249 + ox];
                atomicAdd(&ssb[id * 3 + 0], t0);
                atomicAdd(&ssb[id * 3 + 1], t1);
                atomicAdd(&ssb[id * 3 + 2], t2);
                atomicAdd(&scb[id], 1.f);
            }
        }
    __syncthreads();
    if (tid < 96) atomicAdd(&gsum[tid], ssb[tid]);
    if (tid < 32) atomicAdd(&gcnt[tid], scb[tid]);
}

// ---------------- instance-norm stats + in-place normalize + ReLU ----------------
__global__ void k_instat(float* __restrict__ x, int HW) {
    int p = blockIdx.x;
    float* xp = x + (size_t)p * HW;
    float s0 = 0, s1 = 0, q0 = 0, q1 = 0;
    const bool vec = ((HW & 3) == 0);
    if (vec) {
        const float4* x4 = (const float4*)xp;
        int n4 = HW >> 2;
        for (int i = threadIdx.x; i < n4; i += 256) {
            float4 v = x4[i];
            s0 += v.x + v.y; q0 += v.x * v.x + v.y * v.y;
            s1 += v.z + v.w; q1 += v.z * v.z + v.w * v.w;
        }
    } else {
        int i = threadIdx.x;
        for (; i + 256 < HW; i += 512) {
            float a = xp[i], b = xp[i + 256];
            s0 += a; q0 += a * a;
            s1 += b; q1 += b * b;
        }
        if (i < HW) { float a = xp[i]; s0 += a; q0 += a * a; }
    }
    float s = s0 + s1, q = q0 + q1;
    for (int o = 16; o > 0; o >>= 1) {
        s += __shfl_down_sync(0xffffffffu, s, o);
        q += __shfl_down_sync(0xffffffffu, q, o);
    }
    __shared__ float sh[16];
    __shared__ float s_stat[2];
    int w = threadIdx.x >> 5, l = threadIdx.x & 31;
    if (l == 0) { sh[w] = s; sh[w + 8] = q; }
    __syncthreads();
    if (threadIdx.x == 0) {
        for (int k = 1; k < 8; k++) { s += sh[k]; q += sh[k + 8]; }
        float m = s / HW;
        float var = q / HW - m * m;
        float rs = rsqrtf(fmaxf(var, 0.f) + 1e-5f);
        s_stat[0] = rs;
        s_stat[1] = -m * rs;
    }
    __syncthreads();
    float rs = s_stat[0], sf = s_stat[1];
    if (vec) {
        float4* x4 = (float4*)xp;
        int n4 = HW >> 2;
        for (int i = threadIdx.x; i < n4; i += 256) {
            float4 v = x4[i];
            v.x = fmaxf(fmaf(v.x, rs, sf), 0.f);
            v.y = fmaxf(fmaf(v.y, rs, sf), 0.f);
            v.z = fmaxf(fmaf(v.z, rs, sf), 0.f);
            v.w = fmaxf(fmaf(v.w, rs, sf), 0.f);
            x4[i] = v;
        }
    } else {
        for (int i = threadIdx.x; i < HW; i += 256)
            xp[i] = fmaxf(fmaf(xp[i], rs, sf), 0.f);
    }
}

// ---------------- segment mean ----------------
__global__ void k_segzero(float* sum, float* cnt) {
    int t = threadIdx.x;
    if (t < 96) sum[t] = 0.f;
    if (t < 32) cnt[t] = 0.f;
}
__global__ void k_segbcast(const int* __restrict__ inst, const float* __restrict__ gsum,
                           const float* __restrict__ gcnt, float* __restrict__ out) {
    const int P = 62001, T = 8 * 3 * P;
    for (int i = blockIdx.x * blockDim.x + threadIdx.x; i < T; i += gridDim.x * blockDim.x) {
        int n = i / (3 * P), r = i % (3 * P);
        int c = r / P, p = r % P;
        int id = inst[n * P + p];
        out[i] = gsum[id * 3 + c] / fmaxf(gcnt[id], 1.f);
    }
}

// ---------------- launch ----------------
extern "C" void kernel_launch(void* const* d_in, const int* in_sizes, int n_in,
                              void* d_out, int out_size) {
    const float* x = (const float*)d_in[0];
    const int* inst = (const int*)d_in[1];
    const float* w[8];
    const float* b[8];
    for (int i = 0; i < 8; i++) {
        w[i] = (const float*)d_in[2 + 2 * i];
        b[i] = (const float*)d_in[3 + 2 * i];
    }
    float* out = (float*)d_out;

    float *A, *B;
    float *WT0, *WT1, *WT2, *WT3, *WT4, *WT5, *WT6, *WT7, *SS, *SN;
    cudaGetSymbolAddress((void**)&A, g_bufA);
    cudaGetSymbolAddress((void**)&B, g_bufB);
    cudaGetSymbolAddress((void**)&WT0, g_wt0);
    cudaGetSymbolAddress((void**)&WT1, g_wt1);
    cudaGetSymbolAddress((void**)&WT2, g_wt2);
    cudaGetSymbolAddress((void**)&WT3, g_wt3);
    cudaGetSymbolAddress((void**)&WT4, g_wt4);
    cudaGetSymbolAddress((void**)&WT5, g_wt5);
    cudaGetSymbolAddress((void**)&WT6, g_wt6);
    cudaGetSymbolAddress((void**)&WT7, g_wt7);
    cudaGetSymbolAddress((void**)&SS, g_segsum);
    cudaGetSymbolAddress((void**)&SN, g_segcnt);

    // dynamic smem sizes (bytes)
    const int SM_C = (2*8*9*64 + 2*8*33*36) * 4;   // 112.9 KB
    const int SM_T = (2*8*9*8 + 2*8*578) * 4;
    const int SM_L7 = (6272 + 2*4*1482) * 4;

    cudaFuncSetAttribute(k_conv3s2<32, 64, 8>,  cudaFuncAttributeMaxDynamicSharedMemorySize, SM_C);
    cudaFuncSetAttribute(k_conv3s2<64, 128, 8>, cudaFuncAttributeMaxDynamicSharedMemorySize, SM_C);
    cudaFuncSetAttribute(k_conv3s2<128, 256, 8>,cudaFuncAttributeMaxDynamicSharedMemorySize, SM_C);
    cudaFuncSetAttribute(k_convT<256, 128, 8>,  cudaFuncAttributeMaxDynamicSharedMemorySize, SM_T);
    cudaFuncSetAttribute(k_convT<128, 64, 8>,   cudaFuncAttributeMaxDynamicSharedMemorySize, SM_T);
    cudaFuncSetAttribute(k_convT<64, 32, 8>,    cudaFuncAttributeMaxDynamicSharedMemorySize, SM_T);
    cudaFuncSetAttribute(k_conv7_l7,            cudaFuncAttributeMaxDynamicSharedMemorySize, SM_L7);

    // weight prep
    k_prep<<<dim3(1152, 8), 256>>>(w[0], w[1], w[2], w[3], w[4], w[5], w[6], w[7],
                                   WT0, WT1, WT2, WT3, WT4, WT5, WT6, WT7);
    // layer 0
    k_conv7_l0<<<dim3(16, 16, 8), 256>>>(x, WT0, b[0], A);
    k_instat<<<8 * 32, 256>>>(A, 65536);
    // layers 1-3
    k_conv3s2<32, 64, 8><<<dim3(8, 8, 8), 256, SM_C>>>(A, WT1, b[1], B, 256, 256, 128, 128);
    k_instat<<<8 * 64, 256>>>(B, 16384);
    k_conv3s2<64, 128, 8><<<dim3(4, 4, 16), 256, SM_C>>>(B, WT2, b[2], A, 128, 128, 64, 64);
    k_instat<<<8 * 128, 256>>>(A, 4096);
    k_conv3s2<128, 256, 8><<<dim3(2, 2, 32), 256, SM_C>>>(A, WT3, b[3], B, 64, 64, 32, 32);
    k_instat<<<8 * 256, 256>>>(B, 1024);
    // layers 4-6 (transposed conv)
    k_convT<256, 128, 8><<<dim3(1, 2, 128), 256, SM_T>>>(B, WT4, b[4], A, 32, 32, 63, 63);
    k_instat<<<8 * 128, 256>>>(A, 3969);
    k_convT<128, 64, 8><<<dim3(2, 4, 64), 256, SM_T>>>(A, WT5, b[5], B, 63, 63, 125, 125);
    k_instat<<<8 * 64, 256>>>(B, 15625);
    k_convT<64, 32, 8><<<dim3(4, 8, 32), 256, SM_T>>>(B, WT6, b[6], A, 125, 125, 249, 249);
    k_instat<<<8 * 32, 256>>>(A, 62001);
    // segment bins zero, then layer 7 with fused segment accumulation
    k_segzero<<<1, 128>>>(SS, SN);
    k_conv7_l7<<<dim3(8, 8, 8), 256, SM_L7>>>(A, WT7, b[7], inst, SS, SN);
    // broadcast means
    k_segbcast<<<2048, 256>>>(inst, SS, SN, out);
}

// round 11
// speedup vs baseline: 2.3567x; 1.0151x over previous
#include <cuda_runtime.h>
#include <math.h>

// ---------------- static scratch ----------------
__device__ __align__(16) float g_bufA[16777216];
__device__ __align__(16) float g_bufB[8388608];
__device__ __align__(16) float g_wt0[3*49*32];
__device__ __align__(16) float g_wt1[32*9*64];
__device__ __align__(16) float g_wt2[64*9*128];
__device__ __align__(16) float g_wt3[128*9*256];
__device__ __align__(16) float g_wt4[256*9*128];
__device__ __align__(16) float g_wt5[128*9*64];
__device__ __align__(16) float g_wt6[64*9*32];
__device__ __align__(16) float g_wt7[32*49*4];
__device__ float g_segsum[96];
__device__ float g_segcnt[32];

typedef unsigned long long ull;

// ---------------- f32x2 packed helpers ----------------
__device__ __forceinline__ ull pack2(float v) {
    ull r;
    asm("mov.b64 %0, {%1, %1};" : "=l"(r) : "f"(v));
    return r;
}
__device__ __forceinline__ void fma2(ull& d, ull a, ull b) {
    asm("fma.rn.f32x2 %0, %1, %2, %0;" : "+l"(d) : "l"(a), "l"(b));
}
__device__ __forceinline__ float2 unpack2(ull v) {
    float2 f;
    asm("mov.b64 {%0, %1}, %2;" : "=f"(f.x), "=f"(f.y) : "l"(v));
    return f;
}

// ---------------- cp.async helpers ----------------
__device__ __forceinline__ unsigned s2u(const void* p) {
    return (unsigned)__cvta_generic_to_shared(p);
}
__device__ __forceinline__ void cp4(unsigned dst, const float* src, bool pred) {
    asm volatile("cp.async.ca.shared.global [%0], [%1], 4, %2;" ::
                 "r"(dst), "l"(src), "r"(pred ? 4u : 0u));
}
__device__ __forceinline__ void cp16(unsigned dst, const float* src) {
    asm volatile("cp.async.ca.shared.global [%0], [%1], 16;" ::
                 "r"(dst), "l"(src));
}
__device__ __forceinline__ void cp16z(unsigned dst, const float* src, unsigned sz) {
    asm volatile("cp.async.ca.shared.global [%0], [%1], 16, %2;" ::
                 "r"(dst), "l"(src), "r"(sz));
}
__device__ __forceinline__ void cp_commit() {
    asm volatile("cp.async.commit_group;" ::: "memory");
}
template <int N>
__device__ __forceinline__ void cp_wait() {
    asm volatile("cp.async.wait_group %0;" :: "n"(N) : "memory");
}

// ---------------- fused weight prep ----------------
__global__ void k_prep(const float* __restrict__ w0, const float* __restrict__ w1,
                       const float* __restrict__ w2, const float* __restrict__ w3,
                       const float* __restrict__ w4, const float* __restrict__ w5,
                       const float* __restrict__ w6, const float* __restrict__ w7,
                       float* o0, float* o1, float* o2, float* o3,
                       float* o4, float* o5, float* o6, float* o7) {
    int idx = blockIdx.x * 256 + threadIdx.x;
    switch (blockIdx.y) {
    case 0: if (idx < 32*3*49)   { int o=idx/147,  r=idx%147,  i=r/49, k=r%49; o0[(i*49+k)*32+o]=w0[idx]; } break;
    case 1: if (idx < 64*32*9)   { int o=idx/288,  r=idx%288,  i=r/9,  k=r%9;  o1[(i*9+k)*64+o]=w1[idx]; } break;
    case 2: if (idx < 128*64*9)  { int o=idx/576,  r=idx%576,  i=r/9,  k=r%9;  o2[(i*9+k)*128+o]=w2[idx]; } break;
    case 3: if (idx < 256*128*9) { int o=idx/1152, r=idx%1152, i=r/9,  k=r%9;  o3[(i*9+k)*256+o]=w3[idx]; } break;
    case 4: if (idx < 256*128*9) { int i=idx/1152, r=idx%1152, o=r/9,  k=r%9;  o4[(i*9+k)*128+o]=w4[idx]; } break;
    case 5: if (idx < 128*64*9)  { int i=idx/576,  r=idx%576,  o=r/9,  k=r%9;  o5[(i*9+k)*64+o]=w5[idx]; } break;
    case 6: if (idx < 64*32*9)   { int i=idx/288,  r=idx%288,  o=r/9,  k=r%9;  o6[(i*9+k)*32+o]=w6[idx]; } break;
    case 7: if (idx < 32*49*4)   { int p=idx>>2, o=idx&3; int i=p/49, k=p%49;
                                   o7[idx] = (o < 3) ? w7[(o*32+i)*49+k] : 0.f; } break;
    }
}

// ---------------- layer 0: reflect-pad 7x7 conv, 3->32, 2px x 16oc / thread ----
__global__ void __launch_bounds__(256)
k_conv7_l0(const float* __restrict__ x, const float* __restrict__ wt,
           const float* __restrict__ bias, float* __restrict__ out) {
    __shared__ __align__(16) float s_w[3 * 49 * 32];
    __shared__ float s_in[3 * 484];
    const int tid = threadIdx.x;
    const int og = tid >> 7;
    const int rem = tid & 127;
    const int ty = rem >> 4;
    const int tx = rem & 15;
    const int n = blockIdx.z;
    const int oy0 = blockIdx.y * 16, ox0 = blockIdx.x * 16;

    for (int i = tid; i < 3 * 49 * 32; i += 256) s_w[i] = wt[i];
    const float* xp = x + (size_t)n * 3 * 65536;
    for (int i = tid; i < 3 * 484; i += 256) {
        int ic = i / 484, rr = (i % 484) / 22, cc = i % 22;
        int iy = oy0 + rr - 3, ix = ox0 + cc - 3;
        iy = iy < 0 ? -iy : (iy > 255 ? 510 - iy : iy);
        ix = ix < 0 ? -ix : (ix > 255 ? 510 - ix : ix);
        s_in[i] = xp[ic * 65536 + iy * 256 + ix];
    }
    __syncthreads();

    ull acc0[8], acc1[8];
#pragma unroll
    for (int j = 0; j < 8; j++) { acc0[j] = 0ull; acc1[j] = 0ull; }

    for (int ic = 0; ic < 3; ic++)
#pragma unroll 1
        for (int ky = 0; ky < 7; ky++)
#pragma unroll
            for (int kx = 0; kx < 7; kx++) {
                ull v0 = pack2(s_in[ic * 484 + (ty + ky) * 22 + tx + kx]);
                ull v1 = pack2(s_in[ic * 484 + (ty + 8 + ky) * 22 + tx + kx]);
                const ulonglong2* wp =
                    (const ulonglong2*)(s_w + ((ic * 7 + ky) * 7 + kx) * 32 + og * 16);
#pragma unroll
                for (int q = 0; q < 4; q++) {
                    ulonglong2 w2 = wp[q];
                    fma2(acc0[2 * q + 0], v0, w2.x);
                    fma2(acc0[2 * q + 1], v0, w2.y);
                    fma2(acc1[2 * q + 0], v1, w2.x);
                    fma2(acc1[2 * q + 1], v1, w2.y);
                }
            }
    int oy = oy0 + ty, ox = ox0 + tx;
    float* op = out + (size_t)n * 32 * 65536 + (size_t)(og * 16) * 65536 + oy * 256 + ox;
#pragma unroll
    for (int j = 0; j < 8; j++) {
        float2 a = unpack2(acc0[j]);
        float2 b = unpack2(acc1[j]);
        float bz0 = bias[og * 16 + 2 * j], bz1 = bias[og * 16 + 2 * j + 1];
        op[(size_t)(2 * j + 0) * 65536] = a.x + bz0;
        op[(size_t)(2 * j + 1) * 65536] = a.y + bz1;
        op[(size_t)(2 * j + 0) * 65536 + 8 * 256] = b.x + bz0;
        op[(size_t)(2 * j + 1) * 65536 + 8 * 256] = b.y + bz1;
    }
}

// ---------------- 3x3 stride-2 conv: 8px x 8oc / thread (SGEMM-style warp map) --
// Warp w owns output rows {2w, 2w+1}, 16 cols, 64 oc.
// lane: og = lane&7 (oc octet, oc = 8*og..8*og+7), pg = lane>>3 (cols 4pg..4pg+3)
template <int IC, int OC, int ICC>
__global__ void __launch_bounds__(256, 2)
k_conv3s2(const float* __restrict__ in, const float* __restrict__ wt,
          const float* __restrict__ bias, float* __restrict__ out,
          int Hin, int Win, int Hout, int Wout) {
    const int OCB = 64;
    const int PIN = 33 * 36;
    extern __shared__ float smem[];
    float* s_w  = smem;                         // 2 * ICC*9*64
    float* s_in = s_w + 2 * ICC * 9 * OCB;      // 2 * ICC*PIN

    const int tid = threadIdx.x;
    const int wz = tid >> 5;            // warp id 0..7 -> rows 2wz, 2wz+1
    const int lane = tid & 31;
    const int og = lane & 7;
    const int pg = lane >> 3;
    const int z = blockIdx.z;
    const int n = z / (OC / OCB);
    const int oc0 = (z % (OC / OCB)) * OCB;
    const int oy0 = blockIdx.y * 16, ox0 = blockIdx.x * 16;
    const int iy0 = 2 * oy0 - 1;
    const int ixa = 2 * ox0 - 4;

    const float* inp = in + (size_t)n * IC * Hin * Win;

    auto prefetch = [&](int st, int b) {
        int ic0 = st * ICC;
        float* bw = s_w + b * (ICC * 9 * OCB);
        float* bi = s_in + b * (ICC * PIN);
        for (int i = tid; i < ICC * 33 * 9; i += 256) {
            int icl = i / 297;
            int r2 = i % 297;
            int r = r2 / 9, c9 = r2 % 9;
            int iy = iy0 + r;
            int sx = ixa + 4 * c9;
            bool ok = ((unsigned)iy < (unsigned)Hin) && (sx >= 0);
            unsigned sz = ok ? 16u : 0u;
            const float* src = inp + (size_t)(ic0 + icl) * Hin * Win +
                               (ok ? iy * Win + sx : 0);
            cp16z(s2u(bi + icl * PIN + r * 36 + 4 * c9), src, sz);
        }
        const float* wsrc = wt + (size_t)ic0 * 9 * OC + oc0;
        for (int i = tid; i < ICC * 9 * (OCB / 4); i += 256) {
            int p = i / (OCB / 4), c = i % (OCB / 4);
            cp16(s2u(bw + p * OCB + 4 * c), wsrc + (size_t)p * OC + 4 * c);
        }
    };

    // acc[r][c][j]: r=row in pair, c=col in quad, j=oc pair (oc 8og+2j, +1)
    ull acc[2][4][4];
#pragma unroll
    for (int r = 0; r < 2; r++)
#pragma unroll
        for (int c = 0; c < 4; c++)
#pragma unroll
            for (int j = 0; j < 4; j++) acc[r][c][j] = 0ull;

    prefetch(0, 0);
    cp_commit();
    const int NS = IC / ICC;
    for (int s = 0; s < NS; s++) {
        if (s + 1 < NS) { prefetch(s + 1, (s + 1) & 1); cp_commit(); cp_wait<1>(); }
        else cp_wait<0>();
        __syncthreads();
        const float* bi = s_in + (s & 1) * (ICC * PIN);
        const float* bw = s_w + (s & 1) * (ICC * 9 * OCB);
#pragma unroll 1
        for (int icl = 0; icl < ICC; icl++) {
            const float* srow = bi + icl * PIN + 8 * pg + 3;
            const float* wb = bw + icl * 9 * OCB + og * 8;
#pragma unroll
            for (int ky = 0; ky < 3; ky++) {
                const float* r0p = srow + (4 * wz + ky) * 36;
                const float* r1p = r0p + 72;
                ull u0[9], u1[9];
#pragma unroll
                for (int k = 0; k < 9; k++) {
                    u0[k] = pack2(r0p[k]);
                    u1[k] = pack2(r1p[k]);
                }
#pragma unroll
                for (int kx = 0; kx < 3; kx++) {
                    const ulonglong2* wp = (const ulonglong2*)(wb + (3 * ky + kx) * OCB);
                    ulonglong2 wa = wp[0], wb2 = wp[1];
#pragma unroll
                    for (int c = 0; c < 4; c++) {
                        ull v0 = u0[2 * c + kx];
                        ull v1 = u1[2 * c + kx];
                        fma2(acc[0][c][0], v0, wa.x);
                        fma2(acc[0][c][1], v0, wa.y);
                        fma2(acc[0][c][2], v0, wb2.x);
                        fma2(acc[0][c][3], v0, wb2.y);
                        fma2(acc[1][c][0], v1, wa.x);
                        fma2(acc[1][c][1], v1, wa.y);
                        fma2(acc[1][c][2], v1, wb2.x);
                        fma2(acc[1][c][3], v1, wb2.y);
                    }
                }
            }
        }
        __syncthreads();
    }

    // epilogue: 2 rows x 8 oc, float4 across the col quad
    const int oy = oy0 + 2 * wz;
    const int ox = ox0 + 4 * pg;
    const size_t cs = (size_t)Hout * Wout;
    float* obase = out + (size_t)(n * OC + oc0 + og * 8) * cs + (size_t)oy * Wout + ox;
#pragma unroll
    for (int r = 0; r < 2; r++)
#pragma unroll
        for (int j = 0; j < 4; j++) {
            float2 p0 = unpack2(acc[r][0][j]);
            float2 p1 = unpack2(acc[r][1][j]);
            float2 p2 = unpack2(acc[r][2][j]);
            float2 p3 = unpack2(acc[r][3][j]);
            float blo = bias[oc0 + og * 8 + 2 * j];
            float bhi = bias[oc0 + og * 8 + 2 * j + 1];
            float4 vlo = make_float4(p0.x + blo, p1.x + blo, p2.x + blo, p3.x + blo);
            float4 vhi = make_float4(p0.y + bhi, p1.y + bhi, p2.y + bhi, p3.y + bhi);
            *(float4*)(obase + (size_t)(2 * j) * cs + r * Wout) = vlo;
            *(float4*)(obase + (size_t)(2 * j + 1) * cs + r * Wout) = vhi;
        }
}

// ---------------- convT on pre-normalized input ----------------
__device__ __forceinline__ void tap8(ull* A, ull* B, ull va, ull vb,
                                     const ulonglong2* wp) {
    ulonglong2 w0 = wp[0], w1 = wp[1];
    fma2(A[0], va, w0.x); fma2(A[1], va, w0.y);
    fma2(A[2], va, w1.x); fma2(A[3], va, w1.y);
    fma2(B[0], vb, w0.x); fma2(B[1], vb, w0.y);
    fma2(B[2], vb, w1.x); fma2(B[3], vb, w1.y);
}

template <int IC, int OC, int ICC>
__global__ void __launch_bounds__(256, 2)
k_convT(const float* __restrict__ in, const float* __restrict__ wt,
        const float* __restrict__ bias, float* __restrict__ out,
        int Hin, int Win, int Hout, int Wout) {
    const int OCB = 8;
    extern __shared__ float smem[];
    float* s_w  = smem;
    float* s_in = s_w + 2 * ICC * 9 * OCB;

    const int tid = threadIdx.x;
    const int ty = tid >> 4;
    const int tx = tid & 15;
    const int z = blockIdx.z;
    const int n = z / (OC / OCB);
    const int oc0 = (z % (OC / OCB)) * OCB;
    const int oy0 = blockIdx.y * 32, ox0 = blockIdx.x * 64;
    const int iy0 = oy0 >> 1, ix0 = ox0 >> 1;

    const float* inp = in + (size_t)n * IC * Hin * Win;

    auto prefetch = [&](int st, int b) {
        int ic0 = st * ICC;
        float* bw = s_w + b * (ICC * 9 * OCB);
        float* bi = s_in + b * (ICC * 578);
        for (int i = tid; i < ICC * 561; i += 256) {
            int icl = i / 561, r2 = i % 561;
            int r = r2 / 33, c = r2 % 33;
            int iy = iy0 + r, ix = ix0 + c;
            bool ok = (iy < Hin) && (ix < Win);
            const float* src = inp + (size_t)(ic0 + icl) * Hin * Win + (ok ? iy * Win + ix : 0);
            cp4(s2u(bi + icl * 578 + r * 34 + c), src, ok);
        }
        const float* wsrc = wt + (size_t)ic0 * 9 * OC + oc0;
        for (int i = tid; i < ICC * 9 * (OCB / 4); i += 256) {
            int p = i / (OCB / 4), c = i % (OCB / 4);
            cp16(s2u(bw + p * OCB + 4 * c), wsrc + (size_t)p * OC + 4 * c);
        }
    };

    ull acc[2][4][4];
#pragma unroll
    for (int b2 = 0; b2 < 2; b2++)
#pragma unroll
        for (int c = 0; c < 4; c++)
#pragma unroll
            for (int j = 0; j < 4; j++) acc[b2][c][j] = 0ull;

    prefetch(0, 0);
    cp_commit();
    const int NS = IC / ICC;
    for (int s = 0; s < NS; s++) {
        if (s + 1 < NS) { prefetch(s + 1, (s + 1) & 1); cp_commit(); cp_wait<1>(); }
        else cp_wait<0>();
        __syncthreads();
        const float* bi = s_in + (s & 1) * (ICC * 578);
        const float* bw = s_w + (s & 1) * (ICC * 9 * OCB);
#pragma unroll 2
        for (int icl = 0; icl < ICC; icl++) {
            const float* sp = bi + icl * 578 + ty * 34 + tx;
            ull a00 = pack2(sp[0]);
            ull a01 = pack2(sp[1]);
            ull a10 = pack2(sp[34]);
            ull a11 = pack2(sp[35]);
            ull b00 = pack2(sp[16]);
            ull b01 = pack2(sp[17]);
            ull b10 = pack2(sp[50]);
            ull b11 = pack2(sp[51]);
            const ulonglong2* wp = (const ulonglong2*)(bw + icl * 9 * OCB);
            tap8(acc[0][3], acc[1][3], a11, b11, wp + 0);
            tap8(acc[0][2], acc[1][2], a10, b10, wp + 2);
            tap8(acc[0][3], acc[1][3], a10, b10, wp + 4);
            tap8(acc[0][1], acc[1][1], a01, b01, wp + 6);
            tap8(acc[0][0], acc[1][0], a00, b00, wp + 8);
            tap8(acc[0][1], acc[1][1], a00, b00, wp + 10);
            tap8(acc[0][3], acc[1][3], a01, b01, wp + 12);
            tap8(acc[0][2], acc[1][2], a00, b00, wp + 14);
            tap8(acc[0][3], acc[1][3], a00, b00, wp + 16);
        }
        __syncthreads();
    }

    const size_t cs = (size_t)Hout * Wout;
#pragma unroll
    for (int b2 = 0; b2 < 2; b2++) {
        int ye = oy0 + 2 * ty;
        int xe = ox0 + 2 * (tx + b2 * 16);
        bool y0v = ye < Hout, y1v = (ye + 1) < Hout;
        bool x0v = xe < Wout, x1v = (xe + 1) < Wout;
#pragma unroll
        for (int j = 0; j < 4; j++) {
            float bz0 = bias[oc0 + 2 * j], bz1 = bias[oc0 + 2 * j + 1];
            float* op0 = out + (size_t)(n * OC + oc0 + 2 * j) * cs;
            float* op1 = op0 + cs;
            float2 a;
            if (y0v && x0v) { a = unpack2(acc[b2][0][j]); op0[ye * Wout + xe] = a.x + bz0; op1[ye * Wout + xe] = a.y + bz1; }
            if (y0v && x1v) { a = unpack2(acc[b2][1][j]); op0[ye * Wout + xe + 1] = a.x + bz0; op1[ye * Wout + xe + 1] = a.y + bz1; }
            if (y1v && x0v) { a = unpack2(acc[b2][2][j]); op0[(ye + 1) * Wout + xe] = a.x + bz0; op1[(ye + 1) * Wout + xe] = a.y + bz1; }
            if (y1v && x1v) { a = unpack2(acc[b2][3][j]); op0[(ye + 1) * Wout + xe + 1] = a.x + bz0; op1[(ye + 1) * Wout + xe + 1] = a.y + bz1; }
        }
    }
}

// ---------------- layer 7: 7x7 conv 32->3 + tanh + fused segment accumulate ----
__global__ void __launch_bounds__(256, 2)
k_conv7_l7(const float* __restrict__ act, const float* __restrict__ wt,
           const float* __restrict__ bias, const int* __restrict__ inst,
           float* __restrict__ gsum, float* __restrict__ gcnt) {
    extern __shared__ float smem[];
    float* s_w  = smem;
    float* s_in = s_w + 6272;
    __shared__ float ssb[96];
    __shared__ float scb[32];

    const int H = 249;
    const int tid = threadIdx.x;
    const int tx = tid & 15, ty = tid >> 4;
    const int n = blockIdx.z;
    const int oy0 = blockIdx.y * 32, ox0 = blockIdx.x * 32;

    for (int i = tid; i < 6272; i += 256) s_w[i] = wt[i];
    if (tid < 96) ssb[tid] = 0.f;
    if (tid < 32) scb[tid] = 0.f;

    const float* ap = act + (size_t)n * 32 * 62001;
    auto prefetch = [&](int st, int b) {
        float* bi = s_in + b * (4 * 1482);
        int ic0 = st * 4;
        for (int i = tid; i < 4 * 1444; i += 256) {
            int icl = i / 1444, r2 = i % 1444;
            int r = r2 / 38, c = r2 % 38;
            int iy = oy0 + r - 3, ix = ox0 + c - 3;
            iy = iy < 0 ? -iy : (iy > 248 ? 496 - iy : iy);
            ix = ix < 0 ? -ix : (ix > 248 ? 496 - ix : ix);
            cp4(s2u(bi + icl * 1482 + r * 39 + c),
                ap + (size_t)(ic0 + icl) * 62001 + iy * 249 + ix, true);
        }
    };

    ull acc[4][2];
#pragma unroll
    for (int p = 0; p < 4; p++) { acc[p][0] = 0ull; acc[p][1] = 0ull; }

    prefetch(0, 0);
    cp_commit();
    for (int s = 0; s < 8; s++) {
        if (s < 7) { prefetch(s + 1, (s + 1) & 1); cp_commit(); cp_wait<1>(); }
        else cp_wait<0>();
        __syncthreads();
        const float* bi = s_in + (s & 1) * (4 * 1482);
#pragma unroll 1
        for (int icl = 0; icl < 4; icl++) {
            const float* wic = s_w + (s * 4 + icl) * 196;
            const float* si = bi + icl * 1482;
#pragma unroll 1
            for (int ky = 0; ky < 7; ky++) {
                const float* sp0 = si + (2 * ty + ky) * 39 + 2 * tx;
                ull r0[9], r1[9];
#pragma unroll
                for (int k = 0; k < 9; k++) {
                    r0[k] = pack2(sp0[k]);
                    r1[k] = pack2(sp0[39 + k]);
                }
                const ulonglong2* wp = (const ulonglong2*)(wic + ky * 28);
#pragma unroll
                for (int kx = 0; kx < 7; kx++) {
                    ulonglong2 w2 = wp[kx];
                    fma2(acc[0][0], r0[kx], w2.x);     fma2(acc[0][1], r0[kx], w2.y);
                    fma2(acc[1][0], r0[kx + 1], w2.x); fma2(acc[1][1], r0[kx + 1], w2.y);
                    fma2(acc[2][0], r1[kx], w2.x);     fma2(acc[2][1], r1[kx], w2.y);
                    fma2(acc[3][0], r1[kx + 1], w2.x); fma2(acc[3][1], r1[kx + 1], w2.y);
                }
            }
        }
        __syncthreads();
    }

    float b0 = bias[0], b1 = bias[1], b2 = bias[2];
    const int* ip = inst + (size_t)n * 62001;
#pragma unroll
    for (int dy = 0; dy < 2; dy++)
#pragma unroll
        for (int dx = 0; dx < 2; dx++) {
            int oy = oy0 + 2 * ty + dy, ox = ox0 + 2 * tx + dx;
            if (oy < H && ox < H) {
                float2 a0 = unpack2(acc[dy * 2 + dx][0]);
                float2 a1 = unpack2(acc[dy * 2 + dx][1]);
                float t0 = tanhf(a0.x + b0);
                float t1 = tanhf(a0.y + b1);
                float t2 = tanhf(a1.x + b2);
                int id = ip[oy * 249 + ox];
                atomicAdd(&ssb[id * 3 + 0], t0);
                atomicAdd(&ssb[id * 3 + 1], t1);
                atomicAdd(&ssb[id * 3 + 2], t2);
                atomicAdd(&scb[id], 1.f);
            }
        }
    __syncthreads();
    if (tid < 96) atomicAdd(&gsum[tid], ssb[tid]);
    if (tid < 32) atomicAdd(&gcnt[tid], scb[tid]);
}

// ---------------- instance-norm stats + in-place normalize + ReLU ----------------
__global__ void k_instat(float* __restrict__ x, int HW) {
    int p = blockIdx.x;
    float* xp = x + (size_t)p * HW;
    float s0 = 0, s1 = 0, q0 = 0, q1 = 0;
    const bool vec = ((HW & 3) == 0);
    if (vec) {
        const float4* x4 = (const float4*)xp;
        int n4 = HW >> 2;
        for (int i = threadIdx.x; i < n4; i += 256) {
            float4 v = x4[i];
            s0 += v.x + v.y; q0 += v.x * v.x + v.y * v.y;
            s1 += v.z + v.w; q1 += v.z * v.z + v.w * v.w;
        }
    } else {
        int i = threadIdx.x;
        for (; i + 256 < HW; i += 512) {
            float a = xp[i], b = xp[i + 256];
            s0 += a; q0 += a * a;
            s1 += b; q1 += b * b;
        }
        if (i < HW) { float a = xp[i]; s0 += a; q0 += a * a; }
    }
    float s = s0 + s1, q = q0 + q1;
    for (int o = 16; o > 0; o >>= 1) {
        s += __shfl_down_sync(0xffffffffu, s, o);
        q += __shfl_down_sync(0xffffffffu, q, o);
    }
    __shared__ float sh[16];
    __shared__ float s_stat[2];
    int w = threadIdx.x >> 5, l = threadIdx.x & 31;
    if (l == 0) { sh[w] = s; sh[w + 8] = q; }
    __syncthreads();
    if (threadIdx.x == 0) {
        for (int k = 1; k < 8; k++) { s += sh[k]; q += sh[k + 8]; }
        float m = s / HW;
        float var = q / HW - m * m;
        float rs = rsqrtf(fmaxf(var, 0.f) + 1e-5f);
        s_stat[0] = rs;
        s_stat[1] = -m * rs;
    }
    __syncthreads();
    float rs = s_stat[0], sf = s_stat[1];
    if (vec) {
        float4* x4 = (float4*)xp;
        int n4 = HW >> 2;
        for (int i = threadIdx.x; i < n4; i += 256) {
            float4 v = x4[i];
            v.x = fmaxf(fmaf(v.x, rs, sf), 0.f);
            v.y = fmaxf(fmaf(v.y, rs, sf), 0.f);
            v.z = fmaxf(fmaf(v.z, rs, sf), 0.f);
            v.w = fmaxf(fmaf(v.w, rs, sf), 0.f);
            x4[i] = v;
        }
    } else {
        for (int i = threadIdx.x; i < HW; i += 256)
            xp[i] = fmaxf(fmaf(xp[i], rs, sf), 0.f);
    }
}

// ---------------- segment mean ----------------
__global__ void k_segzero(float* sum, float* cnt) {
    int t = threadIdx.x;
    if (t < 96) sum[t] = 0.f;
    if (t < 32) cnt[t] = 0.f;
}
__global__ void k_segbcast(const int* __restrict__ inst, const float* __restrict__ gsum,
                           const float* __restrict__ gcnt, float* __restrict__ out) {
    const int P = 62001, T = 8 * 3 * P;
    for (int i = blockIdx.x * blockDim.x + threadIdx.x; i < T; i += gridDim.x * blockDim.x) {
        int n = i / (3 * P), r = i % (3 * P);
        int c = r / P, p = r % P;
        int id = inst[n * P + p];
        out[i] = gsum[id * 3 + c] / fmaxf(gcnt[id], 1.f);
    }
}

// ---------------- launch ----------------
extern "C" void kernel_launch(void* const* d_in, const int* in_sizes, int n_in,
                              void* d_out, int out_size) {
    const float* x = (const float*)d_in[0];
    const int* inst = (const int*)d_in[1];
    const float* w[8];
    const float* b[8];
    for (int i = 0; i < 8; i++) {
        w[i] = (const float*)d_in[2 + 2 * i];
        b[i] = (const float*)d_in[3 + 2 * i];
    }
    float* out = (float*)d_out;

    float *A, *B;
    float *WT0, *WT1, *WT2, *WT3, *WT4, *WT5, *WT6, *WT7, *SS, *SN;
    cudaGetSymbolAddress((void**)&A, g_bufA);
    cudaGetSymbolAddress((void**)&B, g_bufB);
    cudaGetSymbolAddress((void**)&WT0, g_wt0);
    cudaGetSymbolAddress((void**)&WT1, g_wt1);
    cudaGetSymbolAddress((void**)&WT2, g_wt2);
    cudaGetSymbolAddress((void**)&WT3, g_wt3);
    cudaGetSymbolAddress((void**)&WT4, g_wt4);
    cudaGetSymbolAddress((void**)&WT5, g_wt5);
    cudaGetSymbolAddress((void**)&WT6, g_wt6);
    cudaGetSymbolAddress((void**)&WT7, g_wt7);
    cudaGetSymbolAddress((void**)&SS, g_segsum);
    cudaGetSymbolAddress((void**)&SN, g_segcnt);

    const int SM_C = (2*8*9*64 + 2*8*33*36) * 4;
    const int SM_T = (2*8*9*8 + 2*8*578) * 4;
    const int SM_L7 = (6272 + 2*4*1482) * 4;

    cudaFuncSetAttribute(k_conv3s2<32, 64, 8>,  cudaFuncAttributeMaxDynamicSharedMemorySize, SM_C);
    cudaFuncSetAttribute(k_conv3s2<64, 128, 8>, cudaFuncAttributeMaxDynamicSharedMemorySize, SM_C);
    cudaFuncSetAttribute(k_conv3s2<128, 256, 8>,cudaFuncAttributeMaxDynamicSharedMemorySize, SM_C);
    cudaFuncSetAttribute(k_convT<256, 128, 8>,  cudaFuncAttributeMaxDynamicSharedMemorySize, SM_T);
    cudaFuncSetAttribute(k_convT<128, 64, 8>,   cudaFuncAttributeMaxDynamicSharedMemorySize, SM_T);
    cudaFuncSetAttribute(k_convT<64, 32, 8>,    cudaFuncAttributeMaxDynamicSharedMemorySize, SM_T);
    cudaFuncSetAttribute(k_conv7_l7,            cudaFuncAttributeMaxDynamicSharedMemorySize, SM_L7);

    // weight prep
    k_prep<<<dim3(1152, 8), 256>>>(w[0], w[1], w[2], w[3], w[4], w[5], w[6], w[7],
                                   WT0, WT1, WT2, WT3, WT4, WT5, WT6, WT7);
    // layer 0
    k_conv7_l0<<<dim3(16, 16, 8), 256>>>(x, WT0, b[0], A);
    k_instat<<<8 * 32, 256>>>(A, 65536);
    // layers 1-3
    k_conv3s2<32, 64, 8><<<dim3(8, 8, 8), 256, SM_C>>>(A, WT1, b[1], B, 256, 256, 128, 128);
    k_instat<<<8 * 64, 256>>>(B, 16384);
    k_conv3s2<64, 128, 8><<<dim3(4, 4, 16), 256, SM_C>>>(B, WT2, b[2], A, 128, 128, 64, 64);
    k_instat<<<8 * 128, 256>>>(A, 4096);
    k_conv3s2<128, 256, 8><<<dim3(2, 2, 32), 256, SM_C>>>(A, WT3, b[3], B, 64, 64, 32, 32);
    k_instat<<<8 * 256, 256>>>(B, 1024);
    // layers 4-6 (transposed conv)
    k_convT<256, 128, 8><<<dim3(1, 2, 128), 256, SM_T>>>(B, WT4, b[4], A, 32, 32, 63, 63);
    k_instat<<<8 * 128, 256>>>(A, 3969);
    k_convT<128, 64, 8><<<dim3(2, 4, 64), 256, SM_T>>>(A, WT5, b[5], B, 63, 63, 125, 125);
    k_instat<<<8 * 64, 256>>>(B, 15625);
    k_convT<64, 32, 8><<<dim3(4, 8, 32), 256, SM_T>>>(B, WT6, b[6], A, 125, 125, 249, 249);
    k_instat<<<8 * 32, 256>>>(A, 62001);
    // segment bins zero, then layer 7 with fused segment accumulation
    k_segzero<<<1, 128>>>(SS, SN);
    k_conv7_l7<<<dim3(8, 8, 8), 256, SM_L7>>>(A, WT7, b[7], inst, SS, SN);
    // broadcast means
    k_segbcast<<<2048, 256>>>(inst, SS, SN, out);
}

// round 12
// speedup vs baseline: 2.4176x; 1.0258x over previous
#include <cuda_runtime.h>
#include <math.h>

// ---------------- static scratch ----------------
__device__ __align__(16) float g_bufA[16777216];
__device__ __align__(16) float g_bufB[8388608];
__device__ __align__(16) float g_wt0[3*49*32];
__device__ __align__(16) float g_wt1[32*9*64];
__device__ __align__(16) float g_wt2[64*9*128];
__device__ __align__(16) float g_wt3[128*9*256];
__device__ __align__(16) float g_wt4[256*9*128];
__device__ __align__(16) float g_wt5[128*9*64];
__device__ __align__(16) float g_wt6[64*9*32];
__device__ __align__(16) float g_wt7[32*49*4];
__device__ float g_segsum[96];
__device__ float g_segcnt[32];

typedef unsigned long long ull;

// ---------------- f32x2 packed helpers ----------------
__device__ __forceinline__ ull pack2(float v) {
    ull r;
    asm("mov.b64 %0, {%1, %1};" : "=l"(r) : "f"(v));
    return r;
}
__device__ __forceinline__ void fma2(ull& d, ull a, ull b) {
    asm("fma.rn.f32x2 %0, %1, %2, %0;" : "+l"(d) : "l"(a), "l"(b));
}
__device__ __forceinline__ float2 unpack2(ull v) {
    float2 f;
    asm("mov.b64 {%0, %1}, %2;" : "=f"(f.x), "=f"(f.y) : "l"(v));
    return f;
}

// ---------------- cp.async helpers ----------------
__device__ __forceinline__ unsigned s2u(const void* p) {
    return (unsigned)__cvta_generic_to_shared(p);
}
__device__ __forceinline__ void cp4(unsigned dst, const float* src, bool pred) {
    asm volatile("cp.async.ca.shared.global [%0], [%1], 4, %2;" ::
                 "r"(dst), "l"(src), "r"(pred ? 4u : 0u));
}
__device__ __forceinline__ void cp16(unsigned dst, const float* src) {
    asm volatile("cp.async.ca.shared.global [%0], [%1], 16;" ::
                 "r"(dst), "l"(src));
}
__device__ __forceinline__ void cp16z(unsigned dst, const float* src, unsigned sz) {
    asm volatile("cp.async.ca.shared.global [%0], [%1], 16, %2;" ::
                 "r"(dst), "l"(src), "r"(sz));
}
__device__ __forceinline__ void cp_commit() {
    asm volatile("cp.async.commit_group;" ::: "memory");
}
template <int N>
__device__ __forceinline__ void cp_wait() {
    asm volatile("cp.async.wait_group %0;" :: "n"(N) : "memory");
}

// ---------------- fused weight prep ----------------
__global__ void k_prep(const float* __restrict__ w0, const float* __restrict__ w1,
                       const float* __restrict__ w2, const float* __restrict__ w3,
                       const float* __restrict__ w4, const float* __restrict__ w5,
                       const float* __restrict__ w6, const float* __restrict__ w7,
                       float* o0, float* o1, float* o2, float* o3,
                       float* o4, float* o5, float* o6, float* o7) {
    int idx = blockIdx.x * 256 + threadIdx.x;
    switch (blockIdx.y) {
    case 0: if (idx < 32*3*49)   { int o=idx/147,  r=idx%147,  i=r/49, k=r%49; o0[(i*49+k)*32+o]=w0[idx]; } break;
    case 1: if (idx < 64*32*9)   { int o=idx/288,  r=idx%288,  i=r/9,  k=r%9;  o1[(i*9+k)*64+o]=w1[idx]; } break;
    case 2: if (idx < 128*64*9)  { int o=idx/576,  r=idx%576,  i=r/9,  k=r%9;  o2[(i*9+k)*128+o]=w2[idx]; } break;
    case 3: if (idx < 256*128*9) { int o=idx/1152, r=idx%1152, i=r/9,  k=r%9;  o3[(i*9+k)*256+o]=w3[idx]; } break;
    case 4: if (idx < 256*128*9) { int i=idx/1152, r=idx%1152, o=r/9,  k=r%9;  o4[(i*9+k)*128+o]=w4[idx]; } break;
    case 5: if (idx < 128*64*9)  { int i=idx/576,  r=idx%576,  o=r/9,  k=r%9;  o5[(i*9+k)*64+o]=w5[idx]; } break;
    case 6: if (idx < 64*32*9)   { int i=idx/288,  r=idx%288,  o=r/9,  k=r%9;  o6[(i*9+k)*32+o]=w6[idx]; } break;
    case 7: if (idx < 32*49*4)   { int p=idx>>2, o=idx&3; int i=p/49, k=p%49;
                                   o7[idx] = (o < 3) ? w7[(o*32+i)*49+k] : 0.f; } break;
    }
}

// ---------------- layer 0: reflect-pad 7x7 conv, 3->32, 2px x 16oc / thread ----
__global__ void __launch_bounds__(256)
k_conv7_l0(const float* __restrict__ x, const float* __restrict__ wt,
           const float* __restrict__ bias, float* __restrict__ out) {
    __shared__ __align__(16) float s_w[3 * 49 * 32];
    __shared__ float s_in[3 * 484];
    const int tid = threadIdx.x;
    const int og = tid >> 7;
    const int rem = tid & 127;
    const int ty = rem >> 4;
    const int tx = rem & 15;
    const int n = blockIdx.z;
    const int oy0 = blockIdx.y * 16, ox0 = blockIdx.x * 16;

    for (int i = tid; i < 3 * 49 * 32; i += 256) s_w[i] = wt[i];
    const float* xp = x + (size_t)n * 3 * 65536;
    for (int i = tid; i < 3 * 484; i += 256) {
        int ic = i / 484, rr = (i % 484) / 22, cc = i % 22;
        int iy = oy0 + rr - 3, ix = ox0 + cc - 3;
        iy = iy < 0 ? -iy : (iy > 255 ? 510 - iy : iy);
        ix = ix < 0 ? -ix : (ix > 255 ? 510 - ix : ix);
        s_in[i] = xp[ic * 65536 + iy * 256 + ix];
    }
    __syncthreads();

    ull acc0[8], acc1[8];
#pragma unroll
    for (int j = 0; j < 8; j++) { acc0[j] = 0ull; acc1[j] = 0ull; }

    for (int ic = 0; ic < 3; ic++)
#pragma unroll 1
        for (int ky = 0; ky < 7; ky++)
#pragma unroll
            for (int kx = 0; kx < 7; kx++) {
                ull v0 = pack2(s_in[ic * 484 + (ty + ky) * 22 + tx + kx]);
                ull v1 = pack2(s_in[ic * 484 + (ty + 8 + ky) * 22 + tx + kx]);
                const ulonglong2* wp =
                    (const ulonglong2*)(s_w + ((ic * 7 + ky) * 7 + kx) * 32 + og * 16);
#pragma unroll
                for (int q = 0; q < 4; q++) {
                    ulonglong2 w2 = wp[q];
                    fma2(acc0[2 * q + 0], v0, w2.x);
                    fma2(acc0[2 * q + 1], v0, w2.y);
                    fma2(acc1[2 * q + 0], v1, w2.x);
                    fma2(acc1[2 * q + 1], v1, w2.y);
                }
            }
    int oy = oy0 + ty, ox = ox0 + tx;
    float* op = out + (size_t)n * 32 * 65536 + (size_t)(og * 16) * 65536 + oy * 256 + ox;
#pragma unroll
    for (int j = 0; j < 8; j++) {
        float2 a = unpack2(acc0[j]);
        float2 b = unpack2(acc1[j]);
        float bz0 = bias[og * 16 + 2 * j], bz1 = bias[og * 16 + 2 * j + 1];
        op[(size_t)(2 * j + 0) * 65536] = a.x + bz0;
        op[(size_t)(2 * j + 1) * 65536] = a.y + bz1;
        op[(size_t)(2 * j + 0) * 65536 + 8 * 256] = b.x + bz0;
        op[(size_t)(2 * j + 1) * 65536 + 8 * 256] = b.y + bz1;
    }
}

// ---------------- 3x3 stride-2 conv: 8px x 8oc / thread, float4 input loads ----
template <int IC, int OC, int ICC>
__global__ void __launch_bounds__(256, 2)
k_conv3s2(const float* __restrict__ in, const float* __restrict__ wt,
          const float* __restrict__ bias, float* __restrict__ out,
          int Hin, int Win, int Hout, int Wout) {
    const int OCB = 64;
    const int PIN = 33 * 36;
    extern __shared__ float smem[];
    float* s_w  = smem;                         // 2 * ICC*9*64
    float* s_in = s_w + 2 * ICC * 9 * OCB;      // 2 * ICC*PIN

    const int tid = threadIdx.x;
    const int wz = tid >> 5;
    const int lane = tid & 31;
    const int og = lane & 7;
    const int pg = lane >> 3;
    const int z = blockIdx.z;
    const int n = z / (OC / OCB);
    const int oc0 = (z % (OC / OCB)) * OCB;
    const int oy0 = blockIdx.y * 16, ox0 = blockIdx.x * 16;
    const int iy0 = 2 * oy0 - 1;
    const int ixa = 2 * ox0 - 4;

    const float* inp = in + (size_t)n * IC * Hin * Win;

    auto prefetch = [&](int st, int b) {
        int ic0 = st * ICC;
        float* bw = s_w + b * (ICC * 9 * OCB);
        float* bi = s_in + b * (ICC * PIN);
        for (int i = tid; i < ICC * 33 * 9; i += 256) {
            int icl = i / 297;
            int r2 = i % 297;
            int r = r2 / 9, c9 = r2 % 9;
            int iy = iy0 + r;
            int sx = ixa + 4 * c9;
            bool ok = ((unsigned)iy < (unsigned)Hin) && (sx >= 0);
            unsigned sz = ok ? 16u : 0u;
            const float* src = inp + (size_t)(ic0 + icl) * Hin * Win +
                               (ok ? iy * Win + sx : 0);
            cp16z(s2u(bi + icl * PIN + r * 36 + 4 * c9), src, sz);
        }
        const float* wsrc = wt + (size_t)ic0 * 9 * OC + oc0;
        for (int i = tid; i < ICC * 9 * (OCB / 4); i += 256) {
            int p = i / (OCB / 4), c = i % (OCB / 4);
            cp16(s2u(bw + p * OCB + 4 * c), wsrc + (size_t)p * OC + 4 * c);
        }
    };

    ull acc[2][4][4];
#pragma unroll
    for (int r = 0; r < 2; r++)
#pragma unroll
        for (int c = 0; c < 4; c++)
#pragma unroll
            for (int j = 0; j < 4; j++) acc[r][c][j] = 0ull;

    prefetch(0, 0);
    cp_commit();
    const int NS = IC / ICC;
    for (int s = 0; s < NS; s++) {
        if (s + 1 < NS) { prefetch(s + 1, (s + 1) & 1); cp_commit(); cp_wait<1>(); }
        else cp_wait<0>();
        __syncthreads();
        const float* bi = s_in + (s & 1) * (ICC * PIN);
        const float* bw = s_w + (s & 1) * (ICC * 9 * OCB);
#pragma unroll 1
        for (int icl = 0; icl < ICC; icl++) {
            const float* rb = bi + icl * PIN + 8 * pg;      // 16B-aligned
            const float* wb = bw + icl * 9 * OCB + og * 8;
#pragma unroll
            for (int ky = 0; ky < 3; ky++) {
                const float4* r0v = (const float4*)(rb + (4 * wz + ky) * 36);
                const float4* r1v = (const float4*)(rb + (4 * wz + ky + 2) * 36);
                float4 a0 = r0v[0], a1 = r0v[1], a2 = r0v[2];
                float4 c0 = r1v[0], c1 = r1v[1], c2 = r1v[2];
                ull u0[9], u1[9];
                u0[0] = pack2(a0.w); u0[1] = pack2(a1.x); u0[2] = pack2(a1.y);
                u0[3] = pack2(a1.z); u0[4] = pack2(a1.w); u0[5] = pack2(a2.x);
                u0[6] = pack2(a2.y); u0[7] = pack2(a2.z); u0[8] = pack2(a2.w);
                u1[0] = pack2(c0.w); u1[1] = pack2(c1.x); u1[2] = pack2(c1.y);
                u1[3] = pack2(c1.z); u1[4] = pack2(c1.w); u1[5] = pack2(c2.x);
                u1[6] = pack2(c2.y); u1[7] = pack2(c2.z); u1[8] = pack2(c2.w);
#pragma unroll
                for (int kx = 0; kx < 3; kx++) {
                    const ulonglong2* wp = (const ulonglong2*)(wb + (3 * ky + kx) * OCB);
                    ulonglong2 wa = wp[0], wb2 = wp[1];
#pragma unroll
                    for (int c = 0; c < 4; c++) {
                        ull v0 = u0[2 * c + kx];
                        ull v1 = u1[2 * c + kx];
                        fma2(acc[0][c][0], v0, wa.x);
                        fma2(acc[0][c][1], v0, wa.y);
                        fma2(acc[0][c][2], v0, wb2.x);
                        fma2(acc[0][c][3], v0, wb2.y);
                        fma2(acc[1][c][0], v1, wa.x);
                        fma2(acc[1][c][1], v1, wa.y);
                        fma2(acc[1][c][2], v1, wb2.x);
                        fma2(acc[1][c][3], v1, wb2.y);
                    }
                }
            }
        }
        __syncthreads();
    }

    const int oy = oy0 + 2 * wz;
    const int ox = ox0 + 4 * pg;
    const size_t cs = (size_t)Hout * Wout;
    float* obase = out + (size_t)(n * OC + oc0 + og * 8) * cs + (size_t)oy * Wout + ox;
#pragma unroll
    for (int r = 0; r < 2; r++)
#pragma unroll
        for (int j = 0; j < 4; j++) {
            float2 p0 = unpack2(acc[r][0][j]);
            float2 p1 = unpack2(acc[r][1][j]);
            float2 p2 = unpack2(acc[r][2][j]);
            float2 p3 = unpack2(acc[r][3][j]);
            float blo = bias[oc0 + og * 8 + 2 * j];
            float bhi = bias[oc0 + og * 8 + 2 * j + 1];
            float4 vlo = make_float4(p0.x + blo, p1.x + blo, p2.x + blo, p3.x + blo);
            float4 vhi = make_float4(p0.y + bhi, p1.y + bhi, p2.y + bhi, p3.y + bhi);
            *(float4*)(obase + (size_t)(2 * j) * cs + r * Wout) = vlo;
            *(float4*)(obase + (size_t)(2 * j + 1) * cs + r * Wout) = vhi;
        }
}

// ---------------- convT on pre-normalized input ----------------
__device__ __forceinline__ void tap8(ull* A, ull* B, ull va, ull vb,
                                     const ulonglong2* wp) {
    ulonglong2 w0 = wp[0], w1 = wp[1];
    fma2(A[0], va, w0.x); fma2(A[1], va, w0.y);
    fma2(A[2], va, w1.x); fma2(A[3], va, w1.y);
    fma2(B[0], vb, w0.x); fma2(B[1], vb, w0.y);
    fma2(B[2], vb, w1.x); fma2(B[3], vb, w1.y);
}

template <int IC, int OC, int ICC>
__global__ void __launch_bounds__(256, 2)
k_convT(const float* __restrict__ in, const float* __restrict__ wt,
        const float* __restrict__ bias, float* __restrict__ out,
        int Hin, int Win, int Hout, int Wout) {
    const int OCB = 8;
    extern __shared__ float smem[];
    float* s_w  = smem;
    float* s_in = s_w + 2 * ICC * 9 * OCB;

    const int tid = threadIdx.x;
    const int ty = tid >> 4;
    const int tx = tid & 15;
    const int z = blockIdx.z;
    const int n = z / (OC / OCB);
    const int oc0 = (z % (OC / OCB)) * OCB;
    const int oy0 = blockIdx.y * 32, ox0 = blockIdx.x * 64;
    const int iy0 = oy0 >> 1, ix0 = ox0 >> 1;

    const float* inp = in + (size_t)n * IC * Hin * Win;

    auto prefetch = [&](int st, int b) {
        int ic0 = st * ICC;
        float* bw = s_w + b * (ICC * 9 * OCB);
        float* bi = s_in + b * (ICC * 578);
        for (int i = tid; i < ICC * 561; i += 256) {
            int icl = i / 561, r2 = i % 561;
            int r = r2 / 33, c = r2 % 33;
            int iy = iy0 + r, ix = ix0 + c;
            bool ok = (iy < Hin) && (ix < Win);
            const float* src = inp + (size_t)(ic0 + icl) * Hin * Win + (ok ? iy * Win + ix : 0);
            cp4(s2u(bi + icl * 578 + r * 34 + c), src, ok);
        }
        const float* wsrc = wt + (size_t)ic0 * 9 * OC + oc0;
        for (int i = tid; i < ICC * 9 * (OCB / 4); i += 256) {
            int p = i / (OCB / 4), c = i % (OCB / 4);
            cp16(s2u(bw + p * OCB + 4 * c), wsrc + (size_t)p * OC + 4 * c);
        }
    };

    ull acc[2][4][4];
#pragma unroll
    for (int b2 = 0; b2 < 2; b2++)
#pragma unroll
        for (int c = 0; c < 4; c++)
#pragma unroll
            for (int j = 0; j < 4; j++) acc[b2][c][j] = 0ull;

    prefetch(0, 0);
    cp_commit();
    const int NS = IC / ICC;
    for (int s = 0; s < NS; s++) {
        if (s + 1 < NS) { prefetch(s + 1, (s + 1) & 1); cp_commit(); cp_wait<1>(); }
        else cp_wait<0>();
        __syncthreads();
        const float* bi = s_in + (s & 1) * (ICC * 578);
        const float* bw = s_w + (s & 1) * (ICC * 9 * OCB);
#pragma unroll 2
        for (int icl = 0; icl < ICC; icl++) {
            const float* sp = bi + icl * 578 + ty * 34 + tx;
            ull a00 = pack2(sp[0]);
            ull a01 = pack2(sp[1]);
            ull a10 = pack2(sp[34]);
            ull a11 = pack2(sp[35]);
            ull b00 = pack2(sp[16]);
            ull b01 = pack2(sp[17]);
            ull b10 = pack2(sp[50]);
            ull b11 = pack2(sp[51]);
            const ulonglong2* wp = (const ulonglong2*)(bw + icl * 9 * OCB);
            tap8(acc[0][3], acc[1][3], a11, b11, wp + 0);
            tap8(acc[0][2], acc[1][2], a10, b10, wp + 2);
            tap8(acc[0][3], acc[1][3], a10, b10, wp + 4);
            tap8(acc[0][1], acc[1][1], a01, b01, wp + 6);
            tap8(acc[0][0], acc[1][0], a00, b00, wp + 8);
            tap8(acc[0][1], acc[1][1], a00, b00, wp + 10);
            tap8(acc[0][3], acc[1][3], a01, b01, wp + 12);
            tap8(acc[0][2], acc[1][2], a00, b00, wp + 14);
            tap8(acc[0][3], acc[1][3], a00, b00, wp + 16);
        }
        __syncthreads();
    }

    const size_t cs = (size_t)Hout * Wout;
#pragma unroll
    for (int b2 = 0; b2 < 2; b2++) {
        int ye = oy0 + 2 * ty;
        int xe = ox0 + 2 * (tx + b2 * 16);
        bool y0v = ye < Hout, y1v = (ye + 1) < Hout;
        bool x0v = xe < Wout, x1v = (xe + 1) < Wout;
#pragma unroll
        for (int j = 0; j < 4; j++) {
            float bz0 = bias[oc0 + 2 * j], bz1 = bias[oc0 + 2 * j + 1];
            float* op0 = out + (size_t)(n * OC + oc0 + 2 * j) * cs;
            float* op1 = op0 + cs;
            float2 a;
            if (y0v && x0v) { a = unpack2(acc[b2][0][j]); op0[ye * Wout + xe] = a.x + bz0; op1[ye * Wout + xe] = a.y + bz1; }
            if (y0v && x1v) { a = unpack2(acc[b2][1][j]); op0[ye * Wout + xe + 1] = a.x + bz0; op1[ye * Wout + xe + 1] = a.y + bz1; }
            if (y1v && x0v) { a = unpack2(acc[b2][2][j]); op0[(ye + 1) * Wout + xe] = a.x + bz0; op1[(ye + 1) * Wout + xe] = a.y + bz1; }
            if (y1v && x1v) { a = unpack2(acc[b2][3][j]); op0[(ye + 1) * Wout + xe + 1] = a.x + bz0; op1[(ye + 1) * Wout + xe + 1] = a.y + bz1; }
        }
    }
}

// ---------------- layer 7: 7x7 conv 32->3 + tanh, 1row x 4col / thread ----------
__global__ void __launch_bounds__(256, 2)
k_conv7_l7(const float* __restrict__ act, const float* __restrict__ wt,
           const float* __restrict__ bias, const int* __restrict__ inst,
           float* __restrict__ gsum, float* __restrict__ gcnt) {
    extern __shared__ float smem[];
    float* s_w  = smem;                 // 6272
    float* s_in = s_w + 6272;           // 2 * 4*1520 (38 rows x pitch 40)
    __shared__ float ssb[96];
    __shared__ float scb[32];

    const int H = 249;
    const int tid = threadIdx.x;
    const int tx = tid & 7;             // col quad: cols 4tx..4tx+3
    const int ty = tid >> 3;            // row 0..31
    const int n = blockIdx.z;
    const int oy0 = blockIdx.y * 32, ox0 = blockIdx.x * 32;

    for (int i = tid; i < 6272; i += 256) s_w[i] = wt[i];
    if (tid < 96) ssb[tid] = 0.f;
    if (tid < 32) scb[tid] = 0.f;

    const float* ap = act + (size_t)n * 32 * 62001;
    auto prefetch = [&](int st, int b) {
        float* bi = s_in + b * (4 * 1520);
        int ic0 = st * 4;
        for (int i = tid; i < 4 * 1444; i += 256) {
            int icl = i / 1444, r2 = i % 1444;
            int r = r2 / 38, c = r2 % 38;
            int iy = oy0 + r - 3, ix = ox0 + c - 3;
            iy = iy < 0 ? -iy : (iy > 248 ? 496 - iy : iy);
            ix = ix < 0 ? -ix : (ix > 248 ? 496 - ix : ix);
            cp4(s2u(bi + icl * 1520 + r * 40 + c),
                ap + (size_t)(ic0 + icl) * 62001 + iy * 249 + ix, true);
        }
    };

    ull acc[4][2];
#pragma unroll
    for (int p = 0; p < 4; p++) { acc[p][0] = 0ull; acc[p][1] = 0ull; }

    prefetch(0, 0);
    cp_commit();
    for (int s = 0; s < 8; s++) {
        if (s < 7) { prefetch(s + 1, (s + 1) & 1); cp_commit(); cp_wait<1>(); }
        else cp_wait<0>();
        __syncthreads();
        const float* bi = s_in + (s & 1) * (4 * 1520);
#pragma unroll 1
        for (int icl = 0; icl < 4; icl++) {
            const float* wic = s_w + (s * 4 + icl) * 196;
            const float* si = bi + icl * 1520;
#pragma unroll 1
            for (int ky = 0; ky < 7; ky++) {
                const float4* rv = (const float4*)(si + (ty + ky) * 40 + 4 * tx);
                float4 q0 = rv[0], q1 = rv[1], q2 = rv[2];
                ull u[10];
                u[0] = pack2(q0.x); u[1] = pack2(q0.y); u[2] = pack2(q0.z);
                u[3] = pack2(q0.w); u[4] = pack2(q1.x); u[5] = pack2(q1.y);
                u[6] = pack2(q1.z); u[7] = pack2(q1.w); u[8] = pack2(q2.x);
                u[9] = pack2(q2.y);
                const ulonglong2* wp = (const ulonglong2*)(wic + ky * 28);
#pragma unroll
                for (int kx = 0; kx < 7; kx++) {
                    ulonglong2 w2 = wp[kx];
#pragma unroll
                    for (int d = 0; d < 4; d++) {
                        fma2(acc[d][0], u[kx + d], w2.x);
                        fma2(acc[d][1], u[kx + d], w2.y);
                    }
                }
            }
        }
        __syncthreads();
    }

    float b0 = bias[0], b1 = bias[1], b2 = bias[2];
    const int* ip = inst + (size_t)n * 62001;
    int oy = oy0 + ty;
    if (oy < H) {
#pragma unroll
        for (int d = 0; d < 4; d++) {
            int ox = ox0 + 4 * tx + d;
            if (ox < H) {
                float2 a0 = unpack2(acc[d][0]);
                float2 a1 = unpack2(acc[d][1]);
                float t0 = tanhf(a0.x + b0);
                float t1 = tanhf(a0.y + b1);
                float t2 = tanhf(a1.x + b2);
                int id = ip[oy * 249 + ox];
                atomicAdd(&ssb[id * 3 + 0], t0);
                atomicAdd(&ssb[id * 3 + 1], t1);
                atomicAdd(&ssb[id * 3 + 2], t2);
                atomicAdd(&scb[id], 1.f);
            }
        }
    }
    __syncthreads();
    if (tid < 96) atomicAdd(&gsum[tid], ssb[tid]);
    if (tid < 32) atomicAdd(&gcnt[tid], scb[tid]);
}

// ---------------- instance-norm stats + in-place normalize + ReLU ----------------
__global__ void k_instat(float* __restrict__ x, int HW) {
    int p = blockIdx.x;
    float* xp = x + (size_t)p * HW;
    float s0 = 0, s1 = 0, q0 = 0, q1 = 0;
    const bool vec = ((HW & 3) == 0);
    if (vec) {
        const float4* x4 = (const float4*)xp;
        int n4 = HW >> 2;
        for (int i = threadIdx.x; i < n4; i += 256) {
            float4 v = x4[i];
            s0 += v.x + v.y; q0 += v.x * v.x + v.y * v.y;
            s1 += v.z + v.w; q1 += v.z * v.z + v.w * v.w;
        }
    } else {
        int i = threadIdx.x;
        for (; i + 256 < HW; i += 512) {
            float a = xp[i], b = xp[i + 256];
            s0 += a; q0 += a * a;
            s1 += b; q1 += b * b;
        }
        if (i < HW) { float a = xp[i]; s0 += a; q0 += a * a; }
    }
    float s = s0 + s1, q = q0 + q1;
    for (int o = 16; o > 0; o >>= 1) {
        s += __shfl_down_sync(0xffffffffu, s, o);
        q += __shfl_down_sync(0xffffffffu, q, o);
    }
    __shared__ float sh[16];
    __shared__ float s_stat[2];
    int w = threadIdx.x >> 5, l = threadIdx.x & 31;
    if (l == 0) { sh[w] = s; sh[w + 8] = q; }
    __syncthreads();
    if (threadIdx.x == 0) {
        for (int k = 1; k < 8; k++) { s += sh[k]; q += sh[k + 8]; }
        float m = s / HW;
        float var = q / HW - m * m;
        float rs = rsqrtf(fmaxf(var, 0.f) + 1e-5f);
        s_stat[0] = rs;
        s_stat[1] = -m * rs;
    }
    __syncthreads();
    float rs = s_stat[0], sf = s_stat[1];
    if (vec) {
        float4* x4 = (float4*)xp;
        int n4 = HW >> 2;
        for (int i = threadIdx.x; i < n4; i += 256) {
            float4 v = x4[i];
            v.x = fmaxf(fmaf(v.x, rs, sf), 0.f);
            v.y = fmaxf(fmaf(v.y, rs, sf), 0.f);
            v.z = fmaxf(fmaf(v.z, rs, sf), 0.f);
            v.w = fmaxf(fmaf(v.w, rs, sf), 0.f);
            x4[i] = v;
        }
    } else {
        for (int i = threadIdx.x; i < HW; i += 256)
            xp[i] = fmaxf(fmaf(xp[i], rs, sf), 0.f);
    }
}

// ---------------- segment mean ----------------
__global__ void k_segzero(float* sum, float* cnt) {
    int t = threadIdx.x;
    if (t < 96) sum[t] = 0.f;
    if (t < 32) cnt[t] = 0.f;
}
__global__ void k_segbcast(const int* __restrict__ inst, const float* __restrict__ gsum,
                           const float* __restrict__ gcnt, float* __restrict__ out) {
    const int P = 62001, T = 8 * 3 * P;
    for (int i = blockIdx.x * blockDim.x + threadIdx.x; i < T; i += gridDim.x * blockDim.x) {
        int n = i / (3 * P), r = i % (3 * P);
        int c = r / P, p = r % P;
        int id = inst[n * P + p];
        out[i] = gsum[id * 3 + c] / fmaxf(gcnt[id], 1.f);
    }
}

// ---------------- launch ----------------
extern "C" void kernel_launch(void* const* d_in, const int* in_sizes, int n_in,
                              void* d_out, int out_size) {
    const float* x = (const float*)d_in[0];
    const int* inst = (const int*)d_in[1];
    const float* w[8];
    const float* b[8];
    for (int i = 0; i < 8; i++) {
        w[i] = (const float*)d_in[2 + 2 * i];
        b[i] = (const float*)d_in[3 + 2 * i];
    }
    float* out = (float*)d_out;

    float *A, *B;
    float *WT0, *WT1, *WT2, *WT3, *WT4, *WT5, *WT6, *WT7, *SS, *SN;
    cudaGetSymbolAddress((void**)&A, g_bufA);
    cudaGetSymbolAddress((void**)&B, g_bufB);
    cudaGetSymbolAddress((void**)&WT0, g_wt0);
    cudaGetSymbolAddress((void**)&WT1, g_wt1);
    cudaGetSymbolAddress((void**)&WT2, g_wt2);
    cudaGetSymbolAddress((void**)&WT3, g_wt3);
    cudaGetSymbolAddress((void**)&WT4, g_wt4);
    cudaGetSymbolAddress((void**)&WT5, g_wt5);
    cudaGetSymbolAddress((void**)&WT6, g_wt6);
    cudaGetSymbolAddress((void**)&WT7, g_wt7);
    cudaGetSymbolAddress((void**)&SS, g_segsum);
    cudaGetSymbolAddress((void**)&SN, g_segcnt);

    const int SM_C = (2*8*9*64 + 2*8*33*36) * 4;
    const int SM_T = (2*8*9*8 + 2*8*578) * 4;
    const int SM_L7 = (6272 + 2*4*1520) * 4;

    cudaFuncSetAttribute(k_conv3s2<32, 64, 8>,  cudaFuncAttributeMaxDynamicSharedMemorySize, SM_C);
    cudaFuncSetAttribute(k_conv3s2<64, 128, 8>, cudaFuncAttributeMaxDynamicSharedMemorySize, SM_C);
    cudaFuncSetAttribute(k_conv3s2<128, 256, 8>,cudaFuncAttributeMaxDynamicSharedMemorySize, SM_C);
    cudaFuncSetAttribute(k_convT<256, 128, 8>,  cudaFuncAttributeMaxDynamicSharedMemorySize, SM_T);
    cudaFuncSetAttribute(k_convT<128, 64, 8>,   cudaFuncAttributeMaxDynamicSharedMemorySize, SM_T);
    cudaFuncSetAttribute(k_convT<64, 32, 8>,    cudaFuncAttributeMaxDynamicSharedMemorySize, SM_T);
    cudaFuncSetAttribute(k_conv7_l7,            cudaFuncAttributeMaxDynamicSharedMemorySize, SM_L7);

    // weight prep
    k_prep<<<dim3(1152, 8), 256>>>(w[0], w[1], w[2], w[3], w[4], w[5], w[6], w[7],
                                   WT0, WT1, WT2, WT3, WT4, WT5, WT6, WT7);
    // layer 0
    k_conv7_l0<<<dim3(16, 16, 8), 256>>>(x, WT0, b[0], A);
    k_instat<<<8 * 32, 256>>>(A, 65536);
    // layers 1-3
    k_conv3s2<32, 64, 8><<<dim3(8, 8, 8), 256, SM_C>>>(A, WT1, b[1], B, 256, 256, 128, 128);
    k_instat<<<8 * 64, 256>>>(B, 16384);
    k_conv3s2<64, 128, 8><<<dim3(4, 4, 16), 256, SM_C>>>(B, WT2, b[2], A, 128, 128, 64, 64);
    k_instat<<<8 * 128, 256>>>(A, 4096);
    k_conv3s2<128, 256, 8><<<dim3(2, 2, 32), 256, SM_C>>>(A, WT3, b[3], B, 64, 64, 32, 32);
    k_instat<<<8 * 256, 256>>>(B, 1024);
    // layers 4-6 (transposed conv)
    k_convT<256, 128, 8><<<dim3(1, 2, 128), 256, SM_T>>>(B, WT4, b[4], A, 32, 32, 63, 63);
    k_instat<<<8 * 128, 256>>>(A, 3969);
    k_convT<128, 64, 8><<<dim3(2, 4, 64), 256, SM_T>>>(A, WT5, b[5], B, 63, 63, 125, 125);
    k_instat<<<8 * 64, 256>>>(B, 15625);
    k_convT<64, 32, 8><<<dim3(4, 8, 32), 256, SM_T>>>(B, WT6, b[6], A, 125, 125, 249, 249);
    k_instat<<<8 * 32, 256>>>(A, 62001);
    // segment bins zero, then layer 7 with fused segment accumulation
    k_segzero<<<1, 128>>>(SS, SN);
    k_conv7_l7<<<dim3(8, 8, 8), 256, SM_L7>>>(A, WT7, b[7], inst, SS, SN);
    // broadcast means
    k_segbcast<<<2048, 256>>>(inst, SS, SN, out);
}

// round 13
// speedup vs baseline: 2.6208x; 1.0840x over previous
#include <cuda_runtime.h>
#include <math.h>

// ---------------- static scratch ----------------
__device__ __align__(16) float g_bufA[16777216];
__device__ __align__(16) float g_bufB[8388608];
__device__ __align__(16) float g_wt0[3*49*32];
__device__ __align__(16) float g_wt1[32*9*64];
__device__ __align__(16) float g_wt2[64*9*128];
__device__ __align__(16) float g_wt3[128*9*256];
__device__ __align__(16) float g_wt4[256*9*128];
__device__ __align__(16) float g_wt5[128*9*64];
__device__ __align__(16) float g_wt6[64*9*32];
__device__ __align__(16) float g_wt7[32*49*4];
__device__ float g_segsum[96];
__device__ float g_segcnt[32];

typedef unsigned long long ull;

// ---------------- f32x2 packed helpers ----------------
__device__ __forceinline__ ull pack2(float v) {
    ull r;
    asm("mov.b64 %0, {%1, %1};" : "=l"(r) : "f"(v));
    return r;
}
__device__ __forceinline__ void fma2(ull& d, ull a, ull b) {
    asm("fma.rn.f32x2 %0, %1, %2, %0;" : "+l"(d) : "l"(a), "l"(b));
}
__device__ __forceinline__ float2 unpack2(ull v) {
    float2 f;
    asm("mov.b64 {%0, %1}, %2;" : "=f"(f.x), "=f"(f.y) : "l"(v));
    return f;
}

// ---------------- cp.async helpers ----------------
__device__ __forceinline__ unsigned s2u(const void* p) {
    return (unsigned)__cvta_generic_to_shared(p);
}
__device__ __forceinline__ void cp4(unsigned dst, const float* src, bool pred) {
    asm volatile("cp.async.ca.shared.global [%0], [%1], 4, %2;" ::
                 "r"(dst), "l"(src), "r"(pred ? 4u : 0u));
}
__device__ __forceinline__ void cp16(unsigned dst, const float* src) {
    asm volatile("cp.async.ca.shared.global [%0], [%1], 16;" ::
                 "r"(dst), "l"(src));
}
__device__ __forceinline__ void cp16z(unsigned dst, const float* src, unsigned sz) {
    asm volatile("cp.async.ca.shared.global [%0], [%1], 16, %2;" ::
                 "r"(dst), "l"(src), "r"(sz));
}
__device__ __forceinline__ void cp_commit() {
    asm volatile("cp.async.commit_group;" ::: "memory");
}
template <int N>
__device__ __forceinline__ void cp_wait() {
    asm volatile("cp.async.wait_group %0;" :: "n"(N) : "memory");
}

// ---------------- fused weight prep ----------------
__global__ void k_prep(const float* __restrict__ w0, const float* __restrict__ w1,
                       const float* __restrict__ w2, const float* __restrict__ w3,
                       const float* __restrict__ w4, const float* __restrict__ w5,
                       const float* __restrict__ w6, const float* __restrict__ w7,
                       float* o0, float* o1, float* o2, float* o3,
                       float* o4, float* o5, float* o6, float* o7) {
    int idx = blockIdx.x * 256 + threadIdx.x;
    switch (blockIdx.y) {
    case 0: if (idx < 32*3*49)   { int o=idx/147,  r=idx%147,  i=r/49, k=r%49; o0[(i*49+k)*32+o]=w0[idx]; } break;
    case 1: if (idx < 64*32*9)   { int o=idx/288,  r=idx%288,  i=r/9,  k=r%9;  o1[(i*9+k)*64+o]=w1[idx]; } break;
    case 2: if (idx < 128*64*9)  { int o=idx/576,  r=idx%576,  i=r/9,  k=r%9;  o2[(i*9+k)*128+o]=w2[idx]; } break;
    case 3: if (idx < 256*128*9) { int o=idx/1152, r=idx%1152, i=r/9,  k=r%9;  o3[(i*9+k)*256+o]=w3[idx]; } break;
    case 4: if (idx < 256*128*9) { int i=idx/1152, r=idx%1152, o=r/9,  k=r%9;  o4[(i*9+k)*128+o]=w4[idx]; } break;
    case 5: if (idx < 128*64*9)  { int i=idx/576,  r=idx%576,  o=r/9,  k=r%9;  o5[(i*9+k)*64+o]=w5[idx]; } break;
    case 6: if (idx < 64*32*9)   { int i=idx/288,  r=idx%288,  o=r/9,  k=r%9;  o6[(i*9+k)*32+o]=w6[idx]; } break;
    case 7: if (idx < 32*49*4)   { int p=idx>>2, o=idx&3; int i=p/49, k=p%49;
                                   o7[idx] = (o < 3) ? w7[(o*32+i)*49+k] : 0.f; } break;
    }
}

// ---------------- layer 0: reflect-pad 7x7 conv, 3->32, 2px x 16oc / thread ----
__global__ void __launch_bounds__(256)
k_conv7_l0(const float* __restrict__ x, const float* __restrict__ wt,
           const float* __restrict__ bias, float* __restrict__ out) {
    __shared__ __align__(16) float s_w[3 * 49 * 32];
    __shared__ float s_in[3 * 484];
    const int tid = threadIdx.x;
    const int og = tid >> 7;
    const int rem = tid & 127;
    const int ty = rem >> 4;
    const int tx = rem & 15;
    const int n = blockIdx.z;
    const int oy0 = blockIdx.y * 16, ox0 = blockIdx.x * 16;

    for (int i = tid; i < 3 * 49 * 32; i += 256) s_w[i] = wt[i];
    const float* xp = x + (size_t)n * 3 * 65536;
    for (int i = tid; i < 3 * 484; i += 256) {
        int ic = i / 484, rr = (i % 484) / 22, cc = i % 22;
        int iy = oy0 + rr - 3, ix = ox0 + cc - 3;
        iy = iy < 0 ? -iy : (iy > 255 ? 510 - iy : iy);
        ix = ix < 0 ? -ix : (ix > 255 ? 510 - ix : ix);
        s_in[i] = xp[ic * 65536 + iy * 256 + ix];
    }
    __syncthreads();

    ull acc0[8], acc1[8];
#pragma unroll
    for (int j = 0; j < 8; j++) { acc0[j] = 0ull; acc1[j] = 0ull; }

    for (int ic = 0; ic < 3; ic++)
#pragma unroll 1
        for (int ky = 0; ky < 7; ky++)
#pragma unroll
            for (int kx = 0; kx < 7; kx++) {
                ull v0 = pack2(s_in[ic * 484 + (ty + ky) * 22 + tx + kx]);
                ull v1 = pack2(s_in[ic * 484 + (ty + 8 + ky) * 22 + tx + kx]);
                const ulonglong2* wp =
                    (const ulonglong2*)(s_w + ((ic * 7 + ky) * 7 + kx) * 32 + og * 16);
#pragma unroll
                for (int q = 0; q < 4; q++) {
                    ulonglong2 w2 = wp[q];
                    fma2(acc0[2 * q + 0], v0, w2.x);
                    fma2(acc0[2 * q + 1], v0, w2.y);
                    fma2(acc1[2 * q + 0], v1, w2.x);
                    fma2(acc1[2 * q + 1], v1, w2.y);
                }
            }
    int oy = oy0 + ty, ox = ox0 + tx;
    float* op = out + (size_t)n * 32 * 65536 + (size_t)(og * 16) * 65536 + oy * 256 + ox;
#pragma unroll
    for (int j = 0; j < 8; j++) {
        float2 a = unpack2(acc0[j]);
        float2 b = unpack2(acc1[j]);
        float bz0 = bias[og * 16 + 2 * j], bz1 = bias[og * 16 + 2 * j + 1];
        op[(size_t)(2 * j + 0) * 65536] = a.x + bz0;
        op[(size_t)(2 * j + 1) * 65536] = a.y + bz1;
        op[(size_t)(2 * j + 0) * 65536 + 8 * 256] = b.x + bz0;
        op[(size_t)(2 * j + 1) * 65536 + 8 * 256] = b.y + bz1;
    }
}

// ---------------- 3x3 stride-2 conv: 8px x 8oc / thread, float4 input loads ----
template <int IC, int OC, int ICC>
__global__ void __launch_bounds__(256, 2)
k_conv3s2(const float* __restrict__ in, const float* __restrict__ wt,
          const float* __restrict__ bias, float* __restrict__ out,
          int Hin, int Win, int Hout, int Wout) {
    const int OCB = 64;
    const int PIN = 33 * 36;
    extern __shared__ float smem[];
    float* s_w  = smem;
    float* s_in = s_w + 2 * ICC * 9 * OCB;

    const int tid = threadIdx.x;
    const int wz = tid >> 5;
    const int lane = tid & 31;
    const int og = lane & 7;
    const int pg = lane >> 3;
    const int z = blockIdx.z;
    const int n = z / (OC / OCB);
    const int oc0 = (z % (OC / OCB)) * OCB;
    const int oy0 = blockIdx.y * 16, ox0 = blockIdx.x * 16;
    const int iy0 = 2 * oy0 - 1;
    const int ixa = 2 * ox0 - 4;

    const float* inp = in + (size_t)n * IC * Hin * Win;

    auto prefetch = [&](int st, int b) {
        int ic0 = st * ICC;
        float* bw = s_w + b * (ICC * 9 * OCB);
        float* bi = s_in + b * (ICC * PIN);
        for (int i = tid; i < ICC * 33 * 9; i += 256) {
            int icl = i / 297;
            int r2 = i % 297;
            int r = r2 / 9, c9 = r2 % 9;
            int iy = iy0 + r;
            int sx = ixa + 4 * c9;
            bool ok = ((unsigned)iy < (unsigned)Hin) && (sx >= 0);
            unsigned sz = ok ? 16u : 0u;
            const float* src = inp + (size_t)(ic0 + icl) * Hin * Win +
                               (ok ? iy * Win + sx : 0);
            cp16z(s2u(bi + icl * PIN + r * 36 + 4 * c9), src, sz);
        }
        const float* wsrc = wt + (size_t)ic0 * 9 * OC + oc0;
        for (int i = tid; i < ICC * 9 * (OCB / 4); i += 256) {
            int p = i / (OCB / 4), c = i % (OCB / 4);
            cp16(s2u(bw + p * OCB + 4 * c), wsrc + (size_t)p * OC + 4 * c);
        }
    };

    ull acc[2][4][4];
#pragma unroll
    for (int r = 0; r < 2; r++)
#pragma unroll
        for (int c = 0; c < 4; c++)
#pragma unroll
            for (int j = 0; j < 4; j++) acc[r][c][j] = 0ull;

    prefetch(0, 0);
    cp_commit();
    const int NS = IC / ICC;
    for (int s = 0; s < NS; s++) {
        if (s + 1 < NS) { prefetch(s + 1, (s + 1) & 1); cp_commit(); cp_wait<1>(); }
        else cp_wait<0>();
        __syncthreads();
        const float* bi = s_in + (s & 1) * (ICC * PIN);
        const float* bw = s_w + (s & 1) * (ICC * 9 * OCB);
#pragma unroll 1
        for (int icl = 0; icl < ICC; icl++) {
            const float* rb = bi + icl * PIN + 8 * pg;
            const float* wb = bw + icl * 9 * OCB + og * 8;
#pragma unroll
            for (int ky = 0; ky < 3; ky++) {
                const float4* r0v = (const float4*)(rb + (4 * wz + ky) * 36);
                const float4* r1v = (const float4*)(rb + (4 * wz + ky + 2) * 36);
                float4 a0 = r0v[0], a1 = r0v[1], a2 = r0v[2];
                float4 c0 = r1v[0], c1 = r1v[1], c2 = r1v[2];
                ull u0[9], u1[9];
                u0[0] = pack2(a0.w); u0[1] = pack2(a1.x); u0[2] = pack2(a1.y);
                u0[3] = pack2(a1.z); u0[4] = pack2(a1.w); u0[5] = pack2(a2.x);
                u0[6] = pack2(a2.y); u0[7] = pack2(a2.z); u0[8] = pack2(a2.w);
                u1[0] = pack2(c0.w); u1[1] = pack2(c1.x); u1[2] = pack2(c1.y);
                u1[3] = pack2(c1.z); u1[4] = pack2(c1.w); u1[5] = pack2(c2.x);
                u1[6] = pack2(c2.y); u1[7] = pack2(c2.z); u1[8] = pack2(c2.w);
#pragma unroll
                for (int kx = 0; kx < 3; kx++) {
                    const ulonglong2* wp = (const ulonglong2*)(wb + (3 * ky + kx) * OCB);
                    ulonglong2 wa = wp[0], wb2 = wp[1];
#pragma unroll
                    for (int c = 0; c < 4; c++) {
                        ull v0 = u0[2 * c + kx];
                        ull v1 = u1[2 * c + kx];
                        fma2(acc[0][c][0], v0, wa.x);
                        fma2(acc[0][c][1], v0, wa.y);
                        fma2(acc[0][c][2], v0, wb2.x);
                        fma2(acc[0][c][3], v0, wb2.y);
                        fma2(acc[1][c][0], v1, wa.x);
                        fma2(acc[1][c][1], v1, wa.y);
                        fma2(acc[1][c][2], v1, wb2.x);
                        fma2(acc[1][c][3], v1, wb2.y);
                    }
                }
            }
        }
        __syncthreads();
    }

    const int oy = oy0 + 2 * wz;
    const int ox = ox0 + 4 * pg;
    const size_t cs = (size_t)Hout * Wout;
    float* obase = out + (size_t)(n * OC + oc0 + og * 8) * cs + (size_t)oy * Wout + ox;
#pragma unroll
    for (int r = 0; r < 2; r++)
#pragma unroll
        for (int j = 0; j < 4; j++) {
            float2 p0 = unpack2(acc[r][0][j]);
            float2 p1 = unpack2(acc[r][1][j]);
            float2 p2 = unpack2(acc[r][2][j]);
            float2 p3 = unpack2(acc[r][3][j]);
            float blo = bias[oc0 + og * 8 + 2 * j];
            float bhi = bias[oc0 + og * 8 + 2 * j + 1];
            float4 vlo = make_float4(p0.x + blo, p1.x + blo, p2.x + blo, p3.x + blo);
            float4 vhi = make_float4(p0.y + bhi, p1.y + bhi, p2.y + bhi, p3.y + bhi);
            *(float4*)(obase + (size_t)(2 * j) * cs + r * Wout) = vlo;
            *(float4*)(obase + (size_t)(2 * j + 1) * cs + r * Wout) = vhi;
        }
}

// ---------------- convT: pitched I/O, cp.async.16 staging ----------------
__device__ __forceinline__ void tap8(ull* A, ull* B, ull va, ull vb,
                                     const ulonglong2* wp) {
    ulonglong2 w0 = wp[0], w1 = wp[1];
    fma2(A[0], va, w0.x); fma2(A[1], va, w0.y);
    fma2(A[2], va, w1.x); fma2(A[3], va, w1.y);
    fma2(B[0], vb, w0.x); fma2(B[1], vb, w0.y);
    fma2(B[2], vb, w1.x); fma2(B[3], vb, w1.y);
}

template <int IC, int OC, int ICC>
__global__ void __launch_bounds__(256, 2)
k_convT(const float* __restrict__ in, const float* __restrict__ wt,
        const float* __restrict__ bias, float* __restrict__ out,
        int Hin, int Win, int pitchIn, int Hout, int Wout, int pitchOut) {
    const int OCB = 8;
    const int PIN = 17 * 36;    // 612, pitch 36 (16B aligned per row)
    extern __shared__ float smem[];
    float* s_w  = smem;                        // 2 * ICC*72
    float* s_in = s_w + 2 * ICC * 9 * OCB;     // 2 * ICC*612

    const int tid = threadIdx.x;
    const int ty = tid >> 4;
    const int tx = tid & 15;
    const int z = blockIdx.z;
    const int n = z / (OC / OCB);
    const int oc0 = (z % (OC / OCB)) * OCB;
    const int oy0 = blockIdx.y * 32, ox0 = blockIdx.x * 64;
    const int iy0 = oy0 >> 1, ix0 = ox0 >> 1;  // ix0 multiple of 32 -> aligned

    const float* inp = in + (size_t)n * IC * Hin * pitchIn;

    auto prefetch = [&](int st, int b) {
        int ic0 = st * ICC;
        float* bw = s_w + b * (ICC * 9 * OCB);
        float* bi = s_in + b * (ICC * PIN);
        for (int i = tid; i < ICC * 153; i += 256) {   // 17 rows * 9 chunks
            int icl = i / 153, r2 = i % 153;
            int r = r2 / 9, c9 = r2 % 9;
            int iy = iy0 + r;
            int sx = ix0 + 4 * c9;
            int vb = (iy < Hin) ? (Win - sx) : 0;
            unsigned sz = vb >= 4 ? 16u : (vb > 0 ? (unsigned)(4 * vb) : 0u);
            const float* src = inp + (size_t)(ic0 + icl) * Hin * pitchIn +
                               (sz ? iy * pitchIn + sx : 0);
            cp16z(s2u(bi + icl * PIN + r * 36 + 4 * c9), src, sz);
        }
        const float* wsrc = wt + (size_t)ic0 * 9 * OC + oc0;
        for (int i = tid; i < ICC * 9 * 2; i += 256) {
            int p = i >> 1, c = i & 1;
            cp16(s2u(bw + p * OCB + 4 * c), wsrc + (size_t)p * OC + 4 * c);
        }
    };

    ull acc[2][4][4];
#pragma unroll
    for (int b2 = 0; b2 < 2; b2++)
#pragma unroll
        for (int c = 0; c < 4; c++)
#pragma unroll
            for (int j = 0; j < 4; j++) acc[b2][c][j] = 0ull;

    prefetch(0, 0);
    cp_commit();
    const int NS = IC / ICC;
    for (int s = 0; s < NS; s++) {
        if (s + 1 < NS) { prefetch(s + 1, (s + 1) & 1); cp_commit(); cp_wait<1>(); }
        else cp_wait<0>();
        __syncthreads();
        const float* bi = s_in + (s & 1) * (ICC * PIN);
        const float* bw = s_w + (s & 1) * (ICC * 9 * OCB);
#pragma unroll 2
        for (int icl = 0; icl < ICC; icl++) {
            const float* sp = bi + icl * PIN + ty * 36 + tx;
            ull a00 = pack2(sp[0]);
            ull a01 = pack2(sp[1]);
            ull a10 = pack2(sp[36]);
            ull a11 = pack2(sp[37]);
            ull b00 = pack2(sp[16]);
            ull b01 = pack2(sp[17]);
            ull b10 = pack2(sp[52]);
            ull b11 = pack2(sp[53]);
            const ulonglong2* wp = (const ulonglong2*)(bw + icl * 9 * OCB);
            tap8(acc[0][3], acc[1][3], a11, b11, wp + 0);
            tap8(acc[0][2], acc[1][2], a10, b10, wp + 2);
            tap8(acc[0][3], acc[1][3], a10, b10, wp + 4);
            tap8(acc[0][1], acc[1][1], a01, b01, wp + 6);
            tap8(acc[0][0], acc[1][0], a00, b00, wp + 8);
            tap8(acc[0][1], acc[1][1], a00, b00, wp + 10);
            tap8(acc[0][3], acc[1][3], a01, b01, wp + 12);
            tap8(acc[0][2], acc[1][2], a00, b00, wp + 14);
            tap8(acc[0][3], acc[1][3], a00, b00, wp + 16);
        }
        __syncthreads();
    }

    const size_t cs = (size_t)Hout * pitchOut;
#pragma unroll
    for (int b2 = 0; b2 < 2; b2++) {
        int ye = oy0 + 2 * ty;
        int xe = ox0 + 2 * (tx + b2 * 16);
        bool y0v = ye < Hout, y1v = (ye + 1) < Hout;
        bool x0v = xe < Wout, x1v = (xe + 1) < Wout;
#pragma unroll
        for (int j = 0; j < 4; j++) {
            float bz0 = bias[oc0 + 2 * j], bz1 = bias[oc0 + 2 * j + 1];
            float* op0 = out + (size_t)(n * OC + oc0 + 2 * j) * cs;
            float* op1 = op0 + cs;
            float2 a;
            if (y0v && x0v) { a = unpack2(acc[b2][0][j]); op0[ye * pitchOut + xe] = a.x + bz0; op1[ye * pitchOut + xe] = a.y + bz1; }
            if (y0v && x1v) { a = unpack2(acc[b2][1][j]); op0[ye * pitchOut + xe + 1] = a.x + bz0; op1[ye * pitchOut + xe + 1] = a.y + bz1; }
            if (y1v && x0v) { a = unpack2(acc[b2][2][j]); op0[(ye + 1) * pitchOut + xe] = a.x + bz0; op1[(ye + 1) * pitchOut + xe] = a.y + bz1; }
            if (y1v && x1v) { a = unpack2(acc[b2][3][j]); op0[(ye + 1) * pitchOut + xe + 1] = a.x + bz0; op1[(ye + 1) * pitchOut + xe + 1] = a.y + bz1; }
        }
    }
}

// ---------------- layer 7: 7x7 conv 32->3 + tanh, 1row x 4col / thread ----------
// input: pitched plane 249 rows x pitch 256 (63744 floats)
__global__ void __launch_bounds__(256, 2)
k_conv7_l7(const float* __restrict__ act, const float* __restrict__ wt,
           const float* __restrict__ bias, const int* __restrict__ inst,
           float* __restrict__ gsum, float* __restrict__ gcnt) {
    extern __shared__ float smem[];
    float* s_w  = smem;                 // 6272
    float* s_in = s_w + 6272;           // 2 * 4*1520 (38 rows x pitch 40)
    __shared__ float ssb[96];
    __shared__ float scb[32];

    const int H = 249;
    const int PLANE = 63744;            // 249*256
    const int tid = threadIdx.x;
    const int tx = tid & 7;
    const int ty = tid >> 3;
    const int n = blockIdx.z;
    const int oy0 = blockIdx.y * 32, ox0 = blockIdx.x * 32;

    for (int i = tid; i < 6272; i += 256) s_w[i] = wt[i];
    if (tid < 96) ssb[tid] = 0.f;
    if (tid < 32) scb[tid] = 0.f;

    const float* ap = act + (size_t)n * 32 * PLANE;
    auto prefetch = [&](int st, int b) {
        float* bi = s_in + b * (4 * 1520);
        int ic0 = st * 4;
        for (int i = tid; i < 4 * 1444; i += 256) {
            int icl = i / 1444, r2 = i % 1444;
            int r = r2 / 38, c = r2 % 38;
            int iy = oy0 + r - 3, ix = ox0 + c - 3;
            iy = iy < 0 ? -iy : (iy > 248 ? 496 - iy : iy);
            ix = ix < 0 ? -ix : (ix > 248 ? 496 - ix : ix);
            cp4(s2u(bi + icl * 1520 + r * 40 + c),
                ap + (size_t)(ic0 + icl) * PLANE + iy * 256 + ix, true);
        }
    };

    ull acc[4][2];
#pragma unroll
    for (int p = 0; p < 4; p++) { acc[p][0] = 0ull; acc[p][1] = 0ull; }

    prefetch(0, 0);
    cp_commit();
    for (int s = 0; s < 8; s++) {
        if (s < 7) { prefetch(s + 1, (s + 1) & 1); cp_commit(); cp_wait<1>(); }
        else cp_wait<0>();
        __syncthreads();
        const float* bi = s_in + (s & 1) * (4 * 1520);
#pragma unroll 1
        for (int icl = 0; icl < 4; icl++) {
            const float* wic = s_w + (s * 4 + icl) * 196;
            const float* si = bi + icl * 1520;
#pragma unroll 1
            for (int ky = 0; ky < 7; ky++) {
                const float4* rv = (const float4*)(si + (ty + ky) * 40 + 4 * tx);
                float4 q0 = rv[0], q1 = rv[1], q2 = rv[2];
                ull u[10];
                u[0] = pack2(q0.x); u[1] = pack2(q0.y); u[2] = pack2(q0.z);
                u[3] = pack2(q0.w); u[4] = pack2(q1.x); u[5] = pack2(q1.y);
                u[6] = pack2(q1.z); u[7] = pack2(q1.w); u[8] = pack2(q2.x);
                u[9] = pack2(q2.y);
                const ulonglong2* wp = (const ulonglong2*)(wic + ky * 28);
#pragma unroll
                for (int kx = 0; kx < 7; kx++) {
                    ulonglong2 w2 = wp[kx];
#pragma unroll
                    for (int d = 0; d < 4; d++) {
                        fma2(acc[d][0], u[kx + d], w2.x);
                        fma2(acc[d][1], u[kx + d], w2.y);
                    }
                }
            }
        }
        __syncthreads();
    }

    float b0 = bias[0], b1 = bias[1], b2 = bias[2];
    const int* ip = inst + (size_t)n * 62001;
    int oy = oy0 + ty;
    if (oy < H) {
#pragma unroll
        for (int d = 0; d < 4; d++) {
            int ox = ox0 + 4 * tx + d;
            if (ox < H) {
                float2 a0 = unpack2(acc[d][0]);
                float2 a1 = unpack2(acc[d][1]);
                float t0 = tanhf(a0.x + b0);
                float t1 = tanhf(a0.y + b1);
                float t2 = tanhf(a1.x + b2);
                int id = ip[oy * 249 + ox];
                atomicAdd(&ssb[id * 3 + 0], t0);
                atomicAdd(&ssb[id * 3 + 1], t1);
                atomicAdd(&ssb[id * 3 + 2], t2);
                atomicAdd(&scb[id], 1.f);
            }
        }
    }
    __syncthreads();
    if (tid < 96) atomicAdd(&gsum[tid], ssb[tid]);
    if (tid < 32) atomicAdd(&gcnt[tid], scb[tid]);
}

// ---------------- instance-norm (contiguous planes) ----------------
__global__ void k_instat(float* __restrict__ x, int HW) {
    int p = blockIdx.x;
    float* xp = x + (size_t)p * HW;
    float s0 = 0, s1 = 0, q0 = 0, q1 = 0;
    const float4* x4 = (const float4*)xp;
    int n4 = HW >> 2;
    for (int i = threadIdx.x; i < n4; i += 256) {
        float4 v = x4[i];
        s0 += v.x + v.y; q0 += v.x * v.x + v.y * v.y;
        s1 += v.z + v.w; q1 += v.z * v.z + v.w * v.w;
    }
    float s = s0 + s1, q = q0 + q1;
    for (int o = 16; o > 0; o >>= 1) {
        s += __shfl_down_sync(0xffffffffu, s, o);
        q += __shfl_down_sync(0xffffffffu, q, o);
    }
    __shared__ float sh[16];
    __shared__ float s_stat[2];
    int w = threadIdx.x >> 5, l = threadIdx.x & 31;
    if (l == 0) { sh[w] = s; sh[w + 8] = q; }
    __syncthreads();
    if (threadIdx.x == 0) {
        for (int k = 1; k < 8; k++) { s += sh[k]; q += sh[k + 8]; }
        float m = s / HW;
        float var = q / HW - m * m;
        float rs = rsqrtf(fmaxf(var, 0.f) + 1e-5f);
        s_stat[0] = rs;
        s_stat[1] = -m * rs;
    }
    __syncthreads();
    float rs = s_stat[0], sf = s_stat[1];
    float4* y4 = (float4*)xp;
    for (int i = threadIdx.x; i < n4; i += 256) {
        float4 v = y4[i];
        v.x = fmaxf(fmaf(v.x, rs, sf), 0.f);
        v.y = fmaxf(fmaf(v.y, rs, sf), 0.f);
        v.z = fmaxf(fmaf(v.z, rs, sf), 0.f);
        v.w = fmaxf(fmaf(v.w, rs, sf), 0.f);
        y4[i] = v;
    }
}

// ---------------- instance-norm (pitched planes, pitch = pow2) ----------------
__global__ void k_instat_p(float* __restrict__ x, int H, int W, int pitch) {
    int p = blockIdx.x;
    float* xp = x + (size_t)p * H * pitch;
    const int total = H * pitch;
    const int mask = pitch - 1;
    float s = 0, q = 0;
    for (int i = threadIdx.x; i < total; i += 256) {
        if ((i & mask) < W) {
            float v = xp[i];
            s += v; q += v * v;
        }
    }
    for (int o = 16; o > 0; o >>= 1) {
        s += __shfl_down_sync(0xffffffffu, s, o);
        q += __shfl_down_sync(0xffffffffu, q, o);
    }
    __shared__ float sh[16];
    __shared__ float s_stat[2];
    int w = threadIdx.x >> 5, l = threadIdx.x & 31;
    if (l == 0) { sh[w] = s; sh[w + 8] = q; }
    __syncthreads();
    if (threadIdx.x == 0) {
        for (int k = 1; k < 8; k++) { s += sh[k]; q += sh[k + 8]; }
        float inv = 1.f / (float)(H * W);
        float m = s * inv;
        float var = q * inv - m * m;
        float rs = rsqrtf(fmaxf(var, 0.f) + 1e-5f);
        s_stat[0] = rs;
        s_stat[1] = -m * rs;
    }
    __syncthreads();
    float rs = s_stat[0], sf = s_stat[1];
    for (int i = threadIdx.x; i < total; i += 256) {
        bool ok = (i & mask) < W;
        float v = xp[i];
        xp[i] = ok ? fmaxf(fmaf(v, rs, sf), 0.f) : 0.f;
    }
}

// ---------------- segment mean ----------------
__global__ void k_segzero(float* sum, float* cnt) {
    int t = threadIdx.x;
    if (t < 96) sum[t] = 0.f;
    if (t < 32) cnt[t] = 0.f;
}
__global__ void k_segbcast(const int* __restrict__ inst, const float* __restrict__ gsum,
                           const float* __restrict__ gcnt, float* __restrict__ out) {
    const int P = 62001, T = 8 * 3 * P;
    for (int i = blockIdx.x * blockDim.x + threadIdx.x; i < T; i += gridDim.x * blockDim.x) {
        int n = i / (3 * P), r = i % (3 * P);
        int c = r / P, p = r % P;
        int id = inst[n * P + p];
        out[i] = gsum[id * 3 + c] / fmaxf(gcnt[id], 1.f);
    }
}

// ---------------- launch ----------------
extern "C" void kernel_launch(void* const* d_in, const int* in_sizes, int n_in,
                              void* d_out, int out_size) {
    const float* x = (const float*)d_in[0];
    const int* inst = (const int*)d_in[1];
    const float* w[8];
    const float* b[8];
    for (int i = 0; i < 8; i++) {
        w[i] = (const float*)d_in[2 + 2 * i];
        b[i] = (const float*)d_in[3 + 2 * i];
    }
    float* out = (float*)d_out;

    float *A, *B;
    float *WT0, *WT1, *WT2, *WT3, *WT4, *WT5, *WT6, *WT7, *SS, *SN;
    cudaGetSymbolAddress((void**)&A, g_bufA);
    cudaGetSymbolAddress((void**)&B, g_bufB);
    cudaGetSymbolAddress((void**)&WT0, g_wt0);
    cudaGetSymbolAddress((void**)&WT1, g_wt1);
    cudaGetSymbolAddress((void**)&WT2, g_wt2);
    cudaGetSymbolAddress((void**)&WT3, g_wt3);
    cudaGetSymbolAddress((void**)&WT4, g_wt4);
    cudaGetSymbolAddress((void**)&WT5, g_wt5);
    cudaGetSymbolAddress((void**)&WT6, g_wt6);
    cudaGetSymbolAddress((void**)&WT7, g_wt7);
    cudaGetSymbolAddress((void**)&SS, g_segsum);
    cudaGetSymbolAddress((void**)&SN, g_segcnt);

    const int SM_C = (2*8*9*64 + 2*8*33*36) * 4;
    const int SM_T = (2*8*9*8 + 2*8*17*36) * 4;
    const int SM_L7 = (6272 + 2*4*1520) * 4;

    cudaFuncSetAttribute(k_conv3s2<32, 64, 8>,  cudaFuncAttributeMaxDynamicSharedMemorySize, SM_C);
    cudaFuncSetAttribute(k_conv3s2<64, 128, 8>, cudaFuncAttributeMaxDynamicSharedMemorySize, SM_C);
    cudaFuncSetAttribute(k_conv3s2<128, 256, 8>,cudaFuncAttributeMaxDynamicSharedMemorySize, SM_C);
    cudaFuncSetAttribute(k_convT<256, 128, 8>,  cudaFuncAttributeMaxDynamicSharedMemorySize, SM_T);
    cudaFuncSetAttribute(k_convT<128, 64, 8>,   cudaFuncAttributeMaxDynamicSharedMemorySize, SM_T);
    cudaFuncSetAttribute(k_convT<64, 32, 8>,    cudaFuncAttributeMaxDynamicSharedMemorySize, SM_T);
    cudaFuncSetAttribute(k_conv7_l7,            cudaFuncAttributeMaxDynamicSharedMemorySize, SM_L7);

    // weight prep
    k_prep<<<dim3(1152, 8), 256>>>(w[0], w[1], w[2], w[3], w[4], w[5], w[6], w[7],
                                   WT0, WT1, WT2, WT3, WT4, WT5, WT6, WT7);
    // layer 0
    k_conv7_l0<<<dim3(16, 16, 8), 256>>>(x, WT0, b[0], A);
    k_instat<<<8 * 32, 256>>>(A, 65536);
    // layers 1-3 (contiguous planes)
    k_conv3s2<32, 64, 8><<<dim3(8, 8, 8), 256, SM_C>>>(A, WT1, b[1], B, 256, 256, 128, 128);
    k_instat<<<8 * 64, 256>>>(B, 16384);
    k_conv3s2<64, 128, 8><<<dim3(4, 4, 16), 256, SM_C>>>(B, WT2, b[2], A, 128, 128, 64, 64);
    k_instat<<<8 * 128, 256>>>(A, 4096);
    k_conv3s2<128, 256, 8><<<dim3(2, 2, 32), 256, SM_C>>>(A, WT3, b[3], B, 64, 64, 32, 32);
    k_instat<<<8 * 256, 256>>>(B, 1024);
    // layers 4-6 (transposed conv, pitched outputs)
    k_convT<256, 128, 8><<<dim3(1, 2, 128), 256, SM_T>>>(B, WT4, b[4], A,
                                                         32, 32, 32, 63, 63, 64);
    k_instat_p<<<8 * 128, 256>>>(A, 63, 63, 64);
    k_convT<128, 64, 8><<<dim3(2, 4, 64), 256, SM_T>>>(A, WT5, b[5], B,
                                                       63, 63, 64, 125, 125, 128);
    k_instat_p<<<8 * 64, 256>>>(B, 125, 125, 128);
    k_convT<64, 32, 8><<<dim3(4, 8, 32), 256, SM_T>>>(B, WT6, b[6], A,
                                                      125, 125, 128, 249, 249, 256);
    k_instat_p<<<8 * 32, 256>>>(A, 249, 249, 256);
    // segment bins zero, then layer 7 with fused segment accumulation
    k_segzero<<<1, 128>>>(SS, SN);
    k_conv7_l7<<<dim3(8, 8, 8), 256, SM_L7>>>(A, WT7, b[7], inst, SS, SN);
    // broadcast means
    k_segbcast<<<2048, 256>>>(inst, SS, SN, out);
}

// round 15
// speedup vs baseline: 2.6612x; 1.0154x over previous
#include <cuda_runtime.h>
#include <math.h>

// ---------------- static scratch ----------------
__device__ __align__(16) float g_bufA[16777216];
__device__ __align__(16) float g_bufB[8388608];
__device__ __align__(16) float g_wt0[3*49*32];
__device__ __align__(16) float g_wt1[32*9*64];
__device__ __align__(16) float g_wt2[64*9*128];
__device__ __align__(16) float g_wt3[128*9*256];
__device__ __align__(16) float g_wt4[256*9*128];
__device__ __align__(16) float g_wt5[128*9*64];
__device__ __align__(16) float g_wt6[64*9*32];
__device__ __align__(16) float g_wt7[32*49*4];
__device__ float g_segsum[96];
__device__ float g_segcnt[32];

typedef unsigned long long ull;

// ---------------- f32x2 packed helpers ----------------
__device__ __forceinline__ ull pack2(float v) {
    ull r;
    asm("mov.b64 %0, {%1, %1};" : "=l"(r) : "f"(v));
    return r;
}
__device__ __forceinline__ void fma2(ull& d, ull a, ull b) {
    asm("fma.rn.f32x2 %0, %1, %2, %0;" : "+l"(d) : "l"(a), "l"(b));
}
__device__ __forceinline__ float2 unpack2(ull v) {
    float2 f;
    asm("mov.b64 {%0, %1}, %2;" : "=f"(f.x), "=f"(f.y) : "l"(v));
    return f;
}

// ---------------- cp.async helpers ----------------
__device__ __forceinline__ unsigned s2u(const void* p) {
    return (unsigned)__cvta_generic_to_shared(p);
}
__device__ __forceinline__ void cp4(unsigned dst, const float* src, bool pred) {
    asm volatile("cp.async.ca.shared.global [%0], [%1], 4, %2;" ::
                 "r"(dst), "l"(src), "r"(pred ? 4u : 0u));
}
// 16B copies bypass L1 (.cg) — staged data is consumed from smem, never from L1
__device__ __forceinline__ void cp16(unsigned dst, const float* src) {
    asm volatile("cp.async.cg.shared.global [%0], [%1], 16;" ::
                 "r"(dst), "l"(src));
}
__device__ __forceinline__ void cp16z(unsigned dst, const float* src, unsigned sz) {
    asm volatile("cp.async.cg.shared.global [%0], [%1], 16, %2;" ::
                 "r"(dst), "l"(src), "r"(sz));
}
__device__ __forceinline__ void cp_commit() {
    asm volatile("cp.async.commit_group;" ::: "memory");
}
template <int N>
__device__ __forceinline__ void cp_wait() {
    asm volatile("cp.async.wait_group %0;" :: "n"(N) : "memory");
}

// ---------------- fused weight prep + segment-bin zero ----------------
__global__ void k_prep(const float* __restrict__ w0, const float* __restrict__ w1,
                       const float* __restrict__ w2, const float* __restrict__ w3,
                       const float* __restrict__ w4, const float* __restrict__ w5,
                       const float* __restrict__ w6, const float* __restrict__ w7,
                       float* o0, float* o1, float* o2, float* o3,
                       float* o4, float* o5, float* o6, float* o7,
                       float* segsum, float* segcnt) {
    int idx = blockIdx.x * 256 + threadIdx.x;
    switch (blockIdx.y) {
    case 0: if (idx < 32*3*49)   { int o=idx/147,  r=idx%147,  i=r/49, k=r%49; o0[(i*49+k)*32+o]=w0[idx]; } break;
    case 1: if (idx < 64*32*9)   { int o=idx/288,  r=idx%288,  i=r/9,  k=r%9;  o1[(i*9+k)*64+o]=w1[idx]; } break;
    case 2: if (idx < 128*64*9)  { int o=idx/576,  r=idx%576,  i=r/9,  k=r%9;  o2[(i*9+k)*128+o]=w2[idx]; } break;
    case 3: if (idx < 256*128*9) { int o=idx/1152, r=idx%1152, i=r/9,  k=r%9;  o3[(i*9+k)*256+o]=w3[idx]; } break;
    case 4: if (idx < 256*128*9) { int i=idx/1152, r=idx%1152, o=r/9,  k=r%9;  o4[(i*9+k)*128+o]=w4[idx]; } break;
    case 5: if (idx < 128*64*9)  { int i=idx/576,  r=idx%576,  o=r/9,  k=r%9;  o5[(i*9+k)*64+o]=w5[idx]; } break;
    case 6: if (idx < 64*32*9)   { int i=idx/288,  r=idx%288,  o=r/9,  k=r%9;  o6[(i*9+k)*32+o]=w6[idx]; } break;
    case 7: if (idx < 32*49*4)   { int p=idx>>2, o=idx&3; int i=p/49, k=p%49;
                                   o7[idx] = (o < 3) ? w7[(o*32+i)*49+k] : 0.f; } break;
    case 8: if (idx < 96) segsum[idx] = 0.f;
            if (idx < 32) segcnt[idx] = 0.f;
            break;
    }
}

// ---------------- layer 0: reflect-pad 7x7 conv, 3->32, 2px x 16oc / thread ----
__global__ void __launch_bounds__(256)
k_conv7_l0(const float* __restrict__ x, const float* __restrict__ wt,
           const float* __restrict__ bias, float* __restrict__ out) {
    __shared__ __align__(16) float s_w[3 * 49 * 32];
    __shared__ float s_in[3 * 484];
    const int tid = threadIdx.x;
    const int og = tid >> 7;
    const int rem = tid & 127;
    const int ty = rem >> 4;
    const int tx = rem & 15;
    const int n = blockIdx.z;
    const int oy0 = blockIdx.y * 16, ox0 = blockIdx.x * 16;

    for (int i = tid; i < 3 * 49 * 32; i += 256) s_w[i] = wt[i];
    const float* xp = x + (size_t)n * 3 * 65536;
    for (int i = tid; i < 3 * 484; i += 256) {
        int ic = i / 484, rr = (i % 484) / 22, cc = i % 22;
        int iy = oy0 + rr - 3, ix = ox0 + cc - 3;
        iy = iy < 0 ? -iy : (iy > 255 ? 510 - iy : iy);
        ix = ix < 0 ? -ix : (ix > 255 ? 510 - ix : ix);
        s_in[i] = xp[ic * 65536 + iy * 256 + ix];
    }
    __syncthreads();

    ull acc0[8], acc1[8];
#pragma unroll
    for (int j = 0; j < 8; j++) { acc0[j] = 0ull; acc1[j] = 0ull; }

    for (int ic = 0; ic < 3; ic++)
#pragma unroll 1
        for (int ky = 0; ky < 7; ky++)
#pragma unroll
            for (int kx = 0; kx < 7; kx++) {
                ull v0 = pack2(s_in[ic * 484 + (ty + ky) * 22 + tx + kx]);
                ull v1 = pack2(s_in[ic * 484 + (ty + 8 + ky) * 22 + tx + kx]);
                const ulonglong2* wp =
                    (const ulonglong2*)(s_w + ((ic * 7 + ky) * 7 + kx) * 32 + og * 16);
#pragma unroll
                for (int q = 0; q < 4; q++) {
                    ulonglong2 w2 = wp[q];
                    fma2(acc0[2 * q + 0], v0, w2.x);
                    fma2(acc0[2 * q + 1], v0, w2.y);
                    fma2(acc1[2 * q + 0], v1, w2.x);
                    fma2(acc1[2 * q + 1], v1, w2.y);
                }
            }
    int oy = oy0 + ty, ox = ox0 + tx;
    float* op = out + (size_t)n * 32 * 65536 + (size_t)(og * 16) * 65536 + oy * 256 + ox;
#pragma unroll
    for (int j = 0; j < 8; j++) {
        float2 a = unpack2(acc0[j]);
        float2 b = unpack2(acc1[j]);
        float bz0 = bias[og * 16 + 2 * j], bz1 = bias[og * 16 + 2 * j + 1];
        op[(size_t)(2 * j + 0) * 65536] = a.x + bz0;
        op[(size_t)(2 * j + 1) * 65536] = a.y + bz1;
        op[(size_t)(2 * j + 0) * 65536 + 8 * 256] = b.x + bz0;
        op[(size_t)(2 * j + 1) * 65536 + 8 * 256] = b.y + bz1;
    }
}

// ---------------- 3x3 stride-2 conv, templated OCB (64 or 32) ----------------
// Warp covers rows {2wz, 2wz+1} x 16 cols x OCB oc.
// OCB=64: lane = og(8) x pg(4), 2 rows/thread.
// OCB=32: lane = og(4) x pg(4) x r2(2), 1 row/thread.
template <int IC, int OC, int ICC, int OCB>
__global__ void __launch_bounds__(256, 2)
k_conv3s2(const float* __restrict__ in, const float* __restrict__ wt,
          const float* __restrict__ bias, float* __restrict__ out,
          int Hin, int Win, int Hout, int Wout) {
    const int PIN = 33 * 36;
    const int NOG = OCB / 8;
    const int RPT = (OCB == 64) ? 2 : 1;
    extern __shared__ float smem[];
    float* s_w  = smem;
    float* s_in = s_w + 2 * ICC * 9 * OCB;

    const int tid = threadIdx.x;
    const int wz = tid >> 5;
    const int lane = tid & 31;
    const int og = lane % NOG;
    const int rest = lane / NOG;
    const int pg = rest & 3;
    const int r2 = rest >> 2;            // 0 for OCB=64
    const int z = blockIdx.z;
    const int n = z / (OC / OCB);
    const int oc0 = (z % (OC / OCB)) * OCB;
    const int oy0 = blockIdx.y * 16, ox0 = blockIdx.x * 16;
    const int iy0 = 2 * oy0 - 1;
    const int ixa = 2 * ox0 - 4;

    const float* inp = in + (size_t)n * IC * Hin * Win;

    auto prefetch = [&](int st, int b) {
        int ic0 = st * ICC;
        float* bw = s_w + b * (ICC * 9 * OCB);
        float* bi = s_in + b * (ICC * PIN);
        for (int i = tid; i < ICC * 33 * 9; i += 256) {
            int icl = i / 297;
            int rr = i % 297;
            int r = rr / 9, c9 = rr % 9;
            int iy = iy0 + r;
            int sx = ixa + 4 * c9;
            bool ok = ((unsigned)iy < (unsigned)Hin) && (sx >= 0);
            unsigned sz = ok ? 16u : 0u;
            const float* src = inp + (size_t)(ic0 + icl) * Hin * Win +
                               (ok ? iy * Win + sx : 0);
            cp16z(s2u(bi + icl * PIN + r * 36 + 4 * c9), src, sz);
        }
        const float* wsrc = wt + (size_t)ic0 * 9 * OC + oc0;
        for (int i = tid; i < ICC * 9 * (OCB / 4); i += 256) {
            int p = i / (OCB / 4), c = i % (OCB / 4);
            cp16(s2u(bw + p * OCB + 4 * c), wsrc + (size_t)p * OC + 4 * c);
        }
    };

    ull acc[RPT][4][4];
#pragma unroll
    for (int r = 0; r < RPT; r++)
#pragma unroll
        for (int c = 0; c < 4; c++)
#pragma unroll
            for (int j = 0; j < 4; j++) acc[r][c][j] = 0ull;

    prefetch(0, 0);
    cp_commit();
    const int NS = IC / ICC;
    for (int s = 0; s < NS; s++) {
        if (s + 1 < NS) { prefetch(s + 1, (s + 1) & 1); cp_commit(); cp_wait<1>(); }
        else cp_wait<0>();
        __syncthreads();
        const float* bi = s_in + (s & 1) * (ICC * PIN);
        const float* bw = s_w + (s & 1) * (ICC * 9 * OCB);
#pragma unroll 1
        for (int icl = 0; icl < ICC; icl++) {
            const float* rb = bi + icl * PIN + 8 * pg;
            const float* wb = bw + icl * 9 * OCB + og * 8;
#pragma unroll
            for (int ky = 0; ky < 3; ky++) {
                ull u[RPT][9];
#pragma unroll
                for (int r = 0; r < RPT; r++) {
                    int rowr = (RPT == 2) ? r : r2;
                    const float4* rv = (const float4*)(rb + (4 * wz + 2 * rowr + ky) * 36);
                    float4 a0 = rv[0], a1 = rv[1], a2 = rv[2];
                    u[r][0] = pack2(a0.w); u[r][1] = pack2(a1.x); u[r][2] = pack2(a1.y);
                    u[r][3] = pack2(a1.z); u[r][4] = pack2(a1.w); u[r][5] = pack2(a2.x);
                    u[r][6] = pack2(a2.y); u[r][7] = pack2(a2.z); u[r][8] = pack2(a2.w);
                }
#pragma unroll
                for (int kx = 0; kx < 3; kx++) {
                    const ulonglong2* wp = (const ulonglong2*)(wb + (3 * ky + kx) * OCB);
                    ulonglong2 wa = wp[0], wb2 = wp[1];
#pragma unroll
                    for (int c = 0; c < 4; c++)
#pragma unroll
                        for (int r = 0; r < RPT; r++) {
                            ull v = u[r][2 * c + kx];
                            fma2(acc[r][c][0], v, wa.x);
                            fma2(acc[r][c][1], v, wa.y);
                            fma2(acc[r][c][2], v, wb2.x);
                            fma2(acc[r][c][3], v, wb2.y);
                        }
                }
            }
        }
        __syncthreads();
    }

    const int ox = ox0 + 4 * pg;
    const size_t cs = (size_t)Hout * Wout;
#pragma unroll
    for (int r = 0; r < RPT; r++) {
        int rowr = (RPT == 2) ? r : r2;
        int oy = oy0 + 2 * wz + rowr;
        float* obase = out + (size_t)(n * OC + oc0 + og * 8) * cs + (size_t)oy * Wout + ox;
#pragma unroll
        for (int j = 0; j < 4; j++) {
            float2 p0 = unpack2(acc[r][0][j]);
            float2 p1 = unpack2(acc[r][1][j]);
            float2 p2 = unpack2(acc[r][2][j]);
            float2 p3 = unpack2(acc[r][3][j]);
            float blo = bias[oc0 + og * 8 + 2 * j];
            float bhi = bias[oc0 + og * 8 + 2 * j + 1];
            *(float4*)(obase + (size_t)(2 * j) * cs) =
                make_float4(p0.x + blo, p1.x + blo, p2.x + blo, p3.x + blo);
            *(float4*)(obase + (size_t)(2 * j + 1) * cs) =
                make_float4(p0.y + bhi, p1.y + bhi, p2.y + bhi, p3.y + bhi);
        }
    }
}

// ---------------- convT: pitched I/O, cp.async.16 staging ----------------
__device__ __forceinline__ void tap8(ull* A, ull* B, ull va, ull vb,
                                     const ulonglong2* wp) {
    ulonglong2 w0 = wp[0], w1 = wp[1];
    fma2(A[0], va, w0.x); fma2(A[1], va, w0.y);
    fma2(A[2], va, w1.x); fma2(A[3], va, w1.y);
    fma2(B[0], vb, w0.x); fma2(B[1], vb, w0.y);
    fma2(B[2], vb, w1.x); fma2(B[3], vb, w1.y);
}

template <int IC, int OC, int ICC>
__global__ void __launch_bounds__(256, 2)
k_convT(const float* __restrict__ in, const float* __restrict__ wt,
        const float* __restrict__ bias, float* __restrict__ out,
        int Hin, int Win, int pitchIn, int Hout, int Wout, int pitchOut) {
    const int OCB = 8;
    const int PIN = 17 * 36;
    extern __shared__ float smem[];
    float* s_w  = smem;
    float* s_in = s_w + 2 * ICC * 9 * OCB;

    const int tid = threadIdx.x;
    const int ty = tid >> 4;
    const int tx = tid & 15;
    const int z = blockIdx.z;
    const int n = z / (OC / OCB);
    const int oc0 = (z % (OC / OCB)) * OCB;
    const int oy0 = blockIdx.y * 32, ox0 = blockIdx.x * 64;
    const int iy0 = oy0 >> 1, ix0 = ox0 >> 1;

    const float* inp = in + (size_t)n * IC * Hin * pitchIn;

    auto prefetch = [&](int st, int b) {
        int ic0 = st * ICC;
        float* bw = s_w + b * (ICC * 9 * OCB);
        float* bi = s_in + b * (ICC * PIN);
        for (int i = tid; i < ICC * 153; i += 256) {
            int icl = i / 153, rr = i % 153;
            int r = rr / 9, c9 = rr % 9;
            int iy = iy0 + r;
            int sx = ix0 + 4 * c9;
            int vb = (iy < Hin) ? (Win - sx) : 0;
            unsigned sz = vb >= 4 ? 16u : (vb > 0 ? (unsigned)(4 * vb) : 0u);
            const float* src = inp + (size_t)(ic0 + icl) * Hin * pitchIn +
                               (sz ? iy * pitchIn + sx : 0);
            cp16z(s2u(bi + icl * PIN + r * 36 + 4 * c9), src, sz);
        }
        const float* wsrc = wt + (size_t)ic0 * 9 * OC + oc0;
        for (int i = tid; i < ICC * 9 * 2; i += 256) {
            int p = i >> 1, c = i & 1;
            cp16(s2u(bw + p * OCB + 4 * c), wsrc + (size_t)p * OC + 4 * c);
        }
    };

    ull acc[2][4][4];
#pragma unroll
    for (int b2 = 0; b2 < 2; b2++)
#pragma unroll
        for (int c = 0; c < 4; c++)
#pragma unroll
            for (int j = 0; j < 4; j++) acc[b2][c][j] = 0ull;

    prefetch(0, 0);
    cp_commit();
    const int NS = IC / ICC;
    for (int s = 0; s < NS; s++) {
        if (s + 1 < NS) { prefetch(s + 1, (s + 1) & 1); cp_commit(); cp_wait<1>(); }
        else cp_wait<0>();
        __syncthreads();
        const float* bi = s_in + (s & 1) * (ICC * PIN);
        const float* bw = s_w + (s & 1) * (ICC * 9 * OCB);
#pragma unroll 2
        for (int icl = 0; icl < ICC; icl++) {
            const float* sp = bi + icl * PIN + ty * 36 + tx;
            ull a00 = pack2(sp[0]);
            ull a01 = pack2(sp[1]);
            ull a10 = pack2(sp[36]);
            ull a11 = pack2(sp[37]);
            ull b00 = pack2(sp[16]);
            ull b01 = pack2(sp[17]);
            ull b10 = pack2(sp[52]);
            ull b11 = pack2(sp[53]);
            const ulonglong2* wp = (const ulonglong2*)(bw + icl * 9 * OCB);
            tap8(acc[0][3], acc[1][3], a11, b11, wp + 0);
            tap8(acc[0][2], acc[1][2], a10, b10, wp + 2);
            tap8(acc[0][3], acc[1][3], a10, b10, wp + 4);
            tap8(acc[0][1], acc[1][1], a01, b01, wp + 6);
            tap8(acc[0][0], acc[1][0], a00, b00, wp + 8);
            tap8(acc[0][1], acc[1][1], a00, b00, wp + 10);
            tap8(acc[0][3], acc[1][3], a01, b01, wp + 12);
            tap8(acc[0][2], acc[1][2], a00, b00, wp + 14);
            tap8(acc[0][3], acc[1][3], a00, b00, wp + 16);
        }
        __syncthreads();
    }

    const size_t cs = (size_t)Hout * pitchOut;
#pragma unroll
    for (int b2 = 0; b2 < 2; b2++) {
        int ye = oy0 + 2 * ty;
        int xe = ox0 + 2 * (tx + b2 * 16);
        bool y0v = ye < Hout, y1v = (ye + 1) < Hout;
        bool x0v = xe < Wout, x1v = (xe + 1) < Wout;
#pragma unroll
        for (int j = 0; j < 4; j++) {
            float bz0 = bias[oc0 + 2 * j], bz1 = bias[oc0 + 2 * j + 1];
            float* op0 = out + (size_t)(n * OC + oc0 + 2 * j) * cs;
            float* op1 = op0 + cs;
            float2 a;
            if (y0v && x0v) { a = unpack2(acc[b2][0][j]); op0[ye * pitchOut + xe] = a.x + bz0; op1[ye * pitchOut + xe] = a.y + bz1; }
            if (y0v && x1v) { a = unpack2(acc[b2][1][j]); op0[ye * pitchOut + xe + 1] = a.x + bz0; op1[ye * pitchOut + xe + 1] = a.y + bz1; }
            if (y1v && x0v) { a = unpack2(acc[b2][2][j]); op0[(ye + 1) * pitchOut + xe] = a.x + bz0; op1[(ye + 1) * pitchOut + xe] = a.y + bz1; }
            if (y1v && x1v) { a = unpack2(acc[b2][3][j]); op0[(ye + 1) * pitchOut + xe + 1] = a.x + bz0; op1[(ye + 1) * pitchOut + xe + 1] = a.y + bz1; }
        }
    }
}

// ---------------- layer 7: 7x7 conv 32->3 + tanh, 1row x 4col / thread ----------
__global__ void __launch_bounds__(256, 2)
k_conv7_l7(const float* __restrict__ act, const float* __restrict__ wt,
           const float* __restrict__ bias, const int* __restrict__ inst,
           float* __restrict__ gsum, float* __restrict__ gcnt) {
    extern __shared__ float smem[];
    float* s_w  = smem;
    float* s_in = s_w + 6272;
    __shared__ float ssb[96];
    __shared__ float scb[32];

    const int H = 249;
    const int PLANE = 63744;
    const int tid = threadIdx.x;
    const int tx = tid & 7;
    const int ty = tid >> 3;
    const int n = blockIdx.z;
    const int oy0 = blockIdx.y * 32, ox0 = blockIdx.x * 32;

    for (int i = tid; i < 6272; i += 256) s_w[i] = wt[i];
    if (tid < 96) ssb[tid] = 0.f;
    if (tid < 32) scb[tid] = 0.f;

    const float* ap = act + (size_t)n * 32 * PLANE;
    auto prefetch = [&](int st, int b) {
        float* bi = s_in + b * (4 * 1520);
        int ic0 = st * 4;
        for (int i = tid; i < 4 * 1444; i += 256) {
            int icl = i / 1444, rr = i % 1444;
            int r = rr / 38, c = rr % 38;
            int iy = oy0 + r - 3, ix = ox0 + c - 3;
            iy = iy < 0 ? -iy : (iy > 248 ? 496 - iy : iy);
            ix = ix < 0 ? -ix : (ix > 248 ? 496 - ix : ix);
            cp4(s2u(bi + icl * 1520 + r * 40 + c),
                ap + (size_t)(ic0 + icl) * PLANE + iy * 256 + ix, true);
        }
    };

    ull acc[4][2];
#pragma unroll
    for (int p = 0; p < 4; p++) { acc[p][0] = 0ull; acc[p][1] = 0ull; }

    prefetch(0, 0);
    cp_commit();
    for (int s = 0; s < 8; s++) {
        if (s < 7) { prefetch(s + 1, (s + 1) & 1); cp_commit(); cp_wait<1>(); }
        else cp_wait<0>();
        __syncthreads();
        const float* bi = s_in + (s & 1) * (4 * 1520);
#pragma unroll 1
        for (int icl = 0; icl < 4; icl++) {
            const float* wic = s_w + (s * 4 + icl) * 196;
            const float* si = bi + icl * 1520;
#pragma unroll 1
            for (int ky = 0; ky < 7; ky++) {
                const float4* rv = (const float4*)(si + (ty + ky) * 40 + 4 * tx);
                float4 q0 = rv[0], q1 = rv[1], q2 = rv[2];
                ull u[10];
                u[0] = pack2(q0.x); u[1] = pack2(q0.y); u[2] = pack2(q0.z);
                u[3] = pack2(q0.w); u[4] = pack2(q1.x); u[5] = pack2(q1.y);
                u[6] = pack2(q1.z); u[7] = pack2(q1.w); u[8] = pack2(q2.x);
                u[9] = pack2(q2.y);
                const ulonglong2* wp = (const ulonglong2*)(wic + ky * 28);
#pragma unroll
                for (int kx = 0; kx < 7; kx++) {
                    ulonglong2 w2 = wp[kx];
#pragma unroll
                    for (int d = 0; d < 4; d++) {
                        fma2(acc[d][0], u[kx + d], w2.x);
                        fma2(acc[d][1], u[kx + d], w2.y);
                    }
                }
            }
        }
        __syncthreads();
    }

    float b0 = bias[0], b1 = bias[1], b2 = bias[2];
    const int* ip = inst + (size_t)n * 62001;
    int oy = oy0 + ty;
    if (oy < H) {
#pragma unroll
        for (int d = 0; d < 4; d++) {
            int ox = ox0 + 4 * tx + d;
            if (ox < H) {
                float2 a0 = unpack2(acc[d][0]);
                float2 a1 = unpack2(acc[d][1]);
                float t0 = tanhf(a0.x + b0);
                float t1 = tanhf(a0.y + b1);
                float t2 = tanhf(a1.x + b2);
                int id = ip[oy * 249 + ox];
                atomicAdd(&ssb[id * 3 + 0], t0);
                atomicAdd(&ssb[id * 3 + 1], t1);
                atomicAdd(&ssb[id * 3 + 2], t2);
                atomicAdd(&scb[id], 1.f);
            }
        }
    }
    __syncthreads();
    if (tid < 96) atomicAdd(&gsum[tid], ssb[tid]);
    if (tid < 32) atomicAdd(&gcnt[tid], scb[tid]);
}

// ---------------- instance-norm (contiguous planes) ----------------
__global__ void k_instat(float* __restrict__ x, int HW) {
    int p = blockIdx.x;
    float* xp = x + (size_t)p * HW;
    float s0 = 0, s1 = 0, q0 = 0, q1 = 0;
    const float4* x4 = (const float4*)xp;
    int n4 = HW >> 2;
    for (int i = threadIdx.x; i < n4; i += 256) {
        float4 v = x4[i];
        s0 += v.x + v.y; q0 += v.x * v.x + v.y * v.y;
        s1 += v.z + v.w; q1 += v.z * v.z + v.w * v.w;
    }
    float s = s0 + s1, q = q0 + q1;
    for (int o = 16; o > 0; o >>= 1) {
        s += __shfl_down_sync(0xffffffffu, s, o);
        q += __shfl_down_sync(0xffffffffu, q, o);
    }
    __shared__ float sh[16];
    __shared__ float s_stat[2];
    int w = threadIdx.x >> 5, l = threadIdx.x & 31;
    if (l == 0) { sh[w] = s; sh[w + 8] = q; }
    __syncthreads();
    if (threadIdx.x == 0) {
        for (int k = 1; k < 8; k++) { s += sh[k]; q += sh[k + 8]; }
        float m = s / HW;
        float var = q / HW - m * m;
        float rs = rsqrtf(fmaxf(var, 0.f) + 1e-5f);
        s_stat[0] = rs;
        s_stat[1] = -m * rs;
    }
    __syncthreads();
    float rs = s_stat[0], sf = s_stat[1];
    float4* y4 = (float4*)xp;
    for (int i = threadIdx.x; i < n4; i += 256) {
        float4 v = y4[i];
        v.x = fmaxf(fmaf(v.x, rs, sf), 0.f);
        v.y = fmaxf(fmaf(v.y, rs, sf), 0.f);
        v.z = fmaxf(fmaf(v.z, rs, sf), 0.f);
        v.w = fmaxf(fmaf(v.w, rs, sf), 0.f);
        y4[i] = v;
    }
}

// ---------------- instance-norm (pitched planes, pitch = pow2) ----------------
__global__ void k_instat_p(float* __restrict__ x, int H, int W, int pitch) {
    int p = blockIdx.x;
    float* xp = x + (size_t)p * H * pitch;
    const int total = H * pitch;
    const int mask = pitch - 1;
    float s = 0, q = 0;
    for (int i = threadIdx.x; i < total; i += 256) {
        if ((i & mask) < W) {
            float v = xp[i];
            s += v; q += v * v;
        }
    }
    for (int o = 16; o > 0; o >>= 1) {
        s += __shfl_down_sync(0xffffffffu, s, o);
        q += __shfl_down_sync(0xffffffffu, q, o);
    }
    __shared__ float sh[16];
    __shared__ float s_stat[2];
    int w = threadIdx.x >> 5, l = threadIdx.x & 31;
    if (l == 0) { sh[w] = s; sh[w + 8] = q; }
    __syncthreads();
    if (threadIdx.x == 0) {
        for (int k = 1; k < 8; k++) { s += sh[k]; q += sh[k + 8]; }
        float inv = 1.f / (float)(H * W);
        float m = s * inv;
        float var = q * inv - m * m;
        float rs = rsqrtf(fmaxf(var, 0.f) + 1e-5f);
        s_stat[0] = rs;
        s_stat[1] = -m * rs;
    }
    __syncthreads();
    float rs = s_stat[0], sf = s_stat[1];
    for (int i = threadIdx.x; i < total; i += 256) {
        bool ok = (i & mask) < W;
        float v = xp[i];
        xp[i] = ok ? fmaxf(fmaf(v, rs, sf), 0.f) : 0.f;
    }
}

// ---------------- segment mean broadcast ----------------
__global__ void k_segbcast(const int* __restrict__ inst, const float* __restrict__ gsum,
                           const float* __restrict__ gcnt, float* __restrict__ out) {
    const int P = 62001, T = 8 * 3 * P;
    for (int i = blockIdx.x * blockDim.x + threadIdx.x; i < T; i += gridDim.x * blockDim.x) {
        int n = i / (3 * P), r = i % (3 * P);
        int c = r / P, p = r % P;
        int id = inst[n * P + p];
        out[i] = gsum[id * 3 + c] / fmaxf(gcnt[id], 1.f);
    }
}

// ---------------- launch ----------------
extern "C" void kernel_launch(void* const* d_in, const int* in_sizes, int n_in,
                              void* d_out, int out_size) {
    const float* x = (const float*)d_in[0];
    const int* inst = (const int*)d_in[1];
    const float* w[8];
    const float* b[8];
    for (int i = 0; i < 8; i++) {
        w[i] = (const float*)d_in[2 + 2 * i];
        b[i] = (const float*)d_in[3 + 2 * i];
    }
    float* out = (float*)d_out;

    float *A, *B;
    float *WT0, *WT1, *WT2, *WT3, *WT4, *WT5, *WT6, *WT7, *SS, *SN;
    cudaGetSymbolAddress((void**)&A, g_bufA);
    cudaGetSymbolAddress((void**)&B, g_bufB);
    cudaGetSymbolAddress((void**)&WT0, g_wt0);
    cudaGetSymbolAddress((void**)&WT1, g_wt1);
    cudaGetSymbolAddress((void**)&WT2, g_wt2);
    cudaGetSymbolAddress((void**)&WT3, g_wt3);
    cudaGetSymbolAddress((void**)&WT4, g_wt4);
    cudaGetSymbolAddress((void**)&WT5, g_wt5);
    cudaGetSymbolAddress((void**)&WT6, g_wt6);
    cudaGetSymbolAddress((void**)&WT7, g_wt7);
    cudaGetSymbolAddress((void**)&SS, g_segsum);
    cudaGetSymbolAddress((void**)&SN, g_segcnt);

    const int SM_C64 = (2*8*9*64 + 2*8*33*36) * 4;
    const int SM_C32 = (2*8*9*32 + 2*8*33*36) * 4;
    const int SM_T = (2*8*9*8 + 2*8*17*36) * 4;
    const int SM_L7 = (6272 + 2*4*1520) * 4;

    cudaFuncSetAttribute(k_conv3s2<32, 64, 8, 64>,  cudaFuncAttributeMaxDynamicSharedMemorySize, SM_C64);
    cudaFuncSetAttribute(k_conv3s2<64, 128, 8, 64>, cudaFuncAttributeMaxDynamicSharedMemorySize, SM_C64);
    cudaFuncSetAttribute(k_conv3s2<128, 256, 8, 32>,cudaFuncAttributeMaxDynamicSharedMemorySize, SM_C32);
    cudaFuncSetAttribute(k_convT<256, 128, 8>,  cudaFuncAttributeMaxDynamicSharedMemorySize, SM_T);
    cudaFuncSetAttribute(k_convT<128, 64, 8>,   cudaFuncAttributeMaxDynamicSharedMemorySize, SM_T);
    cudaFuncSetAttribute(k_convT<64, 32, 8>,    cudaFuncAttributeMaxDynamicSharedMemorySize, SM_T);
    cudaFuncSetAttribute(k_conv7_l7,            cudaFuncAttributeMaxDynamicSharedMemorySize, SM_L7);

    // weight prep + segment-bin zero
    k_prep<<<dim3(1152, 9), 256>>>(w[0], w[1], w[2], w[3], w[4], w[5], w[6], w[7],
                                   WT0, WT1, WT2, WT3, WT4, WT5, WT6, WT7, SS, SN);
    // layer 0
    k_conv7_l0<<<dim3(16, 16, 8), 256>>>(x, WT0, b[0], A);
    k_instat<<<8 * 32, 256>>>(A, 65536);
    // layers 1-3
    k_conv3s2<32, 64, 8, 64><<<dim3(8, 8, 8), 256, SM_C64>>>(A, WT1, b[1], B, 256, 256, 128, 128);
    k_instat<<<8 * 64, 256>>>(B, 16384);
    k_conv3s2<64, 128, 8, 64><<<dim3(4, 4, 16), 256, SM_C64>>>(B, WT2, b[2], A, 128, 128, 64, 64);
    k_instat<<<8 * 128, 256>>>(A, 4096);
    k_conv3s2<128, 256, 8, 32><<<dim3(2, 2, 64), 256, SM_C32>>>(A, WT3, b[3], B, 64, 64, 32, 32);
    k_instat<<<8 * 256, 256>>>(B, 1024);
    // layers 4-6 (transposed conv, pitched outputs)
    k_convT<256, 128, 8><<<dim3(1, 2, 128), 256, SM_T>>>(B, WT4, b[4], A,
                                                         32, 32, 32, 63, 63, 64);
    k_instat_p<<<8 * 128, 256>>>(A, 63, 63, 64);
    k_convT<128, 64, 8><<<dim3(2, 4, 64), 256, SM_T>>>(A, WT5, b[5], B,
                                                       63, 63, 64, 125, 125, 128);
    k_instat_p<<<8 * 64, 256>>>(B, 125, 125, 128);
    k_convT<64, 32, 8><<<dim3(4, 8, 32), 256, SM_T>>>(B, WT6, b[6], A,
                                                      125, 125, 128, 249, 249, 256);
    k_instat_p<<<8 * 32, 256>>>(A, 249, 249, 256);
    // layer 7 with fused segment accumulation
    k_conv7_l7<<<dim3(8, 8, 8), 256, SM_L7>>>(A, WT7, b[7], inst, SS, SN);
    // broadcast means
    k_segbcast<<<2048, 256>>>(inst, SS, SN, out);
}

// round 16
// speedup vs baseline: 2.6983x; 1.0140x over previous
#include <cuda_runtime.h>
#include <math.h>

// ---------------- static scratch ----------------
__device__ __align__(16) float g_bufA[16777216];
__device__ __align__(16) float g_bufB[8388608];
__device__ __align__(16) float g_wt0[3*49*32];
__device__ __align__(16) float g_wt1[32*9*64];
__device__ __align__(16) float g_wt2[64*9*128];
__device__ __align__(16) float g_wt3[128*9*256];
__device__ __align__(16) float g_wt4[256*9*128];
__device__ __align__(16) float g_wt5[128*9*64];
__device__ __align__(16) float g_wt6[64*9*32];
__device__ __align__(16) float g_wt7[32*49*4];
__device__ float g_segsum[96];
__device__ float g_segcnt[32];

typedef unsigned long long ull;

// ---------------- f32x2 packed helpers ----------------
__device__ __forceinline__ ull pack2(float v) {
    ull r;
    asm("mov.b64 %0, {%1, %1};" : "=l"(r) : "f"(v));
    return r;
}
__device__ __forceinline__ void fma2(ull& d, ull a, ull b) {
    asm("fma.rn.f32x2 %0, %1, %2, %0;" : "+l"(d) : "l"(a), "l"(b));
}
__device__ __forceinline__ float2 unpack2(ull v) {
    float2 f;
    asm("mov.b64 {%0, %1}, %2;" : "=f"(f.x), "=f"(f.y) : "l"(v));
    return f;
}

// ---------------- cp.async helpers ----------------
__device__ __forceinline__ unsigned s2u(const void* p) {
    return (unsigned)__cvta_generic_to_shared(p);
}
__device__ __forceinline__ void cp4(unsigned dst, const float* src, bool pred) {
    asm volatile("cp.async.ca.shared.global [%0], [%1], 4, %2;" ::
                 "r"(dst), "l"(src), "r"(pred ? 4u : 0u));
}
__device__ __forceinline__ void cp16(unsigned dst, const float* src) {
    asm volatile("cp.async.cg.shared.global [%0], [%1], 16;" ::
                 "r"(dst), "l"(src));
}
__device__ __forceinline__ void cp16z(unsigned dst, const float* src, unsigned sz) {
    asm volatile("cp.async.cg.shared.global [%0], [%1], 16, %2;" ::
                 "r"(dst), "l"(src), "r"(sz));
}
__device__ __forceinline__ void cp_commit() {
    asm volatile("cp.async.commit_group;" ::: "memory");
}
template <int N>
__device__ __forceinline__ void cp_wait() {
    asm volatile("cp.async.wait_group %0;" :: "n"(N) : "memory");
}

// ---------------- fused weight prep + segment-bin zero ----------------
__global__ void k_prep(const float* __restrict__ w0, const float* __restrict__ w1,
                       const float* __restrict__ w2, const float* __restrict__ w3,
                       const float* __restrict__ w4, const float* __restrict__ w5,
                       const float* __restrict__ w6, const float* __restrict__ w7,
                       float* o0, float* o1, float* o2, float* o3,
                       float* o4, float* o5, float* o6, float* o7,
                       float* segsum, float* segcnt) {
    int idx = blockIdx.x * 256 + threadIdx.x;
    switch (blockIdx.y) {
    case 0: if (idx < 32*3*49)   { int o=idx/147,  r=idx%147,  i=r/49, k=r%49; o0[(i*49+k)*32+o]=w0[idx]; } break;
    case 1: if (idx < 64*32*9)   { int o=idx/288,  r=idx%288,  i=r/9,  k=r%9;  o1[(i*9+k)*64+o]=w1[idx]; } break;
    case 2: if (idx < 128*64*9)  { int o=idx/576,  r=idx%576,  i=r/9,  k=r%9;  o2[(i*9+k)*128+o]=w2[idx]; } break;
    case 3: if (idx < 256*128*9) { int o=idx/1152, r=idx%1152, i=r/9,  k=r%9;  o3[(i*9+k)*256+o]=w3[idx]; } break;
    case 4: if (idx < 256*128*9) { int i=idx/1152, r=idx%1152, o=r/9,  k=r%9;  o4[(i*9+k)*128+o]=w4[idx]; } break;
    case 5: if (idx < 128*64*9)  { int i=idx/576,  r=idx%576,  o=r/9,  k=r%9;  o5[(i*9+k)*64+o]=w5[idx]; } break;
    case 6: if (idx < 64*32*9)   { int i=idx/288,  r=idx%288,  o=r/9,  k=r%9;  o6[(i*9+k)*32+o]=w6[idx]; } break;
    case 7: if (idx < 32*49*4)   { int p=idx>>2, o=idx&3; int i=p/49, k=p%49;
                                   o7[idx] = (o < 3) ? w7[(o*32+i)*49+k] : 0.f; } break;
    case 8: if (idx < 96) segsum[idx] = 0.f;
            if (idx < 32) segcnt[idx] = 0.f;
            break;
    }
}

// ---------------- layer 0: reflect-pad 7x7 conv 3->32, SGEMM-style warp map ----
// Warp wz owns rows {2wz, 2wz+1} x 16 cols x 32 oc.
// lane: og = lane&3 (oc octet), pg = (lane>>2)&3 (col quad), r = lane>>4 (row).
__global__ void __launch_bounds__(256)
k_conv7_l0(const float* __restrict__ x, const float* __restrict__ wt,
           const float* __restrict__ bias, float* __restrict__ out) {
    __shared__ __align__(16) float s_w[3 * 49 * 32];
    __shared__ __align__(16) float s_in[3 * 22 * 36];
    const int tid = threadIdx.x;
    const int wz = tid >> 5;
    const int lane = tid & 31;
    const int og = lane & 3;
    const int pg = (lane >> 2) & 3;
    const int r = lane >> 4;
    const int n = blockIdx.z;
    const int oy0 = blockIdx.y * 16, ox0 = blockIdx.x * 16;

    for (int i = tid; i < 3 * 49 * 32; i += 256) s_w[i] = wt[i];
    const float* xp = x + (size_t)n * 3 * 65536;
    for (int i = tid; i < 3 * 484; i += 256) {
        int ic = i / 484, rr = (i % 484) / 22, cc = i % 22;
        int iy = oy0 + rr - 3, ix = ox0 + cc - 3;
        iy = iy < 0 ? -iy : (iy > 255 ? 510 - iy : iy);
        ix = ix < 0 ? -ix : (ix > 255 ? 510 - ix : ix);
        s_in[ic * 792 + rr * 36 + cc] = xp[ic * 65536 + iy * 256 + ix];
    }
    __syncthreads();

    // acc[d][j]: d = col offset in quad, j = oc pair within octet (8 oc = 4 ull)
    ull acc[4][4];
#pragma unroll
    for (int d = 0; d < 4; d++)
#pragma unroll
        for (int j = 0; j < 4; j++) acc[d][j] = 0ull;

#pragma unroll 1
    for (int ic = 0; ic < 3; ic++) {
        const float* si = s_in + ic * 792 + 4 * pg;
        const float* wic = s_w + ic * 49 * 32 + og * 8;
#pragma unroll 1
        for (int ky = 0; ky < 7; ky++) {
            const float4* rv = (const float4*)(si + (2 * wz + r + ky) * 36);
            float4 q0 = rv[0], q1 = rv[1], q2 = rv[2];
            ull u[10];
            u[0] = pack2(q0.x); u[1] = pack2(q0.y); u[2] = pack2(q0.z);
            u[3] = pack2(q0.w); u[4] = pack2(q1.x); u[5] = pack2(q1.y);
            u[6] = pack2(q1.z); u[7] = pack2(q1.w); u[8] = pack2(q2.x);
            u[9] = pack2(q2.y);
            const float* wky = wic + ky * 7 * 32;
#pragma unroll
            for (int kx = 0; kx < 7; kx++) {
                const ulonglong2* wp = (const ulonglong2*)(wky + kx * 32);
                ulonglong2 w2 = wp[0], w3 = wp[1];
#pragma unroll
                for (int d = 0; d < 4; d++) {
                    ull v = u[kx + d];
                    fma2(acc[d][0], v, w2.x);
                    fma2(acc[d][1], v, w2.y);
                    fma2(acc[d][2], v, w3.x);
                    fma2(acc[d][3], v, w3.y);
                }
            }
        }
    }

    const int oy = oy0 + 2 * wz + r;
    const int ox = ox0 + 4 * pg;
    float* obase = out + (size_t)n * 32 * 65536 + (size_t)(og * 8) * 65536 +
                   (size_t)oy * 256 + ox;
#pragma unroll
    for (int j = 0; j < 4; j++) {
        float2 p0 = unpack2(acc[0][j]);
        float2 p1 = unpack2(acc[1][j]);
        float2 p2 = unpack2(acc[2][j]);
        float2 p3 = unpack2(acc[3][j]);
        float blo = bias[og * 8 + 2 * j];
        float bhi = bias[og * 8 + 2 * j + 1];
        *(float4*)(obase + (size_t)(2 * j) * 65536) =
            make_float4(p0.x + blo, p1.x + blo, p2.x + blo, p3.x + blo);
        *(float4*)(obase + (size_t)(2 * j + 1) * 65536) =
            make_float4(p0.y + bhi, p1.y + bhi, p2.y + bhi, p3.y + bhi);
    }
}

// ---------------- 3x3 stride-2 conv, templated OCB (64 or 32) ----------------
template <int IC, int OC, int ICC, int OCB>
__global__ void __launch_bounds__(256, 2)
k_conv3s2(const float* __restrict__ in, const float* __restrict__ wt,
          const float* __restrict__ bias, float* __restrict__ out,
          int Hin, int Win, int Hout, int Wout) {
    const int PIN = 33 * 36;
    const int NOG = OCB / 8;
    const int RPT = (OCB == 64) ? 2 : 1;
    extern __shared__ float smem[];
    float* s_w  = smem;
    float* s_in = s_w + 2 * ICC * 9 * OCB;

    const int tid = threadIdx.x;
    const int wz = tid >> 5;
    const int lane = tid & 31;
    const int og = lane % NOG;
    const int rest = lane / NOG;
    const int pg = rest & 3;
    const int r2 = rest >> 2;
    const int z = blockIdx.z;
    const int n = z / (OC / OCB);
    const int oc0 = (z % (OC / OCB)) * OCB;
    const int oy0 = blockIdx.y * 16, ox0 = blockIdx.x * 16;
    const int iy0 = 2 * oy0 - 1;
    const int ixa = 2 * ox0 - 4;

    const float* inp = in + (size_t)n * IC * Hin * Win;

    auto prefetch = [&](int st, int b) {
        int ic0 = st * ICC;
        float* bw = s_w + b * (ICC * 9 * OCB);
        float* bi = s_in + b * (ICC * PIN);
        for (int i = tid; i < ICC * 33 * 9; i += 256) {
            int icl = i / 297;
            int rr = i % 297;
            int rw = rr / 9, c9 = rr % 9;
            int iy = iy0 + rw;
            int sx = ixa + 4 * c9;
            bool ok = ((unsigned)iy < (unsigned)Hin) && (sx >= 0);
            unsigned sz = ok ? 16u : 0u;
            const float* src = inp + (size_t)(ic0 + icl) * Hin * Win +
                               (ok ? iy * Win + sx : 0);
            cp16z(s2u(bi + icl * PIN + rw * 36 + 4 * c9), src, sz);
        }
        const float* wsrc = wt + (size_t)ic0 * 9 * OC + oc0;
        for (int i = tid; i < ICC * 9 * (OCB / 4); i += 256) {
            int p = i / (OCB / 4), c = i % (OCB / 4);
            cp16(s2u(bw + p * OCB + 4 * c), wsrc + (size_t)p * OC + 4 * c);
        }
    };

    ull acc[RPT][4][4];
#pragma unroll
    for (int r = 0; r < RPT; r++)
#pragma unroll
        for (int c = 0; c < 4; c++)
#pragma unroll
            for (int j = 0; j < 4; j++) acc[r][c][j] = 0ull;

    prefetch(0, 0);
    cp_commit();
    const int NS = IC / ICC;
    for (int s = 0; s < NS; s++) {
        if (s + 1 < NS) { prefetch(s + 1, (s + 1) & 1); cp_commit(); cp_wait<1>(); }
        else cp_wait<0>();
        __syncthreads();
        const float* bi = s_in + (s & 1) * (ICC * PIN);
        const float* bw = s_w + (s & 1) * (ICC * 9 * OCB);
#pragma unroll 1
        for (int icl = 0; icl < ICC; icl++) {
            const float* rb = bi + icl * PIN + 8 * pg;
            const float* wb = bw + icl * 9 * OCB + og * 8;
#pragma unroll
            for (int ky = 0; ky < 3; ky++) {
                ull u[RPT][9];
#pragma unroll
                for (int r = 0; r < RPT; r++) {
                    int rowr = (RPT == 2) ? r : r2;
                    const float4* rv = (const float4*)(rb + (4 * wz + 2 * rowr + ky) * 36);
                    float4 a0 = rv[0], a1 = rv[1], a2 = rv[2];
                    u[r][0] = pack2(a0.w); u[r][1] = pack2(a1.x); u[r][2] = pack2(a1.y);
                    u[r][3] = pack2(a1.z); u[r][4] = pack2(a1.w); u[r][5] = pack2(a2.x);
                    u[r][6] = pack2(a2.y); u[r][7] = pack2(a2.z); u[r][8] = pack2(a2.w);
                }
#pragma unroll
                for (int kx = 0; kx < 3; kx++) {
                    const ulonglong2* wp = (const ulonglong2*)(wb + (3 * ky + kx) * OCB);
                    ulonglong2 wa = wp[0], wb2 = wp[1];
#pragma unroll
                    for (int c = 0; c < 4; c++)
#pragma unroll
                        for (int r = 0; r < RPT; r++) {
                            ull v = u[r][2 * c + kx];
                            fma2(acc[r][c][0], v, wa.x);
                            fma2(acc[r][c][1], v, wa.y);
                            fma2(acc[r][c][2], v, wb2.x);
                            fma2(acc[r][c][3], v, wb2.y);
                        }
                }
            }
        }
        __syncthreads();
    }

    const int ox = ox0 + 4 * pg;
    const size_t cs = (size_t)Hout * Wout;
#pragma unroll
    for (int r = 0; r < RPT; r++) {
        int rowr = (RPT == 2) ? r : r2;
        int oy = oy0 + 2 * wz + rowr;
        float* obase = out + (size_t)(n * OC + oc0 + og * 8) * cs + (size_t)oy * Wout + ox;
#pragma unroll
        for (int j = 0; j < 4; j++) {
            float2 p0 = unpack2(acc[r][0][j]);
            float2 p1 = unpack2(acc[r][1][j]);
            float2 p2 = unpack2(acc[r][2][j]);
            float2 p3 = unpack2(acc[r][3][j]);
            float blo = bias[oc0 + og * 8 + 2 * j];
            float bhi = bias[oc0 + og * 8 + 2 * j + 1];
            *(float4*)(obase + (size_t)(2 * j) * cs) =
                make_float4(p0.x + blo, p1.x + blo, p2.x + blo, p3.x + blo);
            *(float4*)(obase + (size_t)(2 * j + 1) * cs) =
                make_float4(p0.y + bhi, p1.y + bhi, p2.y + bhi, p3.y + bhi);
        }
    }
}

// ---------------- convT: pitched I/O, cp.async.16 staging ----------------
__device__ __forceinline__ void tap8(ull* A, ull* B, ull va, ull vb,
                                     const ulonglong2* wp) {
    ulonglong2 w0 = wp[0], w1 = wp[1];
    fma2(A[0], va, w0.x); fma2(A[1], va, w0.y);
    fma2(A[2], va, w1.x); fma2(A[3], va, w1.y);
    fma2(B[0], vb, w0.x); fma2(B[1], vb, w0.y);
    fma2(B[2], vb, w1.x); fma2(B[3], vb, w1.y);
}

template <int IC, int OC, int ICC>
__global__ void __launch_bounds__(256, 2)
k_convT(const float* __restrict__ in, const float* __restrict__ wt,
        const float* __restrict__ bias, float* __restrict__ out,
        int Hin, int Win, int pitchIn, int Hout, int Wout, int pitchOut) {
    const int OCB = 8;
    const int PIN = 17 * 36;
    extern __shared__ float smem[];
    float* s_w  = smem;
    float* s_in = s_w + 2 * ICC * 9 * OCB;

    const int tid = threadIdx.x;
    const int ty = tid >> 4;
    const int tx = tid & 15;
    const int z = blockIdx.z;
    const int n = z / (OC / OCB);
    const int oc0 = (z % (OC / OCB)) * OCB;
    const int oy0 = blockIdx.y * 32, ox0 = blockIdx.x * 64;
    const int iy0 = oy0 >> 1, ix0 = ox0 >> 1;

    const float* inp = in + (size_t)n * IC * Hin * pitchIn;

    auto prefetch = [&](int st, int b) {
        int ic0 = st * ICC;
        float* bw = s_w + b * (ICC * 9 * OCB);
        float* bi = s_in + b * (ICC * PIN);
        for (int i = tid; i < ICC * 153; i += 256) {
            int icl = i / 153, rr = i % 153;
            int r = rr / 9, c9 = rr % 9;
            int iy = iy0 + r;
            int sx = ix0 + 4 * c9;
            int vb = (iy < Hin) ? (Win - sx) : 0;
            unsigned sz = vb >= 4 ? 16u : (vb > 0 ? (unsigned)(4 * vb) : 0u);
            const float* src = inp + (size_t)(ic0 + icl) * Hin * pitchIn +
                               (sz ? iy * pitchIn + sx : 0);
            cp16z(s2u(bi + icl * PIN + r * 36 + 4 * c9), src, sz);
        }
        const float* wsrc = wt + (size_t)ic0 * 9 * OC + oc0;
        for (int i = tid; i < ICC * 9 * 2; i += 256) {
            int p = i >> 1, c = i & 1;
            cp16(s2u(bw + p * OCB + 4 * c), wsrc + (size_t)p * OC + 4 * c);
        }
    };

    ull acc[2][4][4];
#pragma unroll
    for (int b2 = 0; b2 < 2; b2++)
#pragma unroll
        for (int c = 0; c < 4; c++)
#pragma unroll
            for (int j = 0; j < 4; j++) acc[b2][c][j] = 0ull;

    prefetch(0, 0);
    cp_commit();
    const int NS = IC / ICC;
    for (int s = 0; s < NS; s++) {
        if (s + 1 < NS) { prefetch(s + 1, (s + 1) & 1); cp_commit(); cp_wait<1>(); }
        else cp_wait<0>();
        __syncthreads();
        const float* bi = s_in + (s & 1) * (ICC * PIN);
        const float* bw = s_w + (s & 1) * (ICC * 9 * OCB);
#pragma unroll 2
        for (int icl = 0; icl < ICC; icl++) {
            const float* sp = bi + icl * PIN + ty * 36 + tx;
            ull a00 = pack2(sp[0]);
            ull a01 = pack2(sp[1]);
            ull a10 = pack2(sp[36]);
            ull a11 = pack2(sp[37]);
            ull b00 = pack2(sp[16]);
            ull b01 = pack2(sp[17]);
            ull b10 = pack2(sp[52]);
            ull b11 = pack2(sp[53]);
            const ulonglong2* wp = (const ulonglong2*)(bw + icl * 9 * OCB);
            tap8(acc[0][3], acc[1][3], a11, b11, wp + 0);
            tap8(acc[0][2], acc[1][2], a10, b10, wp + 2);
            tap8(acc[0][3], acc[1][3], a10, b10, wp + 4);
            tap8(acc[0][1], acc[1][1], a01, b01, wp + 6);
            tap8(acc[0][0], acc[1][0], a00, b00, wp + 8);
            tap8(acc[0][1], acc[1][1], a00, b00, wp + 10);
            tap8(acc[0][3], acc[1][3], a01, b01, wp + 12);
            tap8(acc[0][2], acc[1][2], a00, b00, wp + 14);
            tap8(acc[0][3], acc[1][3], a00, b00, wp + 16);
        }
        __syncthreads();
    }

    const size_t cs = (size_t)Hout * pitchOut;
#pragma unroll
    for (int b2 = 0; b2 < 2; b2++) {
        int ye = oy0 + 2 * ty;
        int xe = ox0 + 2 * (tx + b2 * 16);
        bool y0v = ye < Hout, y1v = (ye + 1) < Hout;
        bool x0v = xe < Wout, x1v = (xe + 1) < Wout;
#pragma unroll
        for (int j = 0; j < 4; j++) {
            float bz0 = bias[oc0 + 2 * j], bz1 = bias[oc0 + 2 * j + 1];
            float* op0 = out + (size_t)(n * OC + oc0 + 2 * j) * cs;
            float* op1 = op0 + cs;
            float2 a;
            if (y0v && x0v) { a = unpack2(acc[b2][0][j]); op0[ye * pitchOut + xe] = a.x + bz0; op1[ye * pitchOut + xe] = a.y + bz1; }
            if (y0v && x1v) { a = unpack2(acc[b2][1][j]); op0[ye * pitchOut + xe + 1] = a.x + bz0; op1[ye * pitchOut + xe + 1] = a.y + bz1; }
            if (y1v && x0v) { a = unpack2(acc[b2][2][j]); op0[(ye + 1) * pitchOut + xe] = a.x + bz0; op1[(ye + 1) * pitchOut + xe] = a.y + bz1; }
            if (y1v && x1v) { a = unpack2(acc[b2][3][j]); op0[(ye + 1) * pitchOut + xe + 1] = a.x + bz0; op1[(ye + 1) * pitchOut + xe + 1] = a.y + bz1; }
        }
    }
}

// ---------------- layer 7: 7x7 conv 32->3 + tanh, 1row x 4col / thread ----------
__global__ void __launch_bounds__(256, 2)
k_conv7_l7(const float* __restrict__ act, const float* __restrict__ wt,
           const float* __restrict__ bias, const int* __restrict__ inst,
           float* __restrict__ gsum, float* __restrict__ gcnt) {
    extern __shared__ float smem[];
    float* s_w  = smem;
    float* s_in = s_w + 6272;
    __shared__ float ssb[96];
    __shared__ float scb[32];

    const int H = 249;
    const int PLANE = 63744;
    const int tid = threadIdx.x;
    const int tx = tid & 7;
    const int ty = tid >> 3;
    const int n = blockIdx.z;
    const int oy0 = blockIdx.y * 32, ox0 = blockIdx.x * 32;

    for (int i = tid; i < 6272; i += 256) s_w[i] = wt[i];
    if (tid < 96) ssb[tid] = 0.f;
    if (tid < 32) scb[tid] = 0.f;

    const float* ap = act + (size_t)n * 32 * PLANE;
    auto prefetch = [&](int st, int b) {
        float* bi = s_in + b * (4 * 1520);
        int ic0 = st * 4;
        for (int i = tid; i < 4 * 1444; i += 256) {
            int icl = i / 1444, rr = i % 1444;
            int r = rr / 38, c = rr % 38;
            int iy = oy0 + r - 3, ix = ox0 + c - 3;
            iy = iy < 0 ? -iy : (iy > 248 ? 496 - iy : iy);
            ix = ix < 0 ? -ix : (ix > 248 ? 496 - ix : ix);
            cp4(s2u(bi + icl * 1520 + r * 40 + c),
                ap + (size_t)(ic0 + icl) * PLANE + iy * 256 + ix, true);
        }
    };

    ull acc[4][2];
#pragma unroll
    for (int p = 0; p < 4; p++) { acc[p][0] = 0ull; acc[p][1] = 0ull; }

    prefetch(0, 0);
    cp_commit();
    for (int s = 0; s < 8; s++) {
        if (s < 7) { prefetch(s + 1, (s + 1) & 1); cp_commit(); cp_wait<1>(); }
        else cp_wait<0>();
        __syncthreads();
        const float* bi = s_in + (s & 1) * (4 * 1520);
#pragma unroll 1
        for (int icl = 0; icl < 4; icl++) {
            const float* wic = s_w + (s * 4 + icl) * 196;
            const float* si = bi + icl * 1520;
#pragma unroll 1
            for (int ky = 0; ky < 7; ky++) {
                const float4* rv = (const float4*)(si + (ty + ky) * 40 + 4 * tx);
                float4 q0 = rv[0], q1 = rv[1], q2 = rv[2];
                ull u[10];
                u[0] = pack2(q0.x); u[1] = pack2(q0.y); u[2] = pack2(q0.z);
                u[3] = pack2(q0.w); u[4] = pack2(q1.x); u[5] = pack2(q1.y);
                u[6] = pack2(q1.z); u[7] = pack2(q1.w); u[8] = pack2(q2.x);
                u[9] = pack2(q2.y);
                const ulonglong2* wp = (const ulonglong2*)(wic + ky * 28);
#pragma unroll
                for (int kx = 0; kx < 7; kx++) {
                    ulonglong2 w2 = wp[kx];
#pragma unroll
                    for (int d = 0; d < 4; d++) {
                        fma2(acc[d][0], u[kx + d], w2.x);
                        fma2(acc[d][1], u[kx + d], w2.y);
                    }
                }
            }
        }
        __syncthreads();
    }

    float b0 = bias[0], b1 = bias[1], b2 = bias[2];
    const int* ip = inst + (size_t)n * 62001;
    int oy = oy0 + ty;
    if (oy < H) {
#pragma unroll
        for (int d = 0; d < 4; d++) {
            int ox = ox0 + 4 * tx + d;
            if (ox < H) {
                float2 a0 = unpack2(acc[d][0]);
                float2 a1 = unpack2(acc[d][1]);
                float t0 = tanhf(a0.x + b0);
                float t1 = tanhf(a0.y + b1);
                float t2 = tanhf(a1.x + b2);
                int id = ip[oy * 249 + ox];
                atomicAdd(&ssb[id * 3 + 0], t0);
                atomicAdd(&ssb[id * 3 + 1], t1);
                atomicAdd(&ssb[id * 3 + 2], t2);
                atomicAdd(&scb[id], 1.f);
            }
        }
    }
    __syncthreads();
    if (tid < 96) atomicAdd(&gsum[tid], ssb[tid]);
    if (tid < 32) atomicAdd(&gcnt[tid], scb[tid]);
}

// ---------------- instance-norm (contiguous planes) ----------------
__global__ void k_instat(float* __restrict__ x, int HW) {
    int p = blockIdx.x;
    float* xp = x + (size_t)p * HW;
    float s0 = 0, s1 = 0, q0 = 0, q1 = 0;
    const float4* x4 = (const float4*)xp;
    int n4 = HW >> 2;
    for (int i = threadIdx.x; i < n4; i += 256) {
        float4 v = x4[i];
        s0 += v.x + v.y; q0 += v.x * v.x + v.y * v.y;
        s1 += v.z + v.w; q1 += v.z * v.z + v.w * v.w;
    }
    float s = s0 + s1, q = q0 + q1;
    for (int o = 16; o > 0; o >>= 1) {
        s += __shfl_down_sync(0xffffffffu, s, o);
        q += __shfl_down_sync(0xffffffffu, q, o);
    }
    __shared__ float sh[16];
    __shared__ float s_stat[2];
    int w = threadIdx.x >> 5, l = threadIdx.x & 31;
    if (l == 0) { sh[w] = s; sh[w + 8] = q; }
    __syncthreads();
    if (threadIdx.x == 0) {
        for (int k = 1; k < 8; k++) { s += sh[k]; q += sh[k + 8]; }
        float m = s / HW;
        float var = q / HW - m * m;
        float rs = rsqrtf(fmaxf(var, 0.f) + 1e-5f);
        s_stat[0] = rs;
        s_stat[1] = -m * rs;
    }
    __syncthreads();
    float rs = s_stat[0], sf = s_stat[1];
    float4* y4 = (float4*)xp;
    for (int i = threadIdx.x; i < n4; i += 256) {
        float4 v = y4[i];
        v.x = fmaxf(fmaf(v.x, rs, sf), 0.f);
        v.y = fmaxf(fmaf(v.y, rs, sf), 0.f);
        v.z = fmaxf(fmaf(v.z, rs, sf), 0.f);
        v.w = fmaxf(fmaf(v.w, rs, sf), 0.f);
        y4[i] = v;
    }
}

// ---------------- instance-norm (pitched planes, pitch = pow2) ----------------
__global__ void k_instat_p(float* __restrict__ x, int H, int W, int pitch) {
    int p = blockIdx.x;
    float* xp = x + (size_t)p * H * pitch;
    const int total = H * pitch;
    const int mask = pitch - 1;
    float s = 0, q = 0;
    for (int i = threadIdx.x; i < total; i += 256) {
        if ((i & mask) < W) {
            float v = xp[i];
            s += v; q += v * v;
        }
    }
    for (int o = 16; o > 0; o >>= 1) {
        s += __shfl_down_sync(0xffffffffu, s, o);
        q += __shfl_down_sync(0xffffffffu, q, o);
    }
    __shared__ float sh[16];
    __shared__ float s_stat[2];
    int w = threadIdx.x >> 5, l = threadIdx.x & 31;
    if (l == 0) { sh[w] = s; sh[w + 8] = q; }
    __syncthreads();
    if (threadIdx.x == 0) {
        for (int k = 1; k < 8; k++) { s += sh[k]; q += sh[k + 8]; }
        float inv = 1.f / (float)(H * W);
        float m = s * inv;
        float var = q * inv - m * m;
        float rs = rsqrtf(fmaxf(var, 0.f) + 1e-5f);
        s_stat[0] = rs;
        s_stat[1] = -m * rs;
    }
    __syncthreads();
    float rs = s_stat[0], sf = s_stat[1];
    for (int i = threadIdx.x; i < total; i += 256) {
        bool ok = (i & mask) < W;
        float v = xp[i];
        xp[i] = ok ? fmaxf(fmaf(v, rs, sf), 0.f) : 0.f;
    }
}

// ---------------- segment mean broadcast ----------------
__global__ void k_segbcast(const int* __restrict__ inst, const float* __restrict__ gsum,
                           const float* __restrict__ gcnt, float* __restrict__ out) {
    const int P = 62001, T = 8 * 3 * P;
    for (int i = blockIdx.x * blockDim.x + threadIdx.x; i < T; i += gridDim.x * blockDim.x) {
        int n = i / (3 * P), r = i % (3 * P);
        int c = r / P, p = r % P;
        int id = inst[n * P + p];
        out[i] = gsum[id * 3 + c] / fmaxf(gcnt[id], 1.f);
    }
}

// ---------------- launch ----------------
extern "C" void kernel_launch(void* const* d_in, const int* in_sizes, int n_in,
                              void* d_out, int out_size) {
    const float* x = (const float*)d_in[0];
    const int* inst = (const int*)d_in[1];
    const float* w[8];
    const float* b[8];
    for (int i = 0; i < 8; i++) {
        w[i] = (const float*)d_in[2 + 2 * i];
        b[i] = (const float*)d_in[3 + 2 * i];
    }
    float* out = (float*)d_out;

    float *A, *B;
    float *WT0, *WT1, *WT2, *WT3, *WT4, *WT5, *WT6, *WT7, *SS, *SN;
    cudaGetSymbolAddress((void**)&A, g_bufA);
    cudaGetSymbolAddress((void**)&B, g_bufB);
    cudaGetSymbolAddress((void**)&WT0, g_wt0);
    cudaGetSymbolAddress((void**)&WT1, g_wt1);
    cudaGetSymbolAddress((void**)&WT2, g_wt2);
    cudaGetSymbolAddress((void**)&WT3, g_wt3);
    cudaGetSymbolAddress((void**)&WT4, g_wt4);
    cudaGetSymbolAddress((void**)&WT5, g_wt5);
    cudaGetSymbolAddress((void**)&WT6, g_wt6);
    cudaGetSymbolAddress((void**)&WT7, g_wt7);
    cudaGetSymbolAddress((void**)&SS, g_segsum);
    cudaGetSymbolAddress((void**)&SN, g_segcnt);

    const int SM_C64 = (2*8*9*64 + 2*8*33*36) * 4;
    const int SM_C32 = (2*8*9*32 + 2*8*33*36) * 4;
    const int SM_T = (2*8*9*8 + 2*8*17*36) * 4;
    const int SM_L7 = (6272 + 2*4*1520) * 4;

    cudaFuncSetAttribute(k_conv3s2<32, 64, 8, 64>,  cudaFuncAttributeMaxDynamicSharedMemorySize, SM_C64);
    cudaFuncSetAttribute(k_conv3s2<64, 128, 8, 64>, cudaFuncAttributeMaxDynamicSharedMemorySize, SM_C64);
    cudaFuncSetAttribute(k_conv3s2<128, 256, 8, 32>,cudaFuncAttributeMaxDynamicSharedMemorySize, SM_C32);
    cudaFuncSetAttribute(k_convT<256, 128, 8>,  cudaFuncAttributeMaxDynamicSharedMemorySize, SM_T);
    cudaFuncSetAttribute(k_convT<128, 64, 8>,   cudaFuncAttributeMaxDynamicSharedMemorySize, SM_T);
    cudaFuncSetAttribute(k_convT<64, 32, 8>,    cudaFuncAttributeMaxDynamicSharedMemorySize, SM_T);
    cudaFuncSetAttribute(k_conv7_l7,            cudaFuncAttributeMaxDynamicSharedMemorySize, SM_L7);

    // weight prep + segment-bin zero
    k_prep<<<dim3(1152, 9), 256>>>(w[0], w[1], w[2], w[3], w[4], w[5], w[6], w[7],
                                   WT0, WT1, WT2, WT3, WT4, WT5, WT6, WT7, SS, SN);
    // layer 0
    k_conv7_l0<<<dim3(16, 16, 8), 256>>>(x, WT0, b[0], A);
    k_instat<<<8 * 32, 256>>>(A, 65536);
    // layers 1-3
    k_conv3s2<32, 64, 8, 64><<<dim3(8, 8, 8), 256, SM_C64>>>(A, WT1, b[1], B, 256, 256, 128, 128);
    k_instat<<<8 * 64, 256>>>(B, 16384);
    k_conv3s2<64, 128, 8, 64><<<dim3(4, 4, 16), 256, SM_C64>>>(B, WT2, b[2], A, 128, 128, 64, 64);
    k_instat<<<8 * 128, 256>>>(A, 4096);
    k_conv3s2<128, 256, 8, 32><<<dim3(2, 2, 64), 256, SM_C32>>>(A, WT3, b[3], B, 64, 64, 32, 32);
    k_instat<<<8 * 256, 256>>>(B, 1024);
    // layers 4-6 (transposed conv, pitched outputs)
    k_convT<256, 128, 8><<<dim3(1, 2, 128), 256, SM_T>>>(B, WT4, b[4], A,
                                                         32, 32, 32, 63, 63, 64);
    k_instat_p<<<8 * 128, 256>>>(A, 63, 63, 64);
    k_convT<128, 64, 8><<<dim3(2, 4, 64), 256, SM_T>>>(A, WT5, b[5], B,
                                                       63, 63, 64, 125, 125, 128);
    k_instat_p<<<8 * 64, 256>>>(B, 125, 125, 128);
    k_convT<64, 32, 8><<<dim3(4, 8, 32), 256, SM_T>>>(B, WT6, b[6], A,
                                                      125, 125, 128, 249, 249, 256);
    k_instat_p<<<8 * 32, 256>>>(A, 249, 249, 256);
    // layer 7 with fused segment accumulation
    k_conv7_l7<<<dim3(8, 8, 8), 256, SM_L7>>>(A, WT7, b[7], inst, SS, SN);
    // broadcast means
    k_segbcast<<<2048, 256>>>(inst, SS, SN, out);
}